// round 1
// baseline (speedup 1.0000x reference)
#include <cuda_runtime.h>
#include <math.h>

#define BB   64
#define TT   351
#define DD   512
#define HH   8
#define DFFX 1024
#define DKX  64
#define BT   (BB*TT)      // 22464 = 64*351, multiple of 64

// ---------------- scratch (static device allocations; no cudaMalloc) ----------------
static __device__ float g_xn [BT*DD];
static __device__ float g_q  [BT*DD];
static __device__ float g_k  [BT*DD];
static __device__ float g_v  [BT*DD];
static __device__ float g_p  [BT*DD];
static __device__ float g_ctx[BT*DD];
static __device__ float g_h  [BT*DFFX];
static __device__ float g_sc [BB*HH*TT*TT];   // 63,078,912 floats
static __device__ float g_ps [BB*HH*TT*TT];

// ---------------- add pos-emb (optional) + LayerNorm (unbiased std, eps on std) ------
// If pe != nullptr: xupd[row] = xin[row] + pe[t]; LN of that into out.
// If pe == nullptr: LN(xin[row]) into out (xin may alias out; each thread only
// touches its own elements and reads before writing).
__global__ void addln_kernel(const float* __restrict__ xin, float* __restrict__ xupd,
                             const float* __restrict__ pe,
                             const float* __restrict__ ga, const float* __restrict__ gb,
                             float* __restrict__ out) {
    int row = blockIdx.x;
    int t   = row % TT;
    const float* xr = xin + (size_t)row * DD;
    int tid = threadIdx.x;   // 128
    float vals[4];
#pragma unroll
    for (int i = 0; i < 4; i++) {
        int c = tid + i * 128;
        float vv = xr[c];
        if (pe) vv += pe[(size_t)t * DD + c];
        vals[i] = vv;
    }
    if (pe) {
        float* xw = xupd + (size_t)row * DD;
#pragma unroll
        for (int i = 0; i < 4; i++) xw[tid + i * 128] = vals[i];
    }
    __shared__ float sh[4];
    float s = vals[0] + vals[1] + vals[2] + vals[3];
#pragma unroll
    for (int o = 16; o > 0; o >>= 1) s += __shfl_xor_sync(0xffffffffu, s, o);
    if ((tid & 31) == 0) sh[tid >> 5] = s;
    __syncthreads();
    float mean = (sh[0] + sh[1] + sh[2] + sh[3]) * (1.0f / DD);
    __syncthreads();
    float sq = 0.0f;
#pragma unroll
    for (int i = 0; i < 4; i++) { float d = vals[i] - mean; sq += d * d; }
#pragma unroll
    for (int o = 16; o > 0; o >>= 1) sq += __shfl_xor_sync(0xffffffffu, sq, o);
    if ((tid & 31) == 0) sh[tid >> 5] = sq;
    __syncthreads();
    float var  = sh[0] + sh[1] + sh[2] + sh[3];
    float stdv = sqrtf(var * (1.0f / (DD - 1)));
    float inv  = 1.0f / (stdv + 1e-6f);
    float* orow = out + (size_t)row * DD;
#pragma unroll
    for (int i = 0; i < 4; i++) {
        int c = tid + i * 128;
        orow[c] = ga[c] * (vals[i] - mean) * inv + gb[c];
    }
}

// ---------------- generic C = act(A @ W^T + bias) [+ C]  --------------------------
// A: MxK row-major, W: NxK row-major, C: MxN. Requires M%64==0, N%64==0, K%16==0.
template<bool RELU, bool ACCUM>
__global__ void gemm64_kernel(const float* __restrict__ A, const float* __restrict__ W,
                              const float* __restrict__ bias, float* __restrict__ C,
                              int M, int N, int K) {
    __shared__ float As[16][68];
    __shared__ float Ws[16][68];
    int tid = threadIdx.x;           // 256
    int tx  = tid & 15, ty = tid >> 4;
    int bm  = blockIdx.y << 6, bn = blockIdx.x << 6;
    int lk  = tid & 15, lm = tid >> 4;
    const float* Ap = A + (size_t)(bm + lm) * K + lk;
    const float* Wp = W + (size_t)(bn + lm) * K + lk;
    float acc[4][4] = {};
    for (int k0 = 0; k0 < K; k0 += 16) {
#pragma unroll
        for (int i = 0; i < 4; i++) As[lk][lm + 16 * i] = Ap[(size_t)(16 * i) * K + k0];
#pragma unroll
        for (int i = 0; i < 4; i++) Ws[lk][lm + 16 * i] = Wp[(size_t)(16 * i) * K + k0];
        __syncthreads();
#pragma unroll
        for (int kk = 0; kk < 16; kk++) {
            float4 a4 = *(const float4*)&As[kk][ty * 4];
            float4 b4 = *(const float4*)&Ws[kk][tx * 4];
            float av[4] = {a4.x, a4.y, a4.z, a4.w};
            float bv[4] = {b4.x, b4.y, b4.z, b4.w};
#pragma unroll
            for (int i = 0; i < 4; i++)
#pragma unroll
                for (int j = 0; j < 4; j++) acc[i][j] += av[i] * bv[j];
        }
        __syncthreads();
    }
#pragma unroll
    for (int i = 0; i < 4; i++) {
        int r = bm + ty * 4 + i;
        float* Cp = C + (size_t)r * N + bn + tx * 4;
#pragma unroll
        for (int j = 0; j < 4; j++) {
            float vv = acc[i][j];
            if (bias) vv += bias[bn + tx * 4 + j];
            if (RELU)  vv = fmaxf(vv, 0.0f);
            if (ACCUM) vv += Cp[j];
            Cp[j] = vv;
        }
    }
}

// ---------------- batched scores: out[z,q,k] = sum_d (Q[b,q,h,d]+bias[h,d]) * Km[b,k,h,d]
__global__ void score_kernel(const float* __restrict__ Q, const float* __restrict__ Km,
                             const float* __restrict__ bias, float* __restrict__ out) {
    __shared__ float As[16][36];
    __shared__ float Bs[16][36];
    int z = blockIdx.z; int b = z >> 3; int h = z & 7;
    int q0 = blockIdx.y << 5, k0c = blockIdx.x << 5;
    int tid = threadIdx.x;           // 256
    int tx = tid & 15, ty = tid >> 4;
    int lk = tid & 15, lm = tid >> 4;
    const float* qb = Q  + (size_t)b * TT * DD + h * DKX;
    const float* kb = Km + (size_t)b * TT * DD + h * DKX;
    const float* ub = bias + h * DKX;
    float acc[2][2] = {};
    for (int d0 = 0; d0 < DKX; d0 += 16) {
        float bu = ub[d0 + lk];
#pragma unroll
        for (int i = 0; i < 2; i++) {
            int qq = q0 + lm + 16 * i;
            As[lk][lm + 16 * i] = (qq < TT) ? (qb[(size_t)qq * DD + d0 + lk] + bu) : 0.0f;
            int kc = k0c + lm + 16 * i;
            Bs[lk][lm + 16 * i] = (kc < TT) ?  kb[(size_t)kc * DD + d0 + lk]        : 0.0f;
        }
        __syncthreads();
#pragma unroll
        for (int kk = 0; kk < 16; kk++) {
            float2 a2 = *(const float2*)&As[kk][ty * 2];
            float2 b2 = *(const float2*)&Bs[kk][tx * 2];
            acc[0][0] += a2.x * b2.x; acc[0][1] += a2.x * b2.y;
            acc[1][0] += a2.y * b2.x; acc[1][1] += a2.y * b2.y;
        }
        __syncthreads();
    }
    float* ob = out + (size_t)z * TT * TT;
#pragma unroll
    for (int i = 0; i < 2; i++) {
        int qq = q0 + ty * 2 + i;
        if (qq >= TT) continue;
#pragma unroll
        for (int j = 0; j < 2; j++) {
            int kc = k0c + tx * 2 + j;
            if (kc < TT) ob[(size_t)qq * TT + kc] = acc[i][j];
        }
    }
}

// ---------------- fused rel-shift + softmax:  SC = softmax((SC + shift(PS)) / sqrt(D))
__global__ void softmax_kernel(float* __restrict__ SC, const float* __restrict__ PS) {
    int q = blockIdx.x, z = blockIdx.y;
    float* crow = SC + (size_t)z * TT * TT + (size_t)q * TT;
    const float* psb = PS + (size_t)z * TT * TT;
    int tid = threadIdx.x;           // 128
    const float scale = 0.044194173824159216f;   // 1/sqrt(512)
    float vals[3];
    float mx = -1e30f;
#pragma unroll
    for (int i = 0; i < 3; i++) {
        int k = tid + i * 128;
        float vv = -1e30f;
        if (k < TT) {
            float pv;
            if (k <= q)          pv = psb[(size_t)q * TT + (TT - 1 + k - q)];
            else if (k == q + 1) pv = 0.0f;
            else                 pv = psb[(size_t)(q + 1) * TT + (k - q - 2)];
            vv = (crow[k] + pv) * scale;
        }
        vals[i] = vv;
        mx = fmaxf(mx, vv);
    }
    __shared__ float sh[4];
#pragma unroll
    for (int o = 16; o > 0; o >>= 1) mx = fmaxf(mx, __shfl_xor_sync(0xffffffffu, mx, o));
    if ((tid & 31) == 0) sh[tid >> 5] = mx;
    __syncthreads();
    mx = fmaxf(fmaxf(sh[0], sh[1]), fmaxf(sh[2], sh[3]));
    __syncthreads();
    float sum = 0.0f;
#pragma unroll
    for (int i = 0; i < 3; i++) {
        int k = tid + i * 128;
        if (k < TT) { vals[i] = __expf(vals[i] - mx); sum += vals[i]; }
        else vals[i] = 0.0f;
    }
#pragma unroll
    for (int o = 16; o > 0; o >>= 1) sum += __shfl_xor_sync(0xffffffffu, sum, o);
    if ((tid & 31) == 0) sh[tid >> 5] = sum;
    __syncthreads();
    float inv = 1.0f / (sh[0] + sh[1] + sh[2] + sh[3]);
#pragma unroll
    for (int i = 0; i < 3; i++) {
        int k = tid + i * 128;
        if (k < TT) crow[k] = vals[i] * inv;
    }
}

// ---------------- ctx[b,q,h,:] = sum_k attn[z,q,k] * V[b,k,h,:] ----------------------
__global__ void attnv_kernel(const float* __restrict__ Attn, const float* __restrict__ V,
                             float* __restrict__ Ctx) {
    __shared__ float As[16][36];     // [k][q]
    __shared__ float Vs[16][68];     // [k][d]
    int z = blockIdx.z; int b = z >> 3; int h = z & 7;
    int q0 = blockIdx.y << 5;
    int tid = threadIdx.x;           // 256
    int tx = tid & 15, ty = tid >> 4;
    const float* arow = Attn + (size_t)z * TT * TT;
    const float* vb   = V + (size_t)b * TT * DD + h * DKX;
    float acc[2][4] = {};
    for (int k0 = 0; k0 < TT; k0 += 16) {
        {
            int lk = tid & 15, lm = tid >> 4;
#pragma unroll
            for (int i = 0; i < 2; i++) {
                int qq = q0 + lm + 16 * i;
                int kk = k0 + lk;
                As[lk][lm + 16 * i] = (qq < TT && kk < TT) ? arow[(size_t)qq * TT + kk] : 0.0f;
            }
        }
        {
            int ld = tid & 63, lr = tid >> 6;   // lr 0..3
#pragma unroll
            for (int i = 0; i < 4; i++) {
                int kk = k0 + lr + 4 * i;
                Vs[lr + 4 * i][ld] = (kk < TT) ? vb[(size_t)kk * DD + ld] : 0.0f;
            }
        }
        __syncthreads();
#pragma unroll
        for (int kk = 0; kk < 16; kk++) {
            float2 a2 = *(const float2*)&As[kk][ty * 2];
            float4 b4 = *(const float4*)&Vs[kk][tx * 4];
            acc[0][0] += a2.x * b4.x; acc[0][1] += a2.x * b4.y;
            acc[0][2] += a2.x * b4.z; acc[0][3] += a2.x * b4.w;
            acc[1][0] += a2.y * b4.x; acc[1][1] += a2.y * b4.y;
            acc[1][2] += a2.y * b4.z; acc[1][3] += a2.y * b4.w;
        }
        __syncthreads();
    }
#pragma unroll
    for (int i = 0; i < 2; i++) {
        int qq = q0 + ty * 2 + i;
        if (qq >= TT) continue;
        float* cp = Ctx + ((size_t)(b * TT + qq)) * DD + h * DKX + tx * 4;
#pragma unroll
        for (int j = 0; j < 4; j++) cp[j] = acc[i][j];
    }
}

// ---------------- X += conv1d_k3(H, W2) + b2 ; W2 layout [o][f][w] -------------------
__global__ void conv3_kernel(const float* __restrict__ Hin, const float* __restrict__ W2,
                             const float* __restrict__ b2, float* __restrict__ X) {
    __shared__ float Hs[3][16][68];
    __shared__ float Ws[3][16][68];
    int tid = threadIdx.x;           // 256
    int tx = tid & 15, ty = tid >> 4;
    int bm = blockIdx.y << 6, bn = blockIdx.x << 6;
    int lk = tid & 15, lm = tid >> 4;
    // per-thread row validity (constant over K loop)
    int   rr[4]; bool ok[3][4];
#pragma unroll
    for (int i = 0; i < 4; i++) {
        int r = bm + lm + 16 * i;
        rr[i] = r;
        int t = r % TT;
#pragma unroll
        for (int s = 0; s < 3; s++) {
            int tv = t + s - 1;
            ok[s][i] = (tv >= 0) && (tv < TT);
        }
    }
    float acc[4][4] = {};
    for (int k0 = 0; k0 < DFFX; k0 += 16) {
#pragma unroll
        for (int s = 0; s < 3; s++) {
#pragma unroll
            for (int i = 0; i < 4; i++) {
                float vv = 0.0f;
                if (ok[s][i]) vv = Hin[(size_t)(rr[i] + s - 1) * DFFX + k0 + lk];
                Hs[s][lk][lm + 16 * i] = vv;
            }
        }
#pragma unroll
        for (int i = 0; i < 4; i++) {
            int n = lm + 16 * i;
            const float* wp = W2 + ((size_t)(bn + n) * DFFX + k0 + lk) * 3;
            Ws[0][lk][n] = wp[0];
            Ws[1][lk][n] = wp[1];
            Ws[2][lk][n] = wp[2];
        }
        __syncthreads();
#pragma unroll
        for (int kk = 0; kk < 16; kk++) {
#pragma unroll
            for (int s = 0; s < 3; s++) {
                float4 a4 = *(const float4*)&Hs[s][kk][ty * 4];
                float4 b4 = *(const float4*)&Ws[s][kk][tx * 4];
                float av[4] = {a4.x, a4.y, a4.z, a4.w};
                float bv[4] = {b4.x, b4.y, b4.z, b4.w};
#pragma unroll
                for (int i = 0; i < 4; i++)
#pragma unroll
                    for (int j = 0; j < 4; j++) acc[i][j] += av[i] * bv[j];
            }
        }
        __syncthreads();
    }
#pragma unroll
    for (int i = 0; i < 4; i++) {
        int r = bm + ty * 4 + i;
        float* xp = X + (size_t)r * DD + bn + tx * 4;
#pragma unroll
        for (int j = 0; j < 4; j++)
            xp[j] += acc[i][j] + b2[bn + tx * 4 + j];
    }
}

// ------------------------------------ launch -----------------------------------------
extern "C" void kernel_launch(void* const* d_in, const int* in_sizes, int n_in,
                              void* d_out, int out_size) {
    const float* X0  = (const float*)d_in[0];
    const float* MSK = (const float*)d_in[1];   // positional stream fed to Wp
    const float* PE  = (const float*)d_in[2];
    const float* Wq  = (const float*)d_in[3];
    const float* bq  = (const float*)d_in[4];
    const float* Wk  = (const float*)d_in[5];
    const float* bk  = (const float*)d_in[6];
    const float* Wv  = (const float*)d_in[7];
    const float* bv  = (const float*)d_in[8];
    const float* Wp  = (const float*)d_in[9];
    const float* Ub  = (const float*)d_in[10];
    const float* Vb  = (const float*)d_in[11];
    const float* Wo  = (const float*)d_in[12];
    const float* bo  = (const float*)d_in[13];
    const float* l1a = (const float*)d_in[14];
    const float* l1b = (const float*)d_in[15];
    const float* l2a = (const float*)d_in[16];
    const float* l2b = (const float*)d_in[17];
    const float* W1  = (const float*)d_in[18];
    const float* b1  = (const float*)d_in[19];
    const float* W2  = (const float*)d_in[20];
    const float* b2  = (const float*)d_in[21];
    const float* fna = (const float*)d_in[22];
    const float* fnb = (const float*)d_in[23];
    float* x = (float*)d_out;

    float *xn, *q, *k, *v, *p, *ctx, *hbuf, *sc, *ps;
    cudaGetSymbolAddress((void**)&xn,   g_xn);
    cudaGetSymbolAddress((void**)&q,    g_q);
    cudaGetSymbolAddress((void**)&k,    g_k);
    cudaGetSymbolAddress((void**)&v,    g_v);
    cudaGetSymbolAddress((void**)&p,    g_p);
    cudaGetSymbolAddress((void**)&ctx,  g_ctx);
    cudaGetSymbolAddress((void**)&hbuf, g_h);
    cudaGetSymbolAddress((void**)&sc,   g_sc);
    cudaGetSymbolAddress((void**)&ps,   g_ps);

    dim3 gProj(DD / 64, BT / 64);       // (8, 351)
    dim3 gFF1(DFFX / 64, BT / 64);      // (16, 351)
    dim3 gScore(11, 11, BB * HH);       // ceil(351/32)=11
    dim3 gAV(1, 11, BB * HH);
    dim3 gSmax(TT, BB * HH);

    for (int i = 0; i < 3; i++) {
        size_t oD = (size_t)i * DD, oDD = (size_t)i * DD * DD;
        addln_kernel<<<BT, 128>>>(i == 0 ? X0 : x, x, PE + (size_t)i * TT * DD,
                                  l1a + oD, l1b + oD, xn);
        gemm64_kernel<false, false><<<gProj, 256>>>(xn,  Wq + oDD, bq + oD, q, BT, DD, DD);
        gemm64_kernel<false, false><<<gProj, 256>>>(xn,  Wk + oDD, bk + oD, k, BT, DD, DD);
        gemm64_kernel<false, false><<<gProj, 256>>>(xn,  Wv + oDD, bv + oD, v, BT, DD, DD);
        gemm64_kernel<false, false><<<gProj, 256>>>(MSK, Wp + oDD, nullptr, p, BT, DD, DD);
        score_kernel<<<gScore, 256>>>(q, k, Ub + (size_t)i * HH * DKX, sc);
        score_kernel<<<gScore, 256>>>(q, p, Vb + (size_t)i * HH * DKX, ps);
        softmax_kernel<<<gSmax, 128>>>(sc, ps);
        attnv_kernel<<<gAV, 256>>>(sc, v, ctx);
        gemm64_kernel<false, true><<<gProj, 256>>>(ctx, Wo + oDD, bo + oD, x, BT, DD, DD);
        addln_kernel<<<BT, 128>>>(x, x, nullptr, l2a + oD, l2b + oD, xn);
        gemm64_kernel<true, false><<<gFF1, 256>>>(xn, W1 + (size_t)i * DFFX * DD,
                                                  b1 + (size_t)i * DFFX, hbuf, BT, DFFX, DD);
        conv3_kernel<<<dim3(DD / 64, BT / 64), 256>>>(hbuf, W2 + (size_t)i * DD * DFFX * 3,
                                                      b2 + oD, x);
    }
    addln_kernel<<<BT, 128>>>(x, x, nullptr, fna, fnb, x);
}

// round 3
// speedup vs baseline: 1.9530x; 1.9530x over previous
#include <cuda_runtime.h>
#include <cuda_bf16.h>
#include <math.h>
#include <stdint.h>

#define BB   64
#define TT   351
#define DD   512
#define HH   8
#define DFFX 1024
#define DKX  64
#define BT   (BB*TT)       // 22464
#define MP   22528         // BT padded to multiple of 128
#define HPR  22784         // 64*353 padded-H rows + slack (covers remap overrun)
#define STAGE_BYTES 40960  // 4 arrays * 128 rows * 80B
#define SMEMSZ (2*STAGE_BYTES)

// ---------------- scratch (static device; zero-initialized, pads stay zero) ---------
static __device__ float g_q  [MP*(size_t)DD];
static __device__ float g_k  [MP*(size_t)DD];
static __device__ float g_v  [MP*(size_t)DD];
static __device__ float g_p  [MP*(size_t)DD];
static __device__ float g_sc [(size_t)BB*HH*TT*TT];
static __device__ float g_ps [(size_t)BB*HH*TT*TT];
static __device__ __nv_bfloat16 g_xnh[MP*(size_t)DD], g_xnl[MP*(size_t)DD];
static __device__ __nv_bfloat16 g_mkh[MP*(size_t)DD], g_mkl[MP*(size_t)DD];
static __device__ __nv_bfloat16 g_cxh[MP*(size_t)DD], g_cxl[MP*(size_t)DD];
static __device__ __nv_bfloat16 g_hph[(size_t)HPR*DFFX], g_hpl[(size_t)HPR*DFFX];
static __device__ __nv_bfloat16 g_wqh[3*DD*DD], g_wql[3*DD*DD];
static __device__ __nv_bfloat16 g_wkh[3*DD*DD], g_wkl[3*DD*DD];
static __device__ __nv_bfloat16 g_wvh[3*DD*DD], g_wvl[3*DD*DD];
static __device__ __nv_bfloat16 g_wph[3*DD*DD], g_wpl[3*DD*DD];
static __device__ __nv_bfloat16 g_woh[3*DD*DD], g_wol[3*DD*DD];
static __device__ __nv_bfloat16 g_w1h[3*DFFX*DD], g_w1l[3*DFFX*DD];
static __device__ __nv_bfloat16 g_w2h[3*3*DD*DFFX], g_w2l[3*3*DD*DFFX]; // [l][s][n][k]

// ---------------- PTX helpers --------------------------------------------------------
__device__ __forceinline__ uint32_t smem_u32(const void* p) {
    uint32_t a;
    asm("{ .reg .u64 t; cvta.to.shared.u64 t, %1; cvt.u32.u64 %0, t; }" : "=r"(a) : "l"(p));
    return a;
}
__device__ __forceinline__ void cp16(uint32_t dst, const void* src) {
    asm volatile("cp.async.cg.shared.global [%0], [%1], 16;" :: "r"(dst), "l"(src) : "memory");
}
#define CP_COMMIT() asm volatile("cp.async.commit_group;" ::: "memory")
#define CP_WAIT1()  asm volatile("cp.async.wait_group 1;" ::: "memory")

__device__ __forceinline__ void mma16816(float* c, const uint32_t* a, const uint32_t* b) {
    asm volatile(
        "mma.sync.aligned.m16n8k16.row.col.f32.bf16.bf16.f32 "
        "{%0,%1,%2,%3}, {%4,%5,%6,%7}, {%8,%9}, {%0,%1,%2,%3};"
        : "+f"(c[0]), "+f"(c[1]), "+f"(c[2]), "+f"(c[3])
        : "r"(a[0]), "r"(a[1]), "r"(a[2]), "r"(a[3]), "r"(b[0]), "r"(b[1]));
}

// ---------------- split-bf16 conversion kernels --------------------------------------
__global__ void cvt_split(const float* __restrict__ in, __nv_bfloat16* __restrict__ hi,
                          __nv_bfloat16* __restrict__ lo, int n4) {
    int i = blockIdx.x * 256 + threadIdx.x;
    if (i >= n4) return;
    float4 v = ((const float4*)in)[i];
    float vv[4] = {v.x, v.y, v.z, v.w};
    __align__(8) __nv_bfloat16 h[4], l[4];
#pragma unroll
    for (int j = 0; j < 4; j++) {
        h[j] = __float2bfloat16(vv[j]);
        l[j] = __float2bfloat16(vv[j] - __bfloat162float(h[j]));
    }
    ((uint2*)hi)[i] = *(uint2*)h;
    ((uint2*)lo)[i] = *(uint2*)l;
}
// W2 in: [l][n][k][s] -> out [l][s][n][k]
__global__ void cvt_w2(const float* __restrict__ in, __nv_bfloat16* __restrict__ hi,
                       __nv_bfloat16* __restrict__ lo) {
    int idx = blockIdx.x * 256 + threadIdx.x;
    const int per_l = 3 * DD * DFFX;
    if (idx >= 3 * per_l) return;
    int l = idx / per_l; int r = idx - l * per_l;
    int s = r / (DD * DFFX); int r2 = r - s * (DD * DFFX);
    int n = r2 / DFFX; int k2 = r2 - n * DFFX;
    float v = in[(((size_t)l * DD + n) * DFFX + k2) * 3 + s];
    __nv_bfloat16 h = __float2bfloat16(v);
    hi[idx] = h;
    lo[idx] = __float2bfloat16(v - __bfloat162float(h));
}

// ---------------- HMMA split-bf16 GEMM: C = [relu](A @ B^T + bias) [+C] -------------
// A: rows x K (hi/lo), B: N x K (hi/lo; TAPS==3: 3 concatenated blocks).
// Tile 128x128, BK=32, 8 warps (warp tile 64x32), cp.async double buffered.
template<int TAPS, bool ACC, bool RELU, bool BF16O>
__global__ __launch_bounds__(256, 2)
void hmma_gemm(const __nv_bfloat16* __restrict__ Ahi, const __nv_bfloat16* __restrict__ Alo,
               const __nv_bfloat16* __restrict__ Bhi, const __nv_bfloat16* __restrict__ Blo,
               const float* __restrict__ bias,
               float* __restrict__ Cf, __nv_bfloat16* __restrict__ Chi,
               __nv_bfloat16* __restrict__ Clo,
               int Mstore, int N, int K) {
    extern __shared__ char sm[];
    uint32_t dbase = smem_u32(sm);
    int tid = threadIdx.x, lane = tid & 31, w = tid >> 5;
    int wm = (w & 1) << 6, wn = (w >> 1) << 5;
    int bm = blockIdx.y << 7, bn = blockIdx.x << 7;

    // per-thread cp.async metadata: 2 (row, c16) pairs cover 128 rows x 4 c16
    uint32_t so[2]; long ga[2], gb[2];
#pragma unroll
    for (int j = 0; j < 2; j++) {
        int idx = tid + 256 * j; int row = idx >> 2, c16 = idx & 3;
        so[j] = row * 80 + c16 * 16;
        int grow = bm + row;
        long arow;
        if (TAPS == 3) { int b = grow / 351; int t = grow - b * 351; arow = (long)b * 353 + t; }
        else arow = grow;
        ga[j] = arow * (long)K + c16 * 8;
        gb[j] = (long)(bn + row) * K + c16 * 8;
    }
    const int kch = K >> 5;            // chunks per tap
    const int nch = TAPS * kch;

#define LOAD_CHUNK(c, stg) do { \
        int s_ = (c) / kch; int kb_ = ((c) - s_ * kch) << 5; \
        long sK_ = (TAPS == 3) ? (long)s_ * K : 0; \
        long sNK_ = (TAPS == 3) ? (long)s_ * N * K : 0; \
        uint32_t sb_ = dbase + (stg) * STAGE_BYTES; \
        _Pragma("unroll") \
        for (int j = 0; j < 2; j++) { \
            cp16(sb_ + so[j],         Ahi + sK_ + ga[j] + kb_); \
            cp16(sb_ + 10240 + so[j], Alo + sK_ + ga[j] + kb_); \
            cp16(sb_ + 20480 + so[j], Bhi + sNK_ + gb[j] + kb_); \
            cp16(sb_ + 30720 + so[j], Blo + sNK_ + gb[j] + kb_); \
        } \
    } while (0)

    float acc[4][4][4];
#pragma unroll
    for (int a = 0; a < 4; a++)
#pragma unroll
        for (int b = 0; b < 4; b++)
#pragma unroll
            for (int q2 = 0; q2 < 4; q2++) acc[a][b][q2] = 0.0f;

    int bq = lane & 3, bg = lane >> 2;

    LOAD_CHUNK(0, 0);
    CP_COMMIT();
#pragma unroll 1
    for (int c = 0; c < nch; c++) {
        if (c + 1 < nch) LOAD_CHUNK(c + 1, (c + 1) & 1);
        CP_COMMIT();
        CP_WAIT1();
        __syncthreads();
        const char* sA = sm + (c & 1) * STAGE_BYTES;
#pragma unroll
        for (int k16 = 0; k16 < 2; k16++) {
            int kbyte = k16 * 32 + bq * 4;
            uint32_t bh[4][2], bl[4][2];
#pragma unroll
            for (int ni = 0; ni < 4; ni++) {
                int n = wn + ni * 8 + bg;
                const char* pb = sA + 20480 + n * 80 + kbyte;
                bh[ni][0] = *(const uint32_t*)pb;
                bh[ni][1] = *(const uint32_t*)(pb + 16);
                const char* pl = pb + 10240;
                bl[ni][0] = *(const uint32_t*)pl;
                bl[ni][1] = *(const uint32_t*)(pl + 16);
            }
#pragma unroll
            for (int mi = 0; mi < 4; mi++) {
                int r = wm + mi * 16 + bg;
                const char* pa = sA + r * 80 + kbyte;
                uint32_t ah[4], al[4];
                ah[0] = *(const uint32_t*)pa;
                ah[1] = *(const uint32_t*)(pa + 8 * 80);
                ah[2] = *(const uint32_t*)(pa + 16);
                ah[3] = *(const uint32_t*)(pa + 8 * 80 + 16);
                const char* pal = pa + 10240;
                al[0] = *(const uint32_t*)pal;
                al[1] = *(const uint32_t*)(pal + 8 * 80);
                al[2] = *(const uint32_t*)(pal + 16);
                al[3] = *(const uint32_t*)(pal + 8 * 80 + 16);
#pragma unroll
                for (int ni = 0; ni < 4; ni++) {
                    mma16816(acc[mi][ni], ah, bh[ni]);
                    mma16816(acc[mi][ni], ah, bl[ni]);
                    mma16816(acc[mi][ni], al, bh[ni]);
                }
            }
        }
        __syncthreads();
    }
#undef LOAD_CHUNK

    // epilogue
#pragma unroll
    for (int mi = 0; mi < 4; mi++) {
#pragma unroll
        for (int half = 0; half < 2; half++) {
            int m = bm + wm + mi * 16 + bg + half * 8;
            if (m >= Mstore) continue;
            long crow = m;
            if (BF16O) { int b = m / 351; int t = m - b * 351; crow = (long)b * 353 + 1 + t; }
#pragma unroll
            for (int ni = 0; ni < 4; ni++) {
                int col = bn + wn + ni * 8 + bq * 2;
                float v0 = acc[mi][ni][half * 2 + 0];
                float v1 = acc[mi][ni][half * 2 + 1];
                if (bias) { v0 += bias[col]; v1 += bias[col + 1]; }
                if (RELU) { v0 = fmaxf(v0, 0.0f); v1 = fmaxf(v1, 0.0f); }
                if (BF16O) {
                    __nv_bfloat16 h0 = __float2bfloat16(v0), h1 = __float2bfloat16(v1);
                    __nv_bfloat16 l0 = __float2bfloat16(v0 - __bfloat162float(h0));
                    __nv_bfloat16 l1 = __float2bfloat16(v1 - __bfloat162float(h1));
                    uint32_t hp, lp;
                    hp = (uint32_t)__bfloat16_as_ushort(h0) |
                         ((uint32_t)__bfloat16_as_ushort(h1) << 16);
                    lp = (uint32_t)__bfloat16_as_ushort(l0) |
                         ((uint32_t)__bfloat16_as_ushort(l1) << 16);
                    *(uint32_t*)(Chi + crow * (long)N + col) = hp;
                    *(uint32_t*)(Clo + crow * (long)N + col) = lp;
                } else {
                    float* cp = Cf + (long)m * N + col;
                    if (ACC) { v0 += cp[0]; v1 += cp[1]; }
                    float2 st; st.x = v0; st.y = v1;
                    *(float2*)cp = st;
                }
            }
        }
    }
}

// ---------------- add pos-emb + LayerNorm; outputs fp32 or split-bf16 ----------------
template<bool BF16O>
__global__ void addln_kernel(const float* __restrict__ xin, float* __restrict__ xupd,
                             const float* __restrict__ pe,
                             const float* __restrict__ ga, const float* __restrict__ gb,
                             float* __restrict__ out, __nv_bfloat16* __restrict__ ohi,
                             __nv_bfloat16* __restrict__ olo) {
    int row = blockIdx.x;
    int t   = row % TT;
    const float* xr = xin + (size_t)row * DD;
    int tid = threadIdx.x;   // 128
    float vals[4];
#pragma unroll
    for (int i = 0; i < 4; i++) {
        int c = tid + i * 128;
        float vv = xr[c];
        if (pe) vv += pe[(size_t)t * DD + c];
        vals[i] = vv;
    }
    if (pe) {
        float* xw = xupd + (size_t)row * DD;
#pragma unroll
        for (int i = 0; i < 4; i++) xw[tid + i * 128] = vals[i];
    }
    __shared__ float sh[4];
    float s = vals[0] + vals[1] + vals[2] + vals[3];
#pragma unroll
    for (int o = 16; o > 0; o >>= 1) s += __shfl_xor_sync(0xffffffffu, s, o);
    if ((tid & 31) == 0) sh[tid >> 5] = s;
    __syncthreads();
    float mean = (sh[0] + sh[1] + sh[2] + sh[3]) * (1.0f / DD);
    __syncthreads();
    float sq = 0.0f;
#pragma unroll
    for (int i = 0; i < 4; i++) { float d = vals[i] - mean; sq += d * d; }
#pragma unroll
    for (int o = 16; o > 0; o >>= 1) sq += __shfl_xor_sync(0xffffffffu, sq, o);
    if ((tid & 31) == 0) sh[tid >> 5] = sq;
    __syncthreads();
    float var  = sh[0] + sh[1] + sh[2] + sh[3];
    float stdv = sqrtf(var * (1.0f / (DD - 1)));
    float inv  = 1.0f / (stdv + 1e-6f);
#pragma unroll
    for (int i = 0; i < 4; i++) {
        int c = tid + i * 128;
        float v = ga[c] * (vals[i] - mean) * inv + gb[c];
        if (BF16O) {
            __nv_bfloat16 h = __float2bfloat16(v);
            ohi[(size_t)row * DD + c] = h;
            olo[(size_t)row * DD + c] = __float2bfloat16(v - __bfloat162float(h));
        } else {
            out[(size_t)row * DD + c] = v;
        }
    }
}

// ---------------- batched scores -----------------------------------------------------
__global__ void score_kernel(const float* __restrict__ Q, const float* __restrict__ Km,
                             const float* __restrict__ bias, float* __restrict__ out) {
    __shared__ float As[16][36];
    __shared__ float Bs[16][36];
    int z = blockIdx.z; int b = z >> 3; int h = z & 7;
    int q0 = blockIdx.y << 5, k0c = blockIdx.x << 5;
    int tid = threadIdx.x;
    int tx = tid & 15, ty = tid >> 4;
    int lk = tid & 15, lm = tid >> 4;
    const float* qb = Q  + (size_t)b * TT * DD + h * DKX;
    const float* kb = Km + (size_t)b * TT * DD + h * DKX;
    const float* ub = bias + h * DKX;
    float acc[2][2] = {};
    for (int d0 = 0; d0 < DKX; d0 += 16) {
        float bu = ub[d0 + lk];
#pragma unroll
        for (int i = 0; i < 2; i++) {
            int qq = q0 + lm + 16 * i;
            As[lk][lm + 16 * i] = (qq < TT) ? (qb[(size_t)qq * DD + d0 + lk] + bu) : 0.0f;
            int kc = k0c + lm + 16 * i;
            Bs[lk][lm + 16 * i] = (kc < TT) ?  kb[(size_t)kc * DD + d0 + lk]        : 0.0f;
        }
        __syncthreads();
#pragma unroll
        for (int kk = 0; kk < 16; kk++) {
            float2 a2 = *(const float2*)&As[kk][ty * 2];
            float2 b2 = *(const float2*)&Bs[kk][tx * 2];
            acc[0][0] += a2.x * b2.x; acc[0][1] += a2.x * b2.y;
            acc[1][0] += a2.y * b2.x; acc[1][1] += a2.y * b2.y;
        }
        __syncthreads();
    }
    float* ob = out + (size_t)z * TT * TT;
#pragma unroll
    for (int i = 0; i < 2; i++) {
        int qq = q0 + ty * 2 + i;
        if (qq >= TT) continue;
#pragma unroll
        for (int j = 0; j < 2; j++) {
            int kc = k0c + tx * 2 + j;
            if (kc < TT) ob[(size_t)qq * TT + kc] = acc[i][j];
        }
    }
}

// ---------------- fused rel-shift + softmax ------------------------------------------
__global__ void softmax_kernel(float* __restrict__ SC, const float* __restrict__ PS) {
    int q = blockIdx.x, z = blockIdx.y;
    float* crow = SC + (size_t)z * TT * TT + (size_t)q * TT;
    const float* psb = PS + (size_t)z * TT * TT;
    int tid = threadIdx.x;
    const float scale = 0.044194173824159216f;
    float vals[3];
    float mx = -1e30f;
#pragma unroll
    for (int i = 0; i < 3; i++) {
        int k = tid + i * 128;
        float vv = -1e30f;
        if (k < TT) {
            float pv;
            if (k <= q)          pv = psb[(size_t)q * TT + (TT - 1 + k - q)];
            else if (k == q + 1) pv = 0.0f;
            else                 pv = psb[(size_t)(q + 1) * TT + (k - q - 2)];
            vv = (crow[k] + pv) * scale;
        }
        vals[i] = vv;
        mx = fmaxf(mx, vv);
    }
    __shared__ float sh[4];
#pragma unroll
    for (int o = 16; o > 0; o >>= 1) mx = fmaxf(mx, __shfl_xor_sync(0xffffffffu, mx, o));
    if ((tid & 31) == 0) sh[tid >> 5] = mx;
    __syncthreads();
    mx = fmaxf(fmaxf(sh[0], sh[1]), fmaxf(sh[2], sh[3]));
    __syncthreads();
    float sum = 0.0f;
#pragma unroll
    for (int i = 0; i < 3; i++) {
        int k = tid + i * 128;
        if (k < TT) { vals[i] = __expf(vals[i] - mx); sum += vals[i]; }
        else vals[i] = 0.0f;
    }
#pragma unroll
    for (int o = 16; o > 0; o >>= 1) sum += __shfl_xor_sync(0xffffffffu, sum, o);
    if ((tid & 31) == 0) sh[tid >> 5] = sum;
    __syncthreads();
    float inv = 1.0f / (sh[0] + sh[1] + sh[2] + sh[3]);
#pragma unroll
    for (int i = 0; i < 3; i++) {
        int k = tid + i * 128;
        if (k < TT) crow[k] = vals[i] * inv;
    }
}

// ---------------- ctx (split-bf16) = attn @ V ----------------------------------------
__global__ void attnv_kernel(const float* __restrict__ Attn, const float* __restrict__ V,
                             __nv_bfloat16* __restrict__ Chi, __nv_bfloat16* __restrict__ Clo) {
    __shared__ float As[16][36];
    __shared__ float Vs[16][68];
    int z = blockIdx.z; int b = z >> 3; int h = z & 7;
    int q0 = blockIdx.y << 5;
    int tid = threadIdx.x;
    int tx = tid & 15, ty = tid >> 4;
    const float* arow = Attn + (size_t)z * TT * TT;
    const float* vb   = V + (size_t)b * TT * DD + h * DKX;
    float acc[2][4] = {};
    for (int k0 = 0; k0 < TT; k0 += 16) {
        {
            int lk = tid & 15, lm = tid >> 4;
#pragma unroll
            for (int i = 0; i < 2; i++) {
                int qq = q0 + lm + 16 * i;
                int kk = k0 + lk;
                As[lk][lm + 16 * i] = (qq < TT && kk < TT) ? arow[(size_t)qq * TT + kk] : 0.0f;
            }
        }
        {
            int ld = tid & 63, lr = tid >> 6;
#pragma unroll
            for (int i = 0; i < 4; i++) {
                int kk = k0 + lr + 4 * i;
                Vs[lr + 4 * i][ld] = (kk < TT) ? vb[(size_t)kk * DD + ld] : 0.0f;
            }
        }
        __syncthreads();
#pragma unroll
        for (int kk = 0; kk < 16; kk++) {
            float2 a2 = *(const float2*)&As[kk][ty * 2];
            float4 b4 = *(const float4*)&Vs[kk][tx * 4];
            acc[0][0] += a2.x * b4.x; acc[0][1] += a2.x * b4.y;
            acc[0][2] += a2.x * b4.z; acc[0][3] += a2.x * b4.w;
            acc[1][0] += a2.y * b4.x; acc[1][1] += a2.y * b4.y;
            acc[1][2] += a2.y * b4.z; acc[1][3] += a2.y * b4.w;
        }
        __syncthreads();
    }
#pragma unroll
    for (int i = 0; i < 2; i++) {
        int qq = q0 + ty * 2 + i;
        if (qq >= TT) continue;
        size_t off = ((size_t)(b * TT + qq)) * DD + h * DKX + tx * 4;
#pragma unroll
        for (int j = 0; j < 4; j++) {
            float v = acc[i][j];
            __nv_bfloat16 hh = __float2bfloat16(v);
            Chi[off + j] = hh;
            Clo[off + j] = __float2bfloat16(v - __bfloat162float(hh));
        }
    }
}

// ------------------------------------ launch -----------------------------------------
extern "C" void kernel_launch(void* const* d_in, const int* in_sizes, int n_in,
                              void* d_out, int out_size) {
    const float* X0  = (const float*)d_in[0];
    const float* MSK = (const float*)d_in[1];
    const float* PE  = (const float*)d_in[2];
    const float* Wq  = (const float*)d_in[3];
    const float* bq  = (const float*)d_in[4];
    const float* Wk  = (const float*)d_in[5];
    const float* bk  = (const float*)d_in[6];
    const float* Wv  = (const float*)d_in[7];
    const float* bv  = (const float*)d_in[8];
    const float* Wp  = (const float*)d_in[9];
    const float* Ub  = (const float*)d_in[10];
    const float* Vb  = (const float*)d_in[11];
    const float* Wo  = (const float*)d_in[12];
    const float* bo  = (const float*)d_in[13];
    const float* l1a = (const float*)d_in[14];
    const float* l1b = (const float*)d_in[15];
    const float* l2a = (const float*)d_in[16];
    const float* l2b = (const float*)d_in[17];
    const float* W1  = (const float*)d_in[18];
    const float* b1  = (const float*)d_in[19];
    const float* W2  = (const float*)d_in[20];
    const float* b2  = (const float*)d_in[21];
    const float* fna = (const float*)d_in[22];
    const float* fnb = (const float*)d_in[23];
    float* x = (float*)d_out;

    float *q, *k, *v, *p, *sc, *ps;
    __nv_bfloat16 *xnh, *xnl, *mkh, *mkl, *cxh, *cxl, *hph, *hpl;
    __nv_bfloat16 *wqh, *wql, *wkh, *wkl, *wvh, *wvl, *wph, *wpl, *woh, *wol;
    __nv_bfloat16 *w1h, *w1l, *w2h, *w2l;
    cudaGetSymbolAddress((void**)&q,   g_q);   cudaGetSymbolAddress((void**)&k,   g_k);
    cudaGetSymbolAddress((void**)&v,   g_v);   cudaGetSymbolAddress((void**)&p,   g_p);
    cudaGetSymbolAddress((void**)&sc,  g_sc);  cudaGetSymbolAddress((void**)&ps,  g_ps);
    cudaGetSymbolAddress((void**)&xnh, g_xnh); cudaGetSymbolAddress((void**)&xnl, g_xnl);
    cudaGetSymbolAddress((void**)&mkh, g_mkh); cudaGetSymbolAddress((void**)&mkl, g_mkl);
    cudaGetSymbolAddress((void**)&cxh, g_cxh); cudaGetSymbolAddress((void**)&cxl, g_cxl);
    cudaGetSymbolAddress((void**)&hph, g_hph); cudaGetSymbolAddress((void**)&hpl, g_hpl);
    cudaGetSymbolAddress((void**)&wqh, g_wqh); cudaGetSymbolAddress((void**)&wql, g_wql);
    cudaGetSymbolAddress((void**)&wkh, g_wkh); cudaGetSymbolAddress((void**)&wkl, g_wkl);
    cudaGetSymbolAddress((void**)&wvh, g_wvh); cudaGetSymbolAddress((void**)&wvl, g_wvl);
    cudaGetSymbolAddress((void**)&wph, g_wph); cudaGetSymbolAddress((void**)&wpl, g_wpl);
    cudaGetSymbolAddress((void**)&woh, g_woh); cudaGetSymbolAddress((void**)&wol, g_wol);
    cudaGetSymbolAddress((void**)&w1h, g_w1h); cudaGetSymbolAddress((void**)&w1l, g_w1l);
    cudaGetSymbolAddress((void**)&w2h, g_w2h); cudaGetSymbolAddress((void**)&w2l, g_w2l);

    cudaFuncSetAttribute(hmma_gemm<1, false, false, false>,
                         cudaFuncAttributeMaxDynamicSharedMemorySize, SMEMSZ);
    cudaFuncSetAttribute(hmma_gemm<1, true,  false, false>,
                         cudaFuncAttributeMaxDynamicSharedMemorySize, SMEMSZ);
    cudaFuncSetAttribute(hmma_gemm<1, false, true,  true>,
                         cudaFuncAttributeMaxDynamicSharedMemorySize, SMEMSZ);
    cudaFuncSetAttribute(hmma_gemm<3, true,  false, false>,
                         cudaFuncAttributeMaxDynamicSharedMemorySize, SMEMSZ);

    // conversions (weights + MSK) — replayed every call, cheap
    int nW = 3 * DD * DD / 4;
    cvt_split<<<(nW + 255) / 256, 256>>>(Wq, wqh, wql, nW);
    cvt_split<<<(nW + 255) / 256, 256>>>(Wk, wkh, wkl, nW);
    cvt_split<<<(nW + 255) / 256, 256>>>(Wv, wvh, wvl, nW);
    cvt_split<<<(nW + 255) / 256, 256>>>(Wp, wph, wpl, nW);
    cvt_split<<<(nW + 255) / 256, 256>>>(Wo, woh, wol, nW);
    int n1 = 3 * DFFX * DD / 4;
    cvt_split<<<(n1 + 255) / 256, 256>>>(W1, w1h, w1l, n1);
    int nM = BT * DD / 4;
    cvt_split<<<(nM + 255) / 256, 256>>>(MSK, mkh, mkl, nM);
    int n2 = 3 * 3 * DD * DFFX;
    cvt_w2<<<(n2 + 255) / 256, 256>>>(W2, w2h, w2l);

    dim3 gP(4, MP / 128);     // proj / Wo / conv3 (N=512)
    dim3 gF(8, MP / 128);     // FF1 (N=1024)
    dim3 gScore(11, 11, BB * HH);
    dim3 gAV(1, 11, BB * HH);
    dim3 gSmax(TT, BB * HH);

    for (int i = 0; i < 3; i++) {
        size_t oD = (size_t)i * DD, oDD = (size_t)i * DD * DD;
        addln_kernel<true><<<BT, 128>>>(i == 0 ? X0 : x, x, PE + (size_t)i * TT * DD,
                                        l1a + oD, l1b + oD, nullptr, xnh, xnl);
        hmma_gemm<1, false, false, false><<<gP, 256, SMEMSZ>>>(
            xnh, xnl, wqh + oDD, wql + oDD, bq + oD, q, nullptr, nullptr, MP, DD, DD);
        hmma_gemm<1, false, false, false><<<gP, 256, SMEMSZ>>>(
            xnh, xnl, wkh + oDD, wkl + oDD, bk + oD, k, nullptr, nullptr, MP, DD, DD);
        hmma_gemm<1, false, false, false><<<gP, 256, SMEMSZ>>>(
            xnh, xnl, wvh + oDD, wvl + oDD, bv + oD, v, nullptr, nullptr, MP, DD, DD);
        hmma_gemm<1, false, false, false><<<gP, 256, SMEMSZ>>>(
            mkh, mkl, wph + oDD, wpl + oDD, nullptr, p, nullptr, nullptr, MP, DD, DD);
        score_kernel<<<gScore, 256>>>(q, k, Ub + (size_t)i * HH * DKX, sc);
        score_kernel<<<gScore, 256>>>(q, p, Vb + (size_t)i * HH * DKX, ps);
        softmax_kernel<<<gSmax, 128>>>(sc, ps);
        attnv_kernel<<<gAV, 256>>>(sc, v, cxh, cxl);
        hmma_gemm<1, true, false, false><<<gP, 256, SMEMSZ>>>(
            cxh, cxl, woh + oDD, wol + oDD, bo + oD, x, nullptr, nullptr, BT, DD, DD);
        addln_kernel<true><<<BT, 128>>>(x, nullptr, nullptr,
                                        l2a + oD, l2b + oD, nullptr, xnh, xnl);
        hmma_gemm<1, false, true, true><<<gF, 256, SMEMSZ>>>(
            xnh, xnl, w1h + (size_t)i * DFFX * DD, w1l + (size_t)i * DFFX * DD,
            b1 + (size_t)i * DFFX, nullptr, hph, hpl, BT, DFFX, DD);
        hmma_gemm<3, true, false, false><<<gP, 256, SMEMSZ>>>(
            hph, hpl, w2h + (size_t)i * 3 * DD * DFFX, w2l + (size_t)i * 3 * DD * DFFX,
            b2 + oD, x, nullptr, nullptr, BT, DD, DFFX);
    }
    addln_kernel<false><<<BT, 128>>>(x, nullptr, nullptr, fna, fnb, x, nullptr, nullptr);
}

// round 4
// speedup vs baseline: 2.1577x; 1.1048x over previous
#include <cuda_runtime.h>
#include <cuda_bf16.h>
#include <math.h>
#include <stdint.h>

#define BB   64
#define TT   351
#define DD   512
#define HH   8
#define DFFX 1024
#define BT   (BB*TT)       // 22464
#define MP   22528         // BT padded to multiple of 128
#define HPR  22784         // 64*353 padded-H rows + slack
#define TP   384           // padded T
#define ZZ   (BB*HH)       // 512
#define STAGE_BYTES 40960
#define SMEMSZ (2*STAGE_BYTES)
#define AV_STAGE 30720
#define AV_SMEM (2*AV_STAGE)

// ---------------- scratch (static device; zero-initialized, pads stay zero) ---------
static __device__ float g_scp[(size_t)ZZ*TP*TP];                       // content+pos scores
static __device__ __nv_bfloat16 g_ath[(size_t)ZZ*TP*TP], g_atl[(size_t)ZZ*TP*TP];
static __device__ __nv_bfloat16 g_quh[(size_t)ZZ*TP*64], g_qul[(size_t)ZZ*TP*64];
static __device__ __nv_bfloat16 g_qvh[(size_t)ZZ*TP*64], g_qvl[(size_t)ZZ*TP*64];
static __device__ __nv_bfloat16 g_kkh[(size_t)ZZ*TP*64], g_kkl[(size_t)ZZ*TP*64];
static __device__ __nv_bfloat16 g_pph[(size_t)ZZ*TP*64], g_ppl[(size_t)ZZ*TP*64];
static __device__ __nv_bfloat16 g_vth[(size_t)ZZ*64*TP], g_vtl[(size_t)ZZ*64*TP];
static __device__ __nv_bfloat16 g_xnh[MP*(size_t)DD], g_xnl[MP*(size_t)DD];
static __device__ __nv_bfloat16 g_mkh[MP*(size_t)DD], g_mkl[MP*(size_t)DD];
static __device__ __nv_bfloat16 g_cxh[MP*(size_t)DD], g_cxl[MP*(size_t)DD];
static __device__ __nv_bfloat16 g_hph[(size_t)HPR*DFFX], g_hpl[(size_t)HPR*DFFX];
static __device__ __nv_bfloat16 g_wqh[3*DD*DD], g_wql[3*DD*DD];
static __device__ __nv_bfloat16 g_wkh[3*DD*DD], g_wkl[3*DD*DD];
static __device__ __nv_bfloat16 g_wvh[3*DD*DD], g_wvl[3*DD*DD];
static __device__ __nv_bfloat16 g_wph[3*DD*DD], g_wpl[3*DD*DD];
static __device__ __nv_bfloat16 g_woh[3*DD*DD], g_wol[3*DD*DD];
static __device__ __nv_bfloat16 g_w1h[3*DFFX*DD], g_w1l[3*DFFX*DD];
static __device__ __nv_bfloat16 g_w2h[3*3*DD*DFFX], g_w2l[3*3*DD*DFFX];

// ---------------- PTX helpers --------------------------------------------------------
__device__ __forceinline__ uint32_t smem_u32(const void* p) {
    uint32_t a;
    asm("{ .reg .u64 t; cvta.to.shared.u64 t, %1; cvt.u32.u64 %0, t; }" : "=r"(a) : "l"(p));
    return a;
}
__device__ __forceinline__ void cp16(uint32_t dst, const void* src) {
    asm volatile("cp.async.cg.shared.global [%0], [%1], 16;" :: "r"(dst), "l"(src) : "memory");
}
#define CP_COMMIT() asm volatile("cp.async.commit_group;" ::: "memory")
#define CP_WAIT1()  asm volatile("cp.async.wait_group 1;" ::: "memory")
#define CP_WAIT0()  asm volatile("cp.async.wait_group 0;" ::: "memory")

__device__ __forceinline__ void mma16816(float* c, const uint32_t* a, const uint32_t* b) {
    asm volatile(
        "mma.sync.aligned.m16n8k16.row.col.f32.bf16.bf16.f32 "
        "{%0,%1,%2,%3}, {%4,%5,%6,%7}, {%8,%9}, {%0,%1,%2,%3};"
        : "+f"(c[0]), "+f"(c[1]), "+f"(c[2]), "+f"(c[3])
        : "r"(a[0]), "r"(a[1]), "r"(a[2]), "r"(a[3]), "r"(b[0]), "r"(b[1]));
}
__device__ __forceinline__ uint32_t pack_hi(float v0, float v1) {
    __nv_bfloat16 h0 = __float2bfloat16(v0), h1 = __float2bfloat16(v1);
    return (uint32_t)__bfloat16_as_ushort(h0) | ((uint32_t)__bfloat16_as_ushort(h1) << 16);
}
__device__ __forceinline__ uint32_t pack_lo(float v0, float v1) {
    __nv_bfloat16 h0 = __float2bfloat16(v0), h1 = __float2bfloat16(v1);
    float l0 = v0 - __bfloat162float(h0), l1 = v1 - __bfloat162float(h1);
    return (uint32_t)__bfloat16_as_ushort(__float2bfloat16(l0)) |
           ((uint32_t)__bfloat16_as_ushort(__float2bfloat16(l1)) << 16);
}

// ---------------- split-bf16 conversion kernels --------------------------------------
__global__ void cvt_split(const float* __restrict__ in, __nv_bfloat16* __restrict__ hi,
                          __nv_bfloat16* __restrict__ lo, int n4) {
    int i = blockIdx.x * 256 + threadIdx.x;
    if (i >= n4) return;
    float4 v = ((const float4*)in)[i];
    float vv[4] = {v.x, v.y, v.z, v.w};
    __align__(8) __nv_bfloat16 h[4], l[4];
#pragma unroll
    for (int j = 0; j < 4; j++) {
        h[j] = __float2bfloat16(vv[j]);
        l[j] = __float2bfloat16(vv[j] - __bfloat162float(h[j]));
    }
    ((uint2*)hi)[i] = *(uint2*)h;
    ((uint2*)lo)[i] = *(uint2*)l;
}
__global__ void cvt_w2(const float* __restrict__ in, __nv_bfloat16* __restrict__ hi,
                       __nv_bfloat16* __restrict__ lo) {
    int idx = blockIdx.x * 256 + threadIdx.x;
    const int per_l = 3 * DD * DFFX;
    if (idx >= 3 * per_l) return;
    int l = idx / per_l; int r = idx - l * per_l;
    int s = r / (DD * DFFX); int r2 = r - s * (DD * DFFX);
    int n = r2 / DFFX; int k2 = r2 - n * DFFX;
    float v = in[(((size_t)l * DD + n) * DFFX + k2) * 3 + s];
    __nv_bfloat16 h = __float2bfloat16(v);
    hi[idx] = h;
    lo[idx] = __float2bfloat16(v - __bfloat162float(h));
}

// ---------------- HMMA split-bf16 GEMM, multiple output modes ------------------------
// MODE 0: fp32 C [m][N] (+ACC)   MODE 1: split-bf16 rows, padded-H remap (FF1, RELU)
// MODE 2: dual head-major out (O1 += bias2, O2 += bias3), layout [z][TP][64]
// MODE 3: single head-major out  MODE 4: transposed head-major out [z][64][TP]
template<int TAPS, bool ACC, bool RELU, int MODE>
__global__ __launch_bounds__(256, 2)
void hmma_gemm(const __nv_bfloat16* __restrict__ Ahi, const __nv_bfloat16* __restrict__ Alo,
               const __nv_bfloat16* __restrict__ Bhi, const __nv_bfloat16* __restrict__ Blo,
               const float* __restrict__ bias, const float* __restrict__ bias2,
               const float* __restrict__ bias3,
               float* __restrict__ Cf,
               __nv_bfloat16* __restrict__ O1h, __nv_bfloat16* __restrict__ O1l,
               __nv_bfloat16* __restrict__ O2h, __nv_bfloat16* __restrict__ O2l,
               int Mstore, int N, int K) {
    extern __shared__ char sm[];
    uint32_t dbase = smem_u32(sm);
    int tid = threadIdx.x, lane = tid & 31, w = tid >> 5;
    int wm = (w & 1) << 6, wn = (w >> 1) << 5;
    int bm = blockIdx.y << 7, bn = blockIdx.x << 7;

    uint32_t so[2]; long ga[2], gb[2];
#pragma unroll
    for (int j = 0; j < 2; j++) {
        int idx = tid + 256 * j; int row = idx >> 2, c16 = idx & 3;
        so[j] = row * 80 + c16 * 16;
        int grow = bm + row;
        long arow;
        if (TAPS == 3) { int b = grow / 351; int t = grow - b * 351; arow = (long)b * 353 + t; }
        else arow = grow;
        ga[j] = arow * (long)K + c16 * 8;
        gb[j] = (long)(bn + row) * K + c16 * 8;
    }
    const int kch = K >> 5;
    const int nch = TAPS * kch;

#define LOAD_CHUNK(c, stg) do { \
        int s_ = (c) / kch; int kb_ = ((c) - s_ * kch) << 5; \
        long sK_ = (TAPS == 3) ? (long)s_ * K : 0; \
        long sNK_ = (TAPS == 3) ? (long)s_ * N * K : 0; \
        uint32_t sb_ = dbase + (stg) * STAGE_BYTES; \
        _Pragma("unroll") \
        for (int j = 0; j < 2; j++) { \
            cp16(sb_ + so[j],         Ahi + sK_ + ga[j] + kb_); \
            cp16(sb_ + 10240 + so[j], Alo + sK_ + ga[j] + kb_); \
            cp16(sb_ + 20480 + so[j], Bhi + sNK_ + gb[j] + kb_); \
            cp16(sb_ + 30720 + so[j], Blo + sNK_ + gb[j] + kb_); \
        } \
    } while (0)

    float acc[4][4][4];
#pragma unroll
    for (int a = 0; a < 4; a++)
#pragma unroll
        for (int b = 0; b < 4; b++)
#pragma unroll
            for (int q2 = 0; q2 < 4; q2++) acc[a][b][q2] = 0.0f;

    int bq = lane & 3, bg = lane >> 2;

    LOAD_CHUNK(0, 0);
    CP_COMMIT();
#pragma unroll 1
    for (int c = 0; c < nch; c++) {
        if (c + 1 < nch) LOAD_CHUNK(c + 1, (c + 1) & 1);
        CP_COMMIT();
        CP_WAIT1();
        __syncthreads();
        const char* sA = sm + (c & 1) * STAGE_BYTES;
#pragma unroll
        for (int k16 = 0; k16 < 2; k16++) {
            int kbyte = k16 * 32 + bq * 4;
            uint32_t bh[4][2], bl[4][2];
#pragma unroll
            for (int ni = 0; ni < 4; ni++) {
                int n = wn + ni * 8 + bg;
                const char* pb = sA + 20480 + n * 80 + kbyte;
                bh[ni][0] = *(const uint32_t*)pb;
                bh[ni][1] = *(const uint32_t*)(pb + 16);
                const char* pl = pb + 10240;
                bl[ni][0] = *(const uint32_t*)pl;
                bl[ni][1] = *(const uint32_t*)(pl + 16);
            }
#pragma unroll
            for (int mi = 0; mi < 4; mi++) {
                int r = wm + mi * 16 + bg;
                const char* pa = sA + r * 80 + kbyte;
                uint32_t ah[4], al[4];
                ah[0] = *(const uint32_t*)pa;
                ah[1] = *(const uint32_t*)(pa + 8 * 80);
                ah[2] = *(const uint32_t*)(pa + 16);
                ah[3] = *(const uint32_t*)(pa + 8 * 80 + 16);
                const char* pal = pa + 10240;
                al[0] = *(const uint32_t*)pal;
                al[1] = *(const uint32_t*)(pal + 8 * 80);
                al[2] = *(const uint32_t*)(pal + 16);
                al[3] = *(const uint32_t*)(pal + 8 * 80 + 16);
#pragma unroll
                for (int ni = 0; ni < 4; ni++) {
                    mma16816(acc[mi][ni], ah, bh[ni]);
                    mma16816(acc[mi][ni], ah, bl[ni]);
                    mma16816(acc[mi][ni], al, bh[ni]);
                }
            }
        }
        __syncthreads();
    }
#undef LOAD_CHUNK

#pragma unroll
    for (int mi = 0; mi < 4; mi++) {
#pragma unroll
        for (int half = 0; half < 2; half++) {
            int m = bm + wm + mi * 16 + bg + half * 8;
            if (m >= Mstore) continue;
            int b = 0, t = 0; long crow = m;
            if (MODE == 1) { b = m / 351; t = m - b * 351; crow = (long)b * 353 + 1 + t; }
            if (MODE >= 2) { b = m / 351; t = m - b * 351; }
#pragma unroll
            for (int ni = 0; ni < 4; ni++) {
                int col = bn + wn + ni * 8 + bq * 2;
                float v0 = acc[mi][ni][half * 2 + 0];
                float v1 = acc[mi][ni][half * 2 + 1];
                if (bias) { v0 += bias[col]; v1 += bias[col + 1]; }
                if (RELU) { v0 = fmaxf(v0, 0.0f); v1 = fmaxf(v1, 0.0f); }
                if (MODE == 0) {
                    float* cp = Cf + (long)m * N + col;
                    if (ACC) { v0 += cp[0]; v1 += cp[1]; }
                    float2 st; st.x = v0; st.y = v1;
                    *(float2*)cp = st;
                } else if (MODE == 1) {
                    *(uint32_t*)(O1h + crow * (long)N + col) = pack_hi(v0, v1);
                    *(uint32_t*)(O1l + crow * (long)N + col) = pack_lo(v0, v1);
                } else if (MODE == 2 || MODE == 3) {
                    int h = col >> 6, d = col & 63;
                    long base = ((long)(b * 8 + h) * TP + t) * 64 + d;
                    float u0 = v0, u1 = v1;
                    if (bias2) { u0 += bias2[col]; u1 += bias2[col + 1]; }
                    *(uint32_t*)(O1h + base) = pack_hi(u0, u1);
                    *(uint32_t*)(O1l + base) = pack_lo(u0, u1);
                    if (MODE == 2) {
                        float w0 = v0 + bias3[col], w1 = v1 + bias3[col + 1];
                        *(uint32_t*)(O2h + base) = pack_hi(w0, w1);
                        *(uint32_t*)(O2l + base) = pack_lo(w0, w1);
                    }
                } else { // MODE 4: transposed [z][64][TP]
                    int h = col >> 6, d = col & 63;
                    long b0 = ((long)(b * 8 + h) * 64 + d) * TP + t;
                    long b1 = ((long)(b * 8 + h) * 64 + d + 1) * TP + t;
                    __nv_bfloat16 h0 = __float2bfloat16(v0), h1 = __float2bfloat16(v1);
                    O1h[b0] = h0; O1h[b1] = h1;
                    O1l[b0] = __float2bfloat16(v0 - __bfloat162float(h0));
                    O1l[b1] = __float2bfloat16(v1 - __bfloat162float(h1));
                }
            }
        }
    }
}

// ---------------- batched score HMMA: C[z][q][j] = A[z][q]·B[z][j] over K=64 --------
// SCATTER=false: direct store. SCATTER=true: rel-shift scatter-add into C.
template<bool SCATTER>
__global__ __launch_bounds__(256, 2)
void score_hmma(const __nv_bfloat16* __restrict__ Ahg, const __nv_bfloat16* __restrict__ Alg,
                const __nv_bfloat16* __restrict__ Bhg, const __nv_bfloat16* __restrict__ Blg,
                float* __restrict__ C) {
    extern __shared__ char sm[];
    uint32_t dbase = smem_u32(sm);
    int tid = threadIdx.x, lane = tid & 31, w = tid >> 5;
    int wm = (w & 1) << 6, wn = (w >> 1) << 5;
    int z = blockIdx.z, q0 = blockIdx.y << 7, j0 = blockIdx.x << 7;
    const __nv_bfloat16* Ah = Ahg + (long)z * TP * 64;
    const __nv_bfloat16* Al = Alg + (long)z * TP * 64;
    const __nv_bfloat16* Bh = Bhg + (long)z * TP * 64;
    const __nv_bfloat16* Bl = Blg + (long)z * TP * 64;
    float* Cz = C + (long)z * TP * TP;

    uint32_t so[2]; long ga[2], gb[2];
#pragma unroll
    for (int j = 0; j < 2; j++) {
        int idx = tid + 256 * j; int row = idx >> 2, c16 = idx & 3;
        so[j] = row * 80 + c16 * 16;
        ga[j] = (long)(q0 + row) * 64 + c16 * 8;
        gb[j] = (long)(j0 + row) * 64 + c16 * 8;
    }
    // preload both 32-chunks
#pragma unroll
    for (int c = 0; c < 2; c++) {
        uint32_t sb_ = dbase + c * STAGE_BYTES;
        int kb = c << 5;
#pragma unroll
        for (int j = 0; j < 2; j++) {
            cp16(sb_ + so[j],         Ah + ga[j] + kb);
            cp16(sb_ + 10240 + so[j], Al + ga[j] + kb);
            cp16(sb_ + 20480 + so[j], Bh + gb[j] + kb);
            cp16(sb_ + 30720 + so[j], Bl + gb[j] + kb);
        }
    }
    CP_COMMIT();
    CP_WAIT0();
    __syncthreads();

    float acc[4][4][4];
#pragma unroll
    for (int a = 0; a < 4; a++)
#pragma unroll
        for (int b = 0; b < 4; b++)
#pragma unroll
            for (int q2 = 0; q2 < 4; q2++) acc[a][b][q2] = 0.0f;
    int bq = lane & 3, bg = lane >> 4 == 0 ? lane >> 2 : lane >> 2; // bg = lane>>2
    bg = lane >> 2;

#pragma unroll
    for (int c = 0; c < 2; c++) {
        const char* sA = sm + c * STAGE_BYTES;
#pragma unroll
        for (int k16 = 0; k16 < 2; k16++) {
            int kbyte = k16 * 32 + bq * 4;
            uint32_t bh[4][2], bl[4][2];
#pragma unroll
            for (int ni = 0; ni < 4; ni++) {
                int n = wn + ni * 8 + bg;
                const char* pb = sA + 20480 + n * 80 + kbyte;
                bh[ni][0] = *(const uint32_t*)pb;
                bh[ni][1] = *(const uint32_t*)(pb + 16);
                const char* pl = pb + 10240;
                bl[ni][0] = *(const uint32_t*)pl;
                bl[ni][1] = *(const uint32_t*)(pl + 16);
            }
#pragma unroll
            for (int mi = 0; mi < 4; mi++) {
                int r = wm + mi * 16 + bg;
                const char* pa = sA + r * 80 + kbyte;
                uint32_t ah[4], al[4];
                ah[0] = *(const uint32_t*)pa;
                ah[1] = *(const uint32_t*)(pa + 8 * 80);
                ah[2] = *(const uint32_t*)(pa + 16);
                ah[3] = *(const uint32_t*)(pa + 8 * 80 + 16);
                const char* pal = pa + 10240;
                al[0] = *(const uint32_t*)pal;
                al[1] = *(const uint32_t*)(pal + 8 * 80);
                al[2] = *(const uint32_t*)(pal + 16);
                al[3] = *(const uint32_t*)(pal + 8 * 80 + 16);
#pragma unroll
                for (int ni = 0; ni < 4; ni++) {
                    mma16816(acc[mi][ni], ah, bh[ni]);
                    mma16816(acc[mi][ni], ah, bl[ni]);
                    mma16816(acc[mi][ni], al, bh[ni]);
                }
            }
        }
    }

#pragma unroll
    for (int mi = 0; mi < 4; mi++) {
#pragma unroll
        for (int half = 0; half < 2; half++) {
            int r = q0 + wm + mi * 16 + bg + half * 8;   // 0..383
#pragma unroll
            for (int ni = 0; ni < 4; ni++) {
                int j = j0 + wn + ni * 8 + bq * 2;
                float v0 = acc[mi][ni][half * 2 + 0];
                float v1 = acc[mi][ni][half * 2 + 1];
                if (!SCATTER) {
                    float2 st; st.x = v0; st.y = v1;
                    *(float2*)(Cz + (long)r * TP + j) = st;
                } else {
#pragma unroll
                    for (int e = 0; e < 2; e++) {
                        int jj = j + e;
                        if (jj >= TT) continue;
                        float vv = e ? v1 : v0;
                        if (jj >= 350 - r) {
                            Cz[(long)r * TP + (jj - 350 + r)] += vv;
                        } else if (r >= 1) {
                            Cz[(long)(r - 1) * TP + (jj + r + 1)] += vv;
                        }
                    }
                }
            }
        }
    }
}

// ---------------- batched attn·V HMMA: ctx[q][d] over K=384 --------------------------
__global__ __launch_bounds__(256, 2)
void attnv_hmma(const __nv_bfloat16* __restrict__ Ahg, const __nv_bfloat16* __restrict__ Alg,
                const __nv_bfloat16* __restrict__ Bhg, const __nv_bfloat16* __restrict__ Blg,
                __nv_bfloat16* __restrict__ Ch, __nv_bfloat16* __restrict__ Cl) {
    extern __shared__ char sm[];
    uint32_t dbase = smem_u32(sm);
    int tid = threadIdx.x, lane = tid & 31, w = tid >> 5;
    int wm = (w & 3) << 5, wn = (w >> 2) << 5;
    int z = blockIdx.z, q0 = blockIdx.y << 7;
    const __nv_bfloat16* Ah = Ahg + (long)z * TP * TP;
    const __nv_bfloat16* Al = Alg + (long)z * TP * TP;
    const __nv_bfloat16* Bh = Bhg + (long)z * 64 * TP;
    const __nv_bfloat16* Bl = Blg + (long)z * 64 * TP;

    uint32_t soA[2]; long gaA[2];
#pragma unroll
    for (int j = 0; j < 2; j++) {
        int idx = tid + 256 * j; int row = idx >> 2, c16 = idx & 3;
        soA[j] = row * 80 + c16 * 16;
        gaA[j] = (long)(q0 + row) * TP + c16 * 8;
    }
    uint32_t soB = (tid >> 2) * 80 + (tid & 3) * 16;
    long gB = (long)(tid >> 2) * TP + (tid & 3) * 8;

#define AV_LOAD(c, stg) do { \
        int kb_ = (c) << 5; \
        uint32_t sb_ = dbase + (stg) * AV_STAGE; \
        _Pragma("unroll") \
        for (int j = 0; j < 2; j++) { \
            cp16(sb_ + soA[j],         Ah + gaA[j] + kb_); \
            cp16(sb_ + 10240 + soA[j], Al + gaA[j] + kb_); \
        } \
        cp16(sb_ + 20480 + soB, Bh + gB + kb_); \
        cp16(sb_ + 25600 + soB, Bl + gB + kb_); \
    } while (0)

    float acc[2][4][4];
#pragma unroll
    for (int a = 0; a < 2; a++)
#pragma unroll
        for (int b = 0; b < 4; b++)
#pragma unroll
            for (int q2 = 0; q2 < 4; q2++) acc[a][b][q2] = 0.0f;
    int bq = lane & 3, bg = lane >> 2;

    AV_LOAD(0, 0);
    CP_COMMIT();
#pragma unroll 1
    for (int c = 0; c < 12; c++) {
        if (c + 1 < 12) AV_LOAD(c + 1, (c + 1) & 1);
        CP_COMMIT();
        CP_WAIT1();
        __syncthreads();
        const char* sA = sm + (c & 1) * AV_STAGE;
#pragma unroll
        for (int k16 = 0; k16 < 2; k16++) {
            int kbyte = k16 * 32 + bq * 4;
            uint32_t bh[4][2], bl[4][2];
#pragma unroll
            for (int ni = 0; ni < 4; ni++) {
                int n = wn + ni * 8 + bg;
                const char* pb = sA + 20480 + n * 80 + kbyte;
                bh[ni][0] = *(const uint32_t*)pb;
                bh[ni][1] = *(const uint32_t*)(pb + 16);
                const char* pl = pb + 5120;
                bl[ni][0] = *(const uint32_t*)pl;
                bl[ni][1] = *(const uint32_t*)(pl + 16);
            }
#pragma unroll
            for (int mi = 0; mi < 2; mi++) {
                int r = wm + mi * 16 + bg;
                const char* pa = sA + r * 80 + kbyte;
                uint32_t ah[4], al[4];
                ah[0] = *(const uint32_t*)pa;
                ah[1] = *(const uint32_t*)(pa + 8 * 80);
                ah[2] = *(const uint32_t*)(pa + 16);
                ah[3] = *(const uint32_t*)(pa + 8 * 80 + 16);
                const char* pal = pa + 10240;
                al[0] = *(const uint32_t*)pal;
                al[1] = *(const uint32_t*)(pal + 8 * 80);
                al[2] = *(const uint32_t*)(pal + 16);
                al[3] = *(const uint32_t*)(pal + 8 * 80 + 16);
#pragma unroll
                for (int ni = 0; ni < 4; ni++) {
                    mma16816(acc[mi][ni], ah, bh[ni]);
                    mma16816(acc[mi][ni], ah, bl[ni]);
                    mma16816(acc[mi][ni], al, bh[ni]);
                }
            }
        }
        __syncthreads();
    }
#undef AV_LOAD

    int b = z >> 3, h = z & 7;
#pragma unroll
    for (int mi = 0; mi < 2; mi++) {
#pragma unroll
        for (int half = 0; half < 2; half++) {
            int q = q0 + wm + mi * 16 + bg + half * 8;
            if (q >= TT) continue;
#pragma unroll
            for (int ni = 0; ni < 4; ni++) {
                int col = wn + ni * 8 + bq * 2;
                float v0 = acc[mi][ni][half * 2 + 0];
                float v1 = acc[mi][ni][half * 2 + 1];
                long addr = ((long)(b * 351 + q)) * DD + h * 64 + col;
                *(uint32_t*)(Ch + addr) = pack_hi(v0, v1);
                *(uint32_t*)(Cl + addr) = pack_lo(v0, v1);
            }
        }
    }
}

// ---------------- add pos-emb + LayerNorm --------------------------------------------
template<bool BF16O>
__global__ void addln_kernel(const float* __restrict__ xin, float* __restrict__ xupd,
                             const float* __restrict__ pe,
                             const float* __restrict__ ga, const float* __restrict__ gb,
                             float* __restrict__ out, __nv_bfloat16* __restrict__ ohi,
                             __nv_bfloat16* __restrict__ olo) {
    int row = blockIdx.x;
    int t   = row % TT;
    const float* xr = xin + (size_t)row * DD;
    int tid = threadIdx.x;
    float vals[4];
#pragma unroll
    for (int i = 0; i < 4; i++) {
        int c = tid + i * 128;
        float vv = xr[c];
        if (pe) vv += pe[(size_t)t * DD + c];
        vals[i] = vv;
    }
    if (pe) {
        float* xw = xupd + (size_t)row * DD;
#pragma unroll
        for (int i = 0; i < 4; i++) xw[tid + i * 128] = vals[i];
    }
    __shared__ float sh[4];
    float s = vals[0] + vals[1] + vals[2] + vals[3];
#pragma unroll
    for (int o = 16; o > 0; o >>= 1) s += __shfl_xor_sync(0xffffffffu, s, o);
    if ((tid & 31) == 0) sh[tid >> 5] = s;
    __syncthreads();
    float mean = (sh[0] + sh[1] + sh[2] + sh[3]) * (1.0f / DD);
    __syncthreads();
    float sq = 0.0f;
#pragma unroll
    for (int i = 0; i < 4; i++) { float d = vals[i] - mean; sq += d * d; }
#pragma unroll
    for (int o = 16; o > 0; o >>= 1) sq += __shfl_xor_sync(0xffffffffu, sq, o);
    if ((tid & 31) == 0) sh[tid >> 5] = sq;
    __syncthreads();
    float var  = sh[0] + sh[1] + sh[2] + sh[3];
    float stdv = sqrtf(var * (1.0f / (DD - 1)));
    float inv  = 1.0f / (stdv + 1e-6f);
#pragma unroll
    for (int i = 0; i < 4; i++) {
        int c = tid + i * 128;
        float v = ga[c] * (vals[i] - mean) * inv + gb[c];
        if (BF16O) {
            __nv_bfloat16 h = __float2bfloat16(v);
            ohi[(size_t)row * DD + c] = h;
            olo[(size_t)row * DD + c] = __float2bfloat16(v - __bfloat162float(h));
        } else {
            out[(size_t)row * DD + c] = v;
        }
    }
}

// ---------------- row softmax over padded scores -> split-bf16 attn ------------------
__global__ void softmax2_kernel(const float* __restrict__ SC,
                                __nv_bfloat16* __restrict__ Ah,
                                __nv_bfloat16* __restrict__ Al) {
    int q = blockIdx.x, z = blockIdx.y;
    const float* crow = SC + (long)z * TP * TP + (long)q * TP;
    long obase = (long)z * TP * TP + (long)q * TP;
    int tid = threadIdx.x;
    const float scale = 0.044194173824159216f;   // 1/sqrt(512)
    float vals[3];
    float mx = -1e30f;
#pragma unroll
    for (int i = 0; i < 3; i++) {
        int k = tid + i * 128;
        float vv = (k < TT) ? crow[k] * scale : -1e30f;
        vals[i] = vv;
        mx = fmaxf(mx, vv);
    }
    __shared__ float sh[4];
#pragma unroll
    for (int o = 16; o > 0; o >>= 1) mx = fmaxf(mx, __shfl_xor_sync(0xffffffffu, mx, o));
    if ((tid & 31) == 0) sh[tid >> 5] = mx;
    __syncthreads();
    mx = fmaxf(fmaxf(sh[0], sh[1]), fmaxf(sh[2], sh[3]));
    __syncthreads();
    float sum = 0.0f;
#pragma unroll
    for (int i = 0; i < 3; i++) {
        int k = tid + i * 128;
        if (k < TT) { vals[i] = __expf(vals[i] - mx); sum += vals[i]; }
        else vals[i] = 0.0f;
    }
#pragma unroll
    for (int o = 16; o > 0; o >>= 1) sum += __shfl_xor_sync(0xffffffffu, sum, o);
    if ((tid & 31) == 0) sh[tid >> 5] = sum;
    __syncthreads();
    float inv = 1.0f / (sh[0] + sh[1] + sh[2] + sh[3]);
#pragma unroll
    for (int i = 0; i < 3; i++) {
        int k = tid + i * 128;
        float a = (k < TT) ? vals[i] * inv : 0.0f;
        __nv_bfloat16 h = __float2bfloat16(a);
        Ah[obase + k] = h;
        Al[obase + k] = __float2bfloat16(a - __bfloat162float(h));
    }
}

// ------------------------------------ launch -----------------------------------------
extern "C" void kernel_launch(void* const* d_in, const int* in_sizes, int n_in,
                              void* d_out, int out_size) {
    const float* X0  = (const float*)d_in[0];
    const float* MSK = (const float*)d_in[1];
    const float* PE  = (const float*)d_in[2];
    const float* Wq  = (const float*)d_in[3];
    const float* bq  = (const float*)d_in[4];
    const float* Wk  = (const float*)d_in[5];
    const float* bk  = (const float*)d_in[6];
    const float* Wv  = (const float*)d_in[7];
    const float* bv  = (const float*)d_in[8];
    const float* Wp  = (const float*)d_in[9];
    const float* Ub  = (const float*)d_in[10];
    const float* Vb  = (const float*)d_in[11];
    const float* Wo  = (const float*)d_in[12];
    const float* bo  = (const float*)d_in[13];
    const float* l1a = (const float*)d_in[14];
    const float* l1b = (const float*)d_in[15];
    const float* l2a = (const float*)d_in[16];
    const float* l2b = (const float*)d_in[17];
    const float* W1  = (const float*)d_in[18];
    const float* b1  = (const float*)d_in[19];
    const float* W2  = (const float*)d_in[20];
    const float* b2  = (const float*)d_in[21];
    const float* fna = (const float*)d_in[22];
    const float* fnb = (const float*)d_in[23];
    float* x = (float*)d_out;

    float* scp;
    __nv_bfloat16 *ath, *atl, *quh, *qul, *qvh, *qvl, *kkh, *kkl, *pph, *ppl, *vth, *vtl;
    __nv_bfloat16 *xnh, *xnl, *mkh, *mkl, *cxh, *cxl, *hph, *hpl;
    __nv_bfloat16 *wqh, *wql, *wkh, *wkl, *wvh, *wvl, *wph, *wpl, *woh, *wol;
    __nv_bfloat16 *w1h, *w1l, *w2h, *w2l;
    cudaGetSymbolAddress((void**)&scp, g_scp);
    cudaGetSymbolAddress((void**)&ath, g_ath); cudaGetSymbolAddress((void**)&atl, g_atl);
    cudaGetSymbolAddress((void**)&quh, g_quh); cudaGetSymbolAddress((void**)&qul, g_qul);
    cudaGetSymbolAddress((void**)&qvh, g_qvh); cudaGetSymbolAddress((void**)&qvl, g_qvl);
    cudaGetSymbolAddress((void**)&kkh, g_kkh); cudaGetSymbolAddress((void**)&kkl, g_kkl);
    cudaGetSymbolAddress((void**)&pph, g_pph); cudaGetSymbolAddress((void**)&ppl, g_ppl);
    cudaGetSymbolAddress((void**)&vth, g_vth); cudaGetSymbolAddress((void**)&vtl, g_vtl);
    cudaGetSymbolAddress((void**)&xnh, g_xnh); cudaGetSymbolAddress((void**)&xnl, g_xnl);
    cudaGetSymbolAddress((void**)&mkh, g_mkh); cudaGetSymbolAddress((void**)&mkl, g_mkl);
    cudaGetSymbolAddress((void**)&cxh, g_cxh); cudaGetSymbolAddress((void**)&cxl, g_cxl);
    cudaGetSymbolAddress((void**)&hph, g_hph); cudaGetSymbolAddress((void**)&hpl, g_hpl);
    cudaGetSymbolAddress((void**)&wqh, g_wqh); cudaGetSymbolAddress((void**)&wql, g_wql);
    cudaGetSymbolAddress((void**)&wkh, g_wkh); cudaGetSymbolAddress((void**)&wkl, g_wkl);
    cudaGetSymbolAddress((void**)&wvh, g_wvh); cudaGetSymbolAddress((void**)&wvl, g_wvl);
    cudaGetSymbolAddress((void**)&wph, g_wph); cudaGetSymbolAddress((void**)&wpl, g_wpl);
    cudaGetSymbolAddress((void**)&woh, g_woh); cudaGetSymbolAddress((void**)&wol, g_wol);
    cudaGetSymbolAddress((void**)&w1h, g_w1h); cudaGetSymbolAddress((void**)&w1l, g_w1l);
    cudaGetSymbolAddress((void**)&w2h, g_w2h); cudaGetSymbolAddress((void**)&w2l, g_w2l);

    cudaFuncSetAttribute(hmma_gemm<1, true,  false, 0>, cudaFuncAttributeMaxDynamicSharedMemorySize, SMEMSZ);
    cudaFuncSetAttribute(hmma_gemm<3, true,  false, 0>, cudaFuncAttributeMaxDynamicSharedMemorySize, SMEMSZ);
    cudaFuncSetAttribute(hmma_gemm<1, false, true,  1>, cudaFuncAttributeMaxDynamicSharedMemorySize, SMEMSZ);
    cudaFuncSetAttribute(hmma_gemm<1, false, false, 2>, cudaFuncAttributeMaxDynamicSharedMemorySize, SMEMSZ);
    cudaFuncSetAttribute(hmma_gemm<1, false, false, 3>, cudaFuncAttributeMaxDynamicSharedMemorySize, SMEMSZ);
    cudaFuncSetAttribute(hmma_gemm<1, false, false, 4>, cudaFuncAttributeMaxDynamicSharedMemorySize, SMEMSZ);
    cudaFuncSetAttribute(score_hmma<false>, cudaFuncAttributeMaxDynamicSharedMemorySize, SMEMSZ);
    cudaFuncSetAttribute(score_hmma<true>,  cudaFuncAttributeMaxDynamicSharedMemorySize, SMEMSZ);
    cudaFuncSetAttribute(attnv_hmma,        cudaFuncAttributeMaxDynamicSharedMemorySize, AV_SMEM);

    int nW = 3 * DD * DD / 4;
    cvt_split<<<(nW + 255) / 256, 256>>>(Wq, wqh, wql, nW);
    cvt_split<<<(nW + 255) / 256, 256>>>(Wk, wkh, wkl, nW);
    cvt_split<<<(nW + 255) / 256, 256>>>(Wv, wvh, wvl, nW);
    cvt_split<<<(nW + 255) / 256, 256>>>(Wp, wph, wpl, nW);
    cvt_split<<<(nW + 255) / 256, 256>>>(Wo, woh, wol, nW);
    int n1 = 3 * DFFX * DD / 4;
    cvt_split<<<(n1 + 255) / 256, 256>>>(W1, w1h, w1l, n1);
    int nM = BT * DD / 4;
    cvt_split<<<(nM + 255) / 256, 256>>>(MSK, mkh, mkl, nM);
    int n2 = 3 * 3 * DD * DFFX;
    cvt_w2<<<(n2 + 255) / 256, 256>>>(W2, w2h, w2l);

    dim3 gP(4, MP / 128);
    dim3 gF(8, MP / 128);
    dim3 gSc(3, 3, ZZ);
    dim3 gAV(1, 3, ZZ);
    dim3 gSm(TT, ZZ);

    for (int i = 0; i < 3; i++) {
        size_t oD = (size_t)i * DD, oDD = (size_t)i * DD * DD;
        addln_kernel<true><<<BT, 128>>>(i == 0 ? X0 : x, x, PE + (size_t)i * TT * DD,
                                        l1a + oD, l1b + oD, nullptr, xnh, xnl);
        // Q -> (q+u) and (q+v), head-major
        hmma_gemm<1, false, false, 2><<<gP, 256, SMEMSZ>>>(
            xnh, xnl, wqh + oDD, wql + oDD, bq + oD, Ub + oD, Vb + oD,
            nullptr, quh, qul, qvh, qvl, BT, DD, DD);
        hmma_gemm<1, false, false, 3><<<gP, 256, SMEMSZ>>>(
            xnh, xnl, wkh + oDD, wkl + oDD, bk + oD, nullptr, nullptr,
            nullptr, kkh, kkl, nullptr, nullptr, BT, DD, DD);
        hmma_gemm<1, false, false, 3><<<gP, 256, SMEMSZ>>>(
            mkh, mkl, wph + oDD, wpl + oDD, nullptr, nullptr, nullptr,
            nullptr, pph, ppl, nullptr, nullptr, BT, DD, DD);
        hmma_gemm<1, false, false, 4><<<gP, 256, SMEMSZ>>>(
            xnh, xnl, wvh + oDD, wvl + oDD, bv + oD, nullptr, nullptr,
            nullptr, vth, vtl, nullptr, nullptr, BT, DD, DD);
        score_hmma<false><<<gSc, 256, SMEMSZ>>>(quh, qul, kkh, kkl, scp);
        score_hmma<true><<<gSc, 256, SMEMSZ>>>(qvh, qvl, pph, ppl, scp);
        softmax2_kernel<<<gSm, 128>>>(scp, ath, atl);
        attnv_hmma<<<gAV, 256, AV_SMEM>>>(ath, atl, vth, vtl, cxh, cxl);
        hmma_gemm<1, true, false, 0><<<gP, 256, SMEMSZ>>>(
            cxh, cxl, woh + oDD, wol + oDD, bo + oD, nullptr, nullptr,
            x, nullptr, nullptr, nullptr, nullptr, BT, DD, DD);
        addln_kernel<true><<<BT, 128>>>(x, nullptr, nullptr,
                                        l2a + oD, l2b + oD, nullptr, xnh, xnl);
        hmma_gemm<1, false, true, 1><<<gF, 256, SMEMSZ>>>(
            xnh, xnl, w1h + (size_t)i * DFFX * DD, w1l + (size_t)i * DFFX * DD,
            b1 + (size_t)i * DFFX, nullptr, nullptr,
            nullptr, hph, hpl, nullptr, nullptr, BT, DFFX, DD);
        hmma_gemm<3, true, false, 0><<<gP, 256, SMEMSZ>>>(
            hph, hpl, w2h + (size_t)i * 3 * DD * DFFX, w2l + (size_t)i * 3 * DD * DFFX,
            b2 + oD, nullptr, nullptr,
            x, nullptr, nullptr, nullptr, nullptr, BT, DD, DFFX);
    }
    addln_kernel<false><<<BT, 128>>>(x, nullptr, nullptr, fna, fnb, x, nullptr, nullptr);
}

// round 5
// speedup vs baseline: 2.3257x; 1.0778x over previous
#include <cuda_runtime.h>
#include <cuda_bf16.h>
#include <math.h>
#include <stdint.h>

#define BB   64
#define TT   351
#define DD   512
#define HH   8
#define DFFX 1024
#define BT   (BB*TT)       // 22464
#define MP   22528         // BT padded to multiple of 128
#define HPR  22784         // 64*353 padded-H rows + slack
#define TP   384           // padded T
#define ZZ   (BB*HH)       // 512
#define STAGE_BYTES 40960
#define SMEMSZ (2*STAGE_BYTES)
#define AV_STAGE 30720
#define AV_SMEM (2*AV_STAGE)

// fused-attention smem layout (bytes)
#define FS_PITCH 392                  // floats per score row
#define FS_QU    100352               // 64*392*4 score bytes before this
#define FS_QSZ   11520                // 80 rows * 144B
#define FS_QUL   (FS_QU + FS_QSZ)
#define FS_QV    (FS_QUL + FS_QSZ)
#define FS_QVL   (FS_QV + FS_QSZ)
#define FS_B     (FS_QVL + FS_QSZ)   // 146432
#define FS_BSZ   18432                // 128 rows * 144B
#define FS_BL    (FS_B + FS_BSZ)
#define FS_TOT   (FS_BL + FS_BSZ)    // 183296

// ---------------- scratch (static device; zero-initialized, pads stay zero) ---------
static __device__ __nv_bfloat16 g_ath[(size_t)ZZ*TP*TP], g_atl[(size_t)ZZ*TP*TP];
static __device__ __nv_bfloat16 g_quh[(size_t)ZZ*TP*64], g_qul[(size_t)ZZ*TP*64];
static __device__ __nv_bfloat16 g_qvh[(size_t)ZZ*TP*64], g_qvl[(size_t)ZZ*TP*64];
static __device__ __nv_bfloat16 g_kkh[(size_t)ZZ*TP*64], g_kkl[(size_t)ZZ*TP*64];
static __device__ __nv_bfloat16 g_pph[(size_t)ZZ*TP*64], g_ppl[(size_t)ZZ*TP*64];
static __device__ __nv_bfloat16 g_vth[(size_t)ZZ*64*TP], g_vtl[(size_t)ZZ*64*TP];
static __device__ __nv_bfloat16 g_xnh[MP*(size_t)DD], g_xnl[MP*(size_t)DD];
static __device__ __nv_bfloat16 g_mkh[MP*(size_t)DD], g_mkl[MP*(size_t)DD];
static __device__ __nv_bfloat16 g_cxh[MP*(size_t)DD], g_cxl[MP*(size_t)DD];
static __device__ __nv_bfloat16 g_hph[(size_t)HPR*DFFX], g_hpl[(size_t)HPR*DFFX];
static __device__ __nv_bfloat16 g_wqh[3*DD*DD], g_wql[3*DD*DD];
static __device__ __nv_bfloat16 g_wkh[3*DD*DD], g_wkl[3*DD*DD];
static __device__ __nv_bfloat16 g_wvh[3*DD*DD], g_wvl[3*DD*DD];
static __device__ __nv_bfloat16 g_wph[3*DD*DD], g_wpl[3*DD*DD];
static __device__ __nv_bfloat16 g_woh[3*DD*DD], g_wol[3*DD*DD];
static __device__ __nv_bfloat16 g_w1h[3*DFFX*DD], g_w1l[3*DFFX*DD];
static __device__ __nv_bfloat16 g_w2h[3*3*DD*DFFX], g_w2l[3*3*DD*DFFX];

// ---------------- PTX helpers --------------------------------------------------------
__device__ __forceinline__ uint32_t smem_u32(const void* p) {
    uint32_t a;
    asm("{ .reg .u64 t; cvta.to.shared.u64 t, %1; cvt.u32.u64 %0, t; }" : "=r"(a) : "l"(p));
    return a;
}
__device__ __forceinline__ void cp16(uint32_t dst, const void* src) {
    asm volatile("cp.async.cg.shared.global [%0], [%1], 16;" :: "r"(dst), "l"(src) : "memory");
}
#define CP_COMMIT() asm volatile("cp.async.commit_group;" ::: "memory")
#define CP_WAIT1()  asm volatile("cp.async.wait_group 1;" ::: "memory")
#define CP_WAIT0()  asm volatile("cp.async.wait_group 0;" ::: "memory")

__device__ __forceinline__ void mma16816(float* c, const uint32_t* a, const uint32_t* b) {
    asm volatile(
        "mma.sync.aligned.m16n8k16.row.col.f32.bf16.bf16.f32 "
        "{%0,%1,%2,%3}, {%4,%5,%6,%7}, {%8,%9}, {%0,%1,%2,%3};"
        : "+f"(c[0]), "+f"(c[1]), "+f"(c[2]), "+f"(c[3])
        : "r"(a[0]), "r"(a[1]), "r"(a[2]), "r"(a[3]), "r"(b[0]), "r"(b[1]));
}
__device__ __forceinline__ void ldsm4(uint32_t* r, uint32_t addr) {
    asm volatile("ldmatrix.sync.aligned.m8n8.x4.shared.b16 {%0,%1,%2,%3}, [%4];"
        : "=r"(r[0]), "=r"(r[1]), "=r"(r[2]), "=r"(r[3]) : "r"(addr));
}
__device__ __forceinline__ uint32_t pack_hi(float v0, float v1) {
    __nv_bfloat16 h0 = __float2bfloat16(v0), h1 = __float2bfloat16(v1);
    return (uint32_t)__bfloat16_as_ushort(h0) | ((uint32_t)__bfloat16_as_ushort(h1) << 16);
}
__device__ __forceinline__ uint32_t pack_lo(float v0, float v1) {
    __nv_bfloat16 h0 = __float2bfloat16(v0), h1 = __float2bfloat16(v1);
    float l0 = v0 - __bfloat162float(h0), l1 = v1 - __bfloat162float(h1);
    return (uint32_t)__bfloat16_as_ushort(__float2bfloat16(l0)) |
           ((uint32_t)__bfloat16_as_ushort(__float2bfloat16(l1)) << 16);
}

// ---------------- split-bf16 conversion kernels --------------------------------------
__global__ void cvt_split(const float* __restrict__ in, __nv_bfloat16* __restrict__ hi,
                          __nv_bfloat16* __restrict__ lo, int n4) {
    int i = blockIdx.x * 256 + threadIdx.x;
    if (i >= n4) return;
    float4 v = ((const float4*)in)[i];
    float vv[4] = {v.x, v.y, v.z, v.w};
    __align__(8) __nv_bfloat16 h[4], l[4];
#pragma unroll
    for (int j = 0; j < 4; j++) {
        h[j] = __float2bfloat16(vv[j]);
        l[j] = __float2bfloat16(vv[j] - __bfloat162float(h[j]));
    }
    ((uint2*)hi)[i] = *(uint2*)h;
    ((uint2*)lo)[i] = *(uint2*)l;
}
__global__ void cvt_w2(const float* __restrict__ in, __nv_bfloat16* __restrict__ hi,
                       __nv_bfloat16* __restrict__ lo) {
    int idx = blockIdx.x * 256 + threadIdx.x;
    const int per_l = 3 * DD * DFFX;
    if (idx >= 3 * per_l) return;
    int l = idx / per_l; int r = idx - l * per_l;
    int s = r / (DD * DFFX); int r2 = r - s * (DD * DFFX);
    int n = r2 / DFFX; int k2 = r2 - n * DFFX;
    float v = in[(((size_t)l * DD + n) * DFFX + k2) * 3 + s];
    __nv_bfloat16 h = __float2bfloat16(v);
    hi[idx] = h;
    lo[idx] = __float2bfloat16(v - __bfloat162float(h));
}

// ---------------- HMMA split-bf16 GEMM (ldmatrix fragments) --------------------------
// MODE 0: fp32 C (+ACC). MODE 1: split-bf16 padded-H (FF1). MODE 2: dual head-major.
// MODE 3: single head-major. MODE 4: transposed head-major.
template<int TAPS, bool ACC, bool RELU, int MODE>
__global__ __launch_bounds__(256, 2)
void hmma_gemm(const __nv_bfloat16* __restrict__ Ahi, const __nv_bfloat16* __restrict__ Alo,
               const __nv_bfloat16* __restrict__ Bhi, const __nv_bfloat16* __restrict__ Blo,
               const float* __restrict__ bias, const float* __restrict__ bias2,
               const float* __restrict__ bias3,
               float* __restrict__ Cf,
               __nv_bfloat16* __restrict__ O1h, __nv_bfloat16* __restrict__ O1l,
               __nv_bfloat16* __restrict__ O2h, __nv_bfloat16* __restrict__ O2l,
               int Mstore, int N, int K) {
    extern __shared__ char sm[];
    uint32_t dbase = smem_u32(sm);
    int tid = threadIdx.x, lane = tid & 31, w = tid >> 5;
    int wm = (w & 1) << 6, wn = (w >> 1) << 5;
    int bm = blockIdx.y << 7, bn = blockIdx.x << 7;

    uint32_t so[2]; long ga[2], gb[2];
#pragma unroll
    for (int j = 0; j < 2; j++) {
        int idx = tid + 256 * j; int row = idx >> 2, c16 = idx & 3;
        so[j] = row * 80 + c16 * 16;
        int grow = bm + row;
        long arow;
        if (TAPS == 3) { int b = grow / 351; int t = grow - b * 351; arow = (long)b * 353 + t; }
        else arow = grow;
        ga[j] = arow * (long)K + c16 * 8;
        gb[j] = (long)(bn + row) * K + c16 * 8;
    }
    const int kch = K >> 5;
    const int nch = TAPS * kch;

#define LOAD_CHUNK(c, stg) do { \
        int s_ = (c) / kch; int kb_ = ((c) - s_ * kch) << 5; \
        long sK_ = (TAPS == 3) ? (long)s_ * K : 0; \
        long sNK_ = (TAPS == 3) ? (long)s_ * N * K : 0; \
        uint32_t sb_ = dbase + (stg) * STAGE_BYTES; \
        _Pragma("unroll") \
        for (int j = 0; j < 2; j++) { \
            cp16(sb_ + so[j],         Ahi + sK_ + ga[j] + kb_); \
            cp16(sb_ + 10240 + so[j], Alo + sK_ + ga[j] + kb_); \
            cp16(sb_ + 20480 + so[j], Bhi + sNK_ + gb[j] + kb_); \
            cp16(sb_ + 30720 + so[j], Blo + sNK_ + gb[j] + kb_); \
        } \
    } while (0)

    float acc[4][4][4];
#pragma unroll
    for (int a = 0; a < 4; a++)
#pragma unroll
        for (int b = 0; b < 4; b++)
#pragma unroll
            for (int q2 = 0; q2 < 4; q2++) acc[a][b][q2] = 0.0f;

    int bq = lane & 3, bg = lane >> 2;
    uint32_t aoff = (uint32_t)(wm + (lane & 15)) * 80 + (uint32_t)(((lane >> 4) & 1) << 4);
    uint32_t boff = 20480u + (uint32_t)(wn + ((lane >> 4) << 3) + (lane & 7)) * 80
                  + (uint32_t)(((lane >> 3) & 1) << 4);

    LOAD_CHUNK(0, 0);
    CP_COMMIT();
#pragma unroll 1
    for (int c = 0; c < nch; c++) {
        if (c + 1 < nch) LOAD_CHUNK(c + 1, (c + 1) & 1);
        CP_COMMIT();
        CP_WAIT1();
        __syncthreads();
        uint32_t sb = dbase + (c & 1) * STAGE_BYTES;
#pragma unroll
        for (int k16 = 0; k16 < 2; k16++) {
            uint32_t kof = k16 * 32;
            uint32_t bh[4][2], bl[4][2], t[4];
            ldsm4(t, sb + boff + kof);
            bh[0][0] = t[0]; bh[0][1] = t[1]; bh[1][0] = t[2]; bh[1][1] = t[3];
            ldsm4(t, sb + boff + 1280 + kof);
            bh[2][0] = t[0]; bh[2][1] = t[1]; bh[3][0] = t[2]; bh[3][1] = t[3];
            ldsm4(t, sb + boff + 10240 + kof);
            bl[0][0] = t[0]; bl[0][1] = t[1]; bl[1][0] = t[2]; bl[1][1] = t[3];
            ldsm4(t, sb + boff + 10240 + 1280 + kof);
            bl[2][0] = t[0]; bl[2][1] = t[1]; bl[3][0] = t[2]; bl[3][1] = t[3];
#pragma unroll
            for (int mi = 0; mi < 4; mi++) {
                uint32_t ah[4], al[4];
                ldsm4(ah, sb + aoff + mi * 1280 + kof);
                ldsm4(al, sb + aoff + mi * 1280 + 10240 + kof);
#pragma unroll
                for (int ni = 0; ni < 4; ni++) {
                    mma16816(acc[mi][ni], ah, bh[ni]);
                    mma16816(acc[mi][ni], ah, bl[ni]);
                    mma16816(acc[mi][ni], al, bh[ni]);
                }
            }
        }
        __syncthreads();
    }
#undef LOAD_CHUNK

#pragma unroll
    for (int mi = 0; mi < 4; mi++) {
#pragma unroll
        for (int half = 0; half < 2; half++) {
            int m = bm + wm + mi * 16 + bg + half * 8;
            if (m >= Mstore) continue;
            int b = 0, t = 0; long crow = m;
            if (MODE == 1) { b = m / 351; t = m - b * 351; crow = (long)b * 353 + 1 + t; }
            if (MODE >= 2) { b = m / 351; t = m - b * 351; }
#pragma unroll
            for (int ni = 0; ni < 4; ni++) {
                int col = bn + wn + ni * 8 + bq * 2;
                float v0 = acc[mi][ni][half * 2 + 0];
                float v1 = acc[mi][ni][half * 2 + 1];
                if (bias) { v0 += bias[col]; v1 += bias[col + 1]; }
                if (RELU) { v0 = fmaxf(v0, 0.0f); v1 = fmaxf(v1, 0.0f); }
                if (MODE == 0) {
                    float* cp = Cf + (long)m * N + col;
                    if (ACC) { v0 += cp[0]; v1 += cp[1]; }
                    float2 st; st.x = v0; st.y = v1;
                    *(float2*)cp = st;
                } else if (MODE == 1) {
                    *(uint32_t*)(O1h + crow * (long)N + col) = pack_hi(v0, v1);
                    *(uint32_t*)(O1l + crow * (long)N + col) = pack_lo(v0, v1);
                } else if (MODE == 2 || MODE == 3) {
                    int h = col >> 6, d = col & 63;
                    long base = ((long)(b * 8 + h) * TP + t) * 64 + d;
                    float u0 = v0, u1 = v1;
                    if (bias2) { u0 += bias2[col]; u1 += bias2[col + 1]; }
                    *(uint32_t*)(O1h + base) = pack_hi(u0, u1);
                    *(uint32_t*)(O1l + base) = pack_lo(u0, u1);
                    if (MODE == 2) {
                        float w0 = v0 + bias3[col], w1 = v1 + bias3[col + 1];
                        *(uint32_t*)(O2h + base) = pack_hi(w0, w1);
                        *(uint32_t*)(O2l + base) = pack_lo(w0, w1);
                    }
                } else { // MODE 4
                    int h = col >> 6, d = col & 63;
                    long b0 = ((long)(b * 8 + h) * 64 + d) * TP + t;
                    long b1 = ((long)(b * 8 + h) * 64 + d + 1) * TP + t;
                    __nv_bfloat16 h0 = __float2bfloat16(v0), h1 = __float2bfloat16(v1);
                    O1h[b0] = h0; O1h[b1] = h1;
                    O1l[b0] = __float2bfloat16(v0 - __bfloat162float(h0));
                    O1l[b1] = __float2bfloat16(v1 - __bfloat162float(h1));
                }
            }
        }
    }
}

// ---------------- fused attention: scores + rel-shift + softmax ----------------------
// block: z = blockIdx.y, q-rows [q0, q0+63]. smem: S[64][392] fp32 + operand tiles.
__global__ __launch_bounds__(256, 1)
void attn_fused(const __nv_bfloat16* __restrict__ quh, const __nv_bfloat16* __restrict__ qul,
                const __nv_bfloat16* __restrict__ qvh, const __nv_bfloat16* __restrict__ qvl,
                const __nv_bfloat16* __restrict__ kkh, const __nv_bfloat16* __restrict__ kkl,
                const __nv_bfloat16* __restrict__ pph, const __nv_bfloat16* __restrict__ ppl,
                __nv_bfloat16* __restrict__ ath, __nv_bfloat16* __restrict__ atl) {
    extern __shared__ char sm[];
    uint32_t dbase = smem_u32(sm);
    float* S = (float*)sm;
    int z = blockIdx.y, q0 = blockIdx.x << 6;
    int tid = threadIdx.x, lane = tid & 31, w = tid >> 5;
    int wn = w << 4;
    int bq = lane & 3, bg = lane >> 2;

    // load QU/QV tiles (80 rows, clamp out-of-range rows to a safe source)
    for (int i = tid; i < 640; i += 256) {
        int r = i >> 3, c = i & 7;
        int gq = q0 + r; if (gq >= TP) gq = q0;
        long off = ((long)z * TP + gq) * 64 + c * 8;
        uint32_t so = r * 144 + c * 16;
        cp16(dbase + FS_QU  + so, quh + off);
        cp16(dbase + FS_QUL + so, qul + off);
        cp16(dbase + FS_QV  + so, qvh + off);
        cp16(dbase + FS_QVL + so, qvl + off);
    }
    CP_COMMIT();

    // ---- phase 1: content scores into S ----
#pragma unroll 1
    for (int c = 0; c < 3; c++) {
        for (int i = tid; i < 1024; i += 256) {
            int r = i >> 3, cc = i & 7;
            long off = ((long)z * TP + c * 128 + r) * 64 + cc * 8;
            uint32_t so = r * 144 + cc * 16;
            cp16(dbase + FS_B  + so, kkh + off);
            cp16(dbase + FS_BL + so, kkl + off);
        }
        CP_COMMIT(); CP_WAIT0(); __syncthreads();
        float acc[4][2][4];
#pragma unroll
        for (int a = 0; a < 4; a++)
#pragma unroll
            for (int b = 0; b < 2; b++)
#pragma unroll
                for (int e = 0; e < 4; e++) acc[a][b][e] = 0.0f;
#pragma unroll
        for (int k16 = 0; k16 < 4; k16++) {
            int kb = k16 * 32 + bq * 4;
            uint32_t bh[2][2], bl[2][2];
#pragma unroll
            for (int ni = 0; ni < 2; ni++) {
                const char* pb = sm + FS_B + (wn + ni * 8 + bg) * 144 + kb;
                bh[ni][0] = *(const uint32_t*)pb;
                bh[ni][1] = *(const uint32_t*)(pb + 16);
                bl[ni][0] = *(const uint32_t*)(pb + FS_BSZ);
                bl[ni][1] = *(const uint32_t*)(pb + FS_BSZ + 16);
            }
#pragma unroll
            for (int mi = 0; mi < 4; mi++) {
                const char* pa = sm + FS_QU + (mi * 16 + bg) * 144 + kb;
                uint32_t ah[4], al[4];
                ah[0] = *(const uint32_t*)pa;
                ah[1] = *(const uint32_t*)(pa + 8 * 144);
                ah[2] = *(const uint32_t*)(pa + 16);
                ah[3] = *(const uint32_t*)(pa + 8 * 144 + 16);
                al[0] = *(const uint32_t*)(pa + FS_QSZ);
                al[1] = *(const uint32_t*)(pa + FS_QSZ + 8 * 144);
                al[2] = *(const uint32_t*)(pa + FS_QSZ + 16);
                al[3] = *(const uint32_t*)(pa + FS_QSZ + 8 * 144 + 16);
#pragma unroll
                for (int ni = 0; ni < 2; ni++) {
                    mma16816(acc[mi][ni], ah, bh[ni]);
                    mma16816(acc[mi][ni], ah, bl[ni]);
                    mma16816(acc[mi][ni], al, bh[ni]);
                }
            }
        }
#pragma unroll
        for (int mi = 0; mi < 4; mi++)
#pragma unroll
            for (int half = 0; half < 2; half++) {
                int r = mi * 16 + bg + half * 8;
#pragma unroll
                for (int ni = 0; ni < 2; ni++) {
                    int col = c * 128 + wn + ni * 8 + bq * 2;
                    S[r * FS_PITCH + col]     = acc[mi][ni][half * 2 + 0];
                    S[r * FS_PITCH + col + 1] = acc[mi][ni][half * 2 + 1];
                }
            }
        __syncthreads();
    }

    // ---- phase 2: pos scores, rel-shift scatter-add into S ----
#pragma unroll 1
    for (int c = 0; c < 3; c++) {
        for (int i = tid; i < 1024; i += 256) {
            int r = i >> 3, cc = i & 7;
            long off = ((long)z * TP + c * 128 + r) * 64 + cc * 8;
            uint32_t so = r * 144 + cc * 16;
            cp16(dbase + FS_B  + so, pph + off);
            cp16(dbase + FS_BL + so, ppl + off);
        }
        CP_COMMIT(); CP_WAIT0(); __syncthreads();
        float acc[5][2][4];
#pragma unroll
        for (int a = 0; a < 5; a++)
#pragma unroll
            for (int b = 0; b < 2; b++)
#pragma unroll
                for (int e = 0; e < 4; e++) acc[a][b][e] = 0.0f;
#pragma unroll
        for (int k16 = 0; k16 < 4; k16++) {
            int kb = k16 * 32 + bq * 4;
            uint32_t bh[2][2], bl[2][2];
#pragma unroll
            for (int ni = 0; ni < 2; ni++) {
                const char* pb = sm + FS_B + (wn + ni * 8 + bg) * 144 + kb;
                bh[ni][0] = *(const uint32_t*)pb;
                bh[ni][1] = *(const uint32_t*)(pb + 16);
                bl[ni][0] = *(const uint32_t*)(pb + FS_BSZ);
                bl[ni][1] = *(const uint32_t*)(pb + FS_BSZ + 16);
            }
#pragma unroll
            for (int mi = 0; mi < 5; mi++) {
                const char* pa = sm + FS_QV + (mi * 16 + bg) * 144 + kb;
                uint32_t ah[4], al[4];
                ah[0] = *(const uint32_t*)pa;
                ah[1] = *(const uint32_t*)(pa + 8 * 144);
                ah[2] = *(const uint32_t*)(pa + 16);
                ah[3] = *(const uint32_t*)(pa + 8 * 144 + 16);
                al[0] = *(const uint32_t*)(pa + FS_QSZ);
                al[1] = *(const uint32_t*)(pa + FS_QSZ + 8 * 144);
                al[2] = *(const uint32_t*)(pa + FS_QSZ + 16);
                al[3] = *(const uint32_t*)(pa + FS_QSZ + 8 * 144 + 16);
#pragma unroll
                for (int ni = 0; ni < 2; ni++) {
                    mma16816(acc[mi][ni], ah, bh[ni]);
                    mma16816(acc[mi][ni], ah, bl[ni]);
                    mma16816(acc[mi][ni], al, bh[ni]);
                }
            }
        }
#pragma unroll
        for (int mi = 0; mi < 5; mi++)
#pragma unroll
            for (int half = 0; half < 2; half++) {
                int r = mi * 16 + bg + half * 8;
                if (r > 64) continue;
                int rp = q0 + r;
#pragma unroll
                for (int ni = 0; ni < 2; ni++)
#pragma unroll
                    for (int e = 0; e < 2; e++) {
                        int jj = c * 128 + wn + ni * 8 + bq * 2 + e;
                        if (jj >= TT) continue;
                        float v = acc[mi][ni][half * 2 + e];
                        if (jj >= 350 - rp) {
                            if (r < 64) atomicAdd(&S[r * FS_PITCH + jj - 350 + rp], v);
                        } else if (r >= 1) {
                            atomicAdd(&S[(r - 1) * FS_PITCH + jj + rp + 1], v);
                        }
                    }
            }
        __syncthreads();
    }

    // ---- softmax + split-bf16 store ----
    {
        int r = tid >> 2, qu = tid & 3;
        int gq = q0 + r;
        long rowbase = ((long)z * TP + gq) * TP;
        const float scale = 0.044194173824159216f;
        float* Srow = S + r * FS_PITCH;
        int c0 = qu * 96;
        if (gq >= TT) {
            for (int cc = c0; cc < c0 + 96; cc += 2) {
                *(uint32_t*)(ath + rowbase + cc) = 0u;
                *(uint32_t*)(atl + rowbase + cc) = 0u;
            }
        } else {
            float mx = -1e30f;
            for (int cc = c0; cc < c0 + 96; cc++)
                if (cc < TT) mx = fmaxf(mx, Srow[cc]);
            mx = fmaxf(mx, __shfl_xor_sync(0xffffffffu, mx, 1));
            mx = fmaxf(mx, __shfl_xor_sync(0xffffffffu, mx, 2));
            float mxs = mx * scale;
            float sum = 0.0f;
            for (int cc = c0; cc < c0 + 96; cc++)
                if (cc < TT) {
                    float e = __expf(Srow[cc] * scale - mxs);
                    Srow[cc] = e;
                    sum += e;
                }
            sum += __shfl_xor_sync(0xffffffffu, sum, 1);
            sum += __shfl_xor_sync(0xffffffffu, sum, 2);
            float inv = 1.0f / sum;
            for (int cc = c0; cc < c0 + 96; cc += 2) {
                float v0 = (cc < TT)     ? Srow[cc] * inv     : 0.0f;
                float v1 = (cc + 1 < TT) ? Srow[cc + 1] * inv : 0.0f;
                *(uint32_t*)(ath + rowbase + cc) = pack_hi(v0, v1);
                *(uint32_t*)(atl + rowbase + cc) = pack_lo(v0, v1);
            }
        }
    }
}

// ---------------- batched attn·V HMMA (ldmatrix) -------------------------------------
__global__ __launch_bounds__(256, 2)
void attnv_hmma(const __nv_bfloat16* __restrict__ Ahg, const __nv_bfloat16* __restrict__ Alg,
                const __nv_bfloat16* __restrict__ Bhg, const __nv_bfloat16* __restrict__ Blg,
                __nv_bfloat16* __restrict__ Ch, __nv_bfloat16* __restrict__ Cl) {
    extern __shared__ char sm[];
    uint32_t dbase = smem_u32(sm);
    int tid = threadIdx.x, lane = tid & 31, w = tid >> 5;
    int wm = (w & 3) << 5, wn = (w >> 2) << 5;
    int z = blockIdx.z, q0 = blockIdx.y << 7;
    const __nv_bfloat16* Ah = Ahg + (long)z * TP * TP;
    const __nv_bfloat16* Al = Alg + (long)z * TP * TP;
    const __nv_bfloat16* Bh = Bhg + (long)z * 64 * TP;
    const __nv_bfloat16* Bl = Blg + (long)z * 64 * TP;

    uint32_t soA[2]; long gaA[2];
#pragma unroll
    for (int j = 0; j < 2; j++) {
        int idx = tid + 256 * j; int row = idx >> 2, c16 = idx & 3;
        soA[j] = row * 80 + c16 * 16;
        gaA[j] = (long)(q0 + row) * TP + c16 * 8;
    }
    uint32_t soB = (tid >> 2) * 80 + (tid & 3) * 16;
    long gB = (long)(tid >> 2) * TP + (tid & 3) * 8;

#define AV_LOAD(c, stg) do { \
        int kb_ = (c) << 5; \
        uint32_t sb_ = dbase + (stg) * AV_STAGE; \
        _Pragma("unroll") \
        for (int j = 0; j < 2; j++) { \
            cp16(sb_ + soA[j],         Ah + gaA[j] + kb_); \
            cp16(sb_ + 10240 + soA[j], Al + gaA[j] + kb_); \
        } \
        cp16(sb_ + 20480 + soB, Bh + gB + kb_); \
        cp16(sb_ + 25600 + soB, Bl + gB + kb_); \
    } while (0)

    float acc[2][4][4];
#pragma unroll
    for (int a = 0; a < 2; a++)
#pragma unroll
        for (int b = 0; b < 4; b++)
#pragma unroll
            for (int q2 = 0; q2 < 4; q2++) acc[a][b][q2] = 0.0f;
    int bq = lane & 3, bg = lane >> 2;
    uint32_t aoff = (uint32_t)(wm + (lane & 15)) * 80 + (uint32_t)(((lane >> 4) & 1) << 4);
    uint32_t boff = 20480u + (uint32_t)(wn + ((lane >> 4) << 3) + (lane & 7)) * 80
                  + (uint32_t)(((lane >> 3) & 1) << 4);

    AV_LOAD(0, 0);
    CP_COMMIT();
#pragma unroll 1
    for (int c = 0; c < 12; c++) {
        if (c + 1 < 12) AV_LOAD(c + 1, (c + 1) & 1);
        CP_COMMIT();
        CP_WAIT1();
        __syncthreads();
        uint32_t sb = dbase + (c & 1) * AV_STAGE;
#pragma unroll
        for (int k16 = 0; k16 < 2; k16++) {
            uint32_t kof = k16 * 32;
            uint32_t bh[4][2], bl[4][2], t[4];
            ldsm4(t, sb + boff + kof);
            bh[0][0] = t[0]; bh[0][1] = t[1]; bh[1][0] = t[2]; bh[1][1] = t[3];
            ldsm4(t, sb + boff + 1280 + kof);
            bh[2][0] = t[0]; bh[2][1] = t[1]; bh[3][0] = t[2]; bh[3][1] = t[3];
            ldsm4(t, sb + boff + 5120 + kof);
            bl[0][0] = t[0]; bl[0][1] = t[1]; bl[1][0] = t[2]; bl[1][1] = t[3];
            ldsm4(t, sb + boff + 5120 + 1280 + kof);
            bl[2][0] = t[0]; bl[2][1] = t[1]; bl[3][0] = t[2]; bl[3][1] = t[3];
#pragma unroll
            for (int mi = 0; mi < 2; mi++) {
                uint32_t ah[4], al[4];
                ldsm4(ah, sb + aoff + mi * 1280 + kof);
                ldsm4(al, sb + aoff + mi * 1280 + 10240 + kof);
#pragma unroll
                for (int ni = 0; ni < 4; ni++) {
                    mma16816(acc[mi][ni], ah, bh[ni]);
                    mma16816(acc[mi][ni], ah, bl[ni]);
                    mma16816(acc[mi][ni], al, bh[ni]);
                }
            }
        }
        __syncthreads();
    }
#undef AV_LOAD

    int b = z >> 3, h = z & 7;
#pragma unroll
    for (int mi = 0; mi < 2; mi++) {
#pragma unroll
        for (int half = 0; half < 2; half++) {
            int q = q0 + wm + mi * 16 + bg + half * 8;
            if (q >= TT) continue;
#pragma unroll
            for (int ni = 0; ni < 4; ni++) {
                int col = wn + ni * 8 + bq * 2;
                float v0 = acc[mi][ni][half * 2 + 0];
                float v1 = acc[mi][ni][half * 2 + 1];
                long addr = ((long)(b * 351 + q)) * DD + h * 64 + col;
                *(uint32_t*)(Ch + addr) = pack_hi(v0, v1);
                *(uint32_t*)(Cl + addr) = pack_lo(v0, v1);
            }
        }
    }
}

// ---------------- add pos-emb + LayerNorm --------------------------------------------
template<bool BF16O>
__global__ void addln_kernel(const float* __restrict__ xin, float* __restrict__ xupd,
                             const float* __restrict__ pe,
                             const float* __restrict__ ga, const float* __restrict__ gb,
                             float* __restrict__ out, __nv_bfloat16* __restrict__ ohi,
                             __nv_bfloat16* __restrict__ olo) {
    int row = blockIdx.x;
    int t   = row % TT;
    const float* xr = xin + (size_t)row * DD;
    int tid = threadIdx.x;
    float vals[4];
#pragma unroll
    for (int i = 0; i < 4; i++) {
        int c = tid + i * 128;
        float vv = xr[c];
        if (pe) vv += pe[(size_t)t * DD + c];
        vals[i] = vv;
    }
    if (pe) {
        float* xw = xupd + (size_t)row * DD;
#pragma unroll
        for (int i = 0; i < 4; i++) xw[tid + i * 128] = vals[i];
    }
    __shared__ float sh[4];
    float s = vals[0] + vals[1] + vals[2] + vals[3];
#pragma unroll
    for (int o = 16; o > 0; o >>= 1) s += __shfl_xor_sync(0xffffffffu, s, o);
    if ((tid & 31) == 0) sh[tid >> 5] = s;
    __syncthreads();
    float mean = (sh[0] + sh[1] + sh[2] + sh[3]) * (1.0f / DD);
    __syncthreads();
    float sq = 0.0f;
#pragma unroll
    for (int i = 0; i < 4; i++) { float d = vals[i] - mean; sq += d * d; }
#pragma unroll
    for (int o = 16; o > 0; o >>= 1) sq += __shfl_xor_sync(0xffffffffu, sq, o);
    if ((tid & 31) == 0) sh[tid >> 5] = sq;
    __syncthreads();
    float var  = sh[0] + sh[1] + sh[2] + sh[3];
    float stdv = sqrtf(var * (1.0f / (DD - 1)));
    float inv  = 1.0f / (stdv + 1e-6f);
#pragma unroll
    for (int i = 0; i < 4; i++) {
        int c = tid + i * 128;
        float v = ga[c] * (vals[i] - mean) * inv + gb[c];
        if (BF16O) {
            __nv_bfloat16 h = __float2bfloat16(v);
            ohi[(size_t)row * DD + c] = h;
            olo[(size_t)row * DD + c] = __float2bfloat16(v - __bfloat162float(h));
        } else {
            out[(size_t)row * DD + c] = v;
        }
    }
}

// ------------------------------------ launch -----------------------------------------
extern "C" void kernel_launch(void* const* d_in, const int* in_sizes, int n_in,
                              void* d_out, int out_size) {
    const float* X0  = (const float*)d_in[0];
    const float* MSK = (const float*)d_in[1];
    const float* PE  = (const float*)d_in[2];
    const float* Wq  = (const float*)d_in[3];
    const float* bq  = (const float*)d_in[4];
    const float* Wk  = (const float*)d_in[5];
    const float* bk  = (const float*)d_in[6];
    const float* Wv  = (const float*)d_in[7];
    const float* bv  = (const float*)d_in[8];
    const float* Wp  = (const float*)d_in[9];
    const float* Ub  = (const float*)d_in[10];
    const float* Vb  = (const float*)d_in[11];
    const float* Wo  = (const float*)d_in[12];
    const float* bo  = (const float*)d_in[13];
    const float* l1a = (const float*)d_in[14];
    const float* l1b = (const float*)d_in[15];
    const float* l2a = (const float*)d_in[16];
    const float* l2b = (const float*)d_in[17];
    const float* W1  = (const float*)d_in[18];
    const float* b1  = (const float*)d_in[19];
    const float* W2  = (const float*)d_in[20];
    const float* b2  = (const float*)d_in[21];
    const float* fna = (const float*)d_in[22];
    const float* fnb = (const float*)d_in[23];
    float* x = (float*)d_out;

    __nv_bfloat16 *ath, *atl, *quh, *qul, *qvh, *qvl, *kkh, *kkl, *pph, *ppl, *vth, *vtl;
    __nv_bfloat16 *xnh, *xnl, *mkh, *mkl, *cxh, *cxl, *hph, *hpl;
    __nv_bfloat16 *wqh, *wql, *wkh, *wkl, *wvh, *wvl, *wph, *wpl, *woh, *wol;
    __nv_bfloat16 *w1h, *w1l, *w2h, *w2l;
    cudaGetSymbolAddress((void**)&ath, g_ath); cudaGetSymbolAddress((void**)&atl, g_atl);
    cudaGetSymbolAddress((void**)&quh, g_quh); cudaGetSymbolAddress((void**)&qul, g_qul);
    cudaGetSymbolAddress((void**)&qvh, g_qvh); cudaGetSymbolAddress((void**)&qvl, g_qvl);
    cudaGetSymbolAddress((void**)&kkh, g_kkh); cudaGetSymbolAddress((void**)&kkl, g_kkl);
    cudaGetSymbolAddress((void**)&pph, g_pph); cudaGetSymbolAddress((void**)&ppl, g_ppl);
    cudaGetSymbolAddress((void**)&vth, g_vth); cudaGetSymbolAddress((void**)&vtl, g_vtl);
    cudaGetSymbolAddress((void**)&xnh, g_xnh); cudaGetSymbolAddress((void**)&xnl, g_xnl);
    cudaGetSymbolAddress((void**)&mkh, g_mkh); cudaGetSymbolAddress((void**)&mkl, g_mkl);
    cudaGetSymbolAddress((void**)&cxh, g_cxh); cudaGetSymbolAddress((void**)&cxl, g_cxl);
    cudaGetSymbolAddress((void**)&hph, g_hph); cudaGetSymbolAddress((void**)&hpl, g_hpl);
    cudaGetSymbolAddress((void**)&wqh, g_wqh); cudaGetSymbolAddress((void**)&wql, g_wql);
    cudaGetSymbolAddress((void**)&wkh, g_wkh); cudaGetSymbolAddress((void**)&wkl, g_wkl);
    cudaGetSymbolAddress((void**)&wvh, g_wvh); cudaGetSymbolAddress((void**)&wvl, g_wvl);
    cudaGetSymbolAddress((void**)&wph, g_wph); cudaGetSymbolAddress((void**)&wpl, g_wpl);
    cudaGetSymbolAddress((void**)&woh, g_woh); cudaGetSymbolAddress((void**)&wol, g_wol);
    cudaGetSymbolAddress((void**)&w1h, g_w1h); cudaGetSymbolAddress((void**)&w1l, g_w1l);
    cudaGetSymbolAddress((void**)&w2h, g_w2h); cudaGetSymbolAddress((void**)&w2l, g_w2l);

    cudaFuncSetAttribute(hmma_gemm<1, true,  false, 0>, cudaFuncAttributeMaxDynamicSharedMemorySize, SMEMSZ);
    cudaFuncSetAttribute(hmma_gemm<3, true,  false, 0>, cudaFuncAttributeMaxDynamicSharedMemorySize, SMEMSZ);
    cudaFuncSetAttribute(hmma_gemm<1, false, true,  1>, cudaFuncAttributeMaxDynamicSharedMemorySize, SMEMSZ);
    cudaFuncSetAttribute(hmma_gemm<1, false, false, 2>, cudaFuncAttributeMaxDynamicSharedMemorySize, SMEMSZ);
    cudaFuncSetAttribute(hmma_gemm<1, false, false, 3>, cudaFuncAttributeMaxDynamicSharedMemorySize, SMEMSZ);
    cudaFuncSetAttribute(hmma_gemm<1, false, false, 4>, cudaFuncAttributeMaxDynamicSharedMemorySize, SMEMSZ);
    cudaFuncSetAttribute(attn_fused, cudaFuncAttributeMaxDynamicSharedMemorySize, FS_TOT);
    cudaFuncSetAttribute(attnv_hmma, cudaFuncAttributeMaxDynamicSharedMemorySize, AV_SMEM);

    int nW = 3 * DD * DD / 4;
    cvt_split<<<(nW + 255) / 256, 256>>>(Wq, wqh, wql, nW);
    cvt_split<<<(nW + 255) / 256, 256>>>(Wk, wkh, wkl, nW);
    cvt_split<<<(nW + 255) / 256, 256>>>(Wv, wvh, wvl, nW);
    cvt_split<<<(nW + 255) / 256, 256>>>(Wp, wph, wpl, nW);
    cvt_split<<<(nW + 255) / 256, 256>>>(Wo, woh, wol, nW);
    int n1 = 3 * DFFX * DD / 4;
    cvt_split<<<(n1 + 255) / 256, 256>>>(W1, w1h, w1l, n1);
    int nM = BT * DD / 4;
    cvt_split<<<(nM + 255) / 256, 256>>>(MSK, mkh, mkl, nM);
    int n2 = 3 * 3 * DD * DFFX;
    cvt_w2<<<(n2 + 255) / 256, 256>>>(W2, w2h, w2l);

    dim3 gP(4, MP / 128);
    dim3 gF(8, MP / 128);
    dim3 gAt(6, ZZ);
    dim3 gAV(1, 3, ZZ);

    for (int i = 0; i < 3; i++) {
        size_t oD = (size_t)i * DD, oDD = (size_t)i * DD * DD;
        addln_kernel<true><<<BT, 128>>>(i == 0 ? X0 : x, x, PE + (size_t)i * TT * DD,
                                        l1a + oD, l1b + oD, nullptr, xnh, xnl);
        hmma_gemm<1, false, false, 2><<<gP, 256, SMEMSZ>>>(
            xnh, xnl, wqh + oDD, wql + oDD, bq + oD, Ub + oD, Vb + oD,
            nullptr, quh, qul, qvh, qvl, BT, DD, DD);
        hmma_gemm<1, false, false, 3><<<gP, 256, SMEMSZ>>>(
            xnh, xnl, wkh + oDD, wkl + oDD, bk + oD, nullptr, nullptr,
            nullptr, kkh, kkl, nullptr, nullptr, BT, DD, DD);
        hmma_gemm<1, false, false, 3><<<gP, 256, SMEMSZ>>>(
            mkh, mkl, wph + oDD, wpl + oDD, nullptr, nullptr, nullptr,
            nullptr, pph, ppl, nullptr, nullptr, BT, DD, DD);
        hmma_gemm<1, false, false, 4><<<gP, 256, SMEMSZ>>>(
            xnh, xnl, wvh + oDD, wvl + oDD, bv + oD, nullptr, nullptr,
            nullptr, vth, vtl, nullptr, nullptr, BT, DD, DD);
        attn_fused<<<gAt, 256, FS_TOT>>>(quh, qul, qvh, qvl, kkh, kkl, pph, ppl, ath, atl);
        attnv_hmma<<<gAV, 256, AV_SMEM>>>(ath, atl, vth, vtl, cxh, cxl);
        hmma_gemm<1, true, false, 0><<<gP, 256, SMEMSZ>>>(
            cxh, cxl, woh + oDD, wol + oDD, bo + oD, nullptr, nullptr,
            x, nullptr, nullptr, nullptr, nullptr, BT, DD, DD);
        addln_kernel<true><<<BT, 128>>>(x, nullptr, nullptr,
                                        l2a + oD, l2b + oD, nullptr, xnh, xnl);
        hmma_gemm<1, false, true, 1><<<gF, 256, SMEMSZ>>>(
            xnh, xnl, w1h + (size_t)i * DFFX * DD, w1l + (size_t)i * DFFX * DD,
            b1 + (size_t)i * DFFX, nullptr, nullptr,
            nullptr, hph, hpl, nullptr, nullptr, BT, DFFX, DD);
        hmma_gemm<3, true, false, 0><<<gP, 256, SMEMSZ>>>(
            hph, hpl, w2h + (size_t)i * 3 * DD * DFFX, w2l + (size_t)i * 3 * DD * DFFX,
            b2 + oD, nullptr, nullptr,
            x, nullptr, nullptr, nullptr, nullptr, BT, DD, DFFX);
    }
    addln_kernel<false><<<BT, 128>>>(x, nullptr, nullptr, fna, fnb, x, nullptr, nullptr);
}

// round 6
// speedup vs baseline: 2.8605x; 1.2300x over previous
#include <cuda_runtime.h>
#include <cuda_fp16.h>
#include <math.h>
#include <stdint.h>

#define BB   64
#define TT   351
#define DD   512
#define HH   8
#define DFFX 1024
#define BT   (BB*TT)       // 22464
#define MP   22528
#define HPR  22784
#define TP   384
#define ZZ   (BB*HH)       // 512
#define STAGE_BYTES 30720  // Ah 10240 + Al 10240 + Bh 10240
#define SMEMSZ (2*STAGE_BYTES)
#define AV_STAGE 25600     // Ah 10240 + Al 10240 + Bh 5120
#define AV_SMEM (2*AV_STAGE)

// fused-attention smem layout (bytes)
#define FS_PITCH 392
#define FS_QU    100352
#define FS_QSZ   11520
#define FS_QUL   (FS_QU + FS_QSZ)
#define FS_QV    (FS_QUL + FS_QSZ)
#define FS_QVL   (FS_QV + FS_QSZ)
#define FS_B     (FS_QVL + FS_QSZ)   // 146432
#define FS_BSZ   18432
#define FS_TOT   (FS_B + FS_BSZ)     // 164864

// ---------------- scratch ------------------------------------------------------------
static __device__ __half g_ath[(size_t)ZZ*TP*TP], g_atl[(size_t)ZZ*TP*TP];
static __device__ __half g_quh[(size_t)ZZ*TP*64], g_qul[(size_t)ZZ*TP*64];
static __device__ __half g_qvh[(size_t)ZZ*TP*64], g_qvl[(size_t)ZZ*TP*64];
static __device__ __half g_kkh[(size_t)ZZ*TP*64];
static __device__ __half g_pph[(size_t)ZZ*TP*64];
static __device__ __half g_vth[(size_t)ZZ*64*TP];
static __device__ __half g_xnh[MP*(size_t)DD], g_xnl[MP*(size_t)DD];
static __device__ __half g_mkh[MP*(size_t)DD], g_mkl[MP*(size_t)DD];
static __device__ __half g_cxh[MP*(size_t)DD], g_cxl[MP*(size_t)DD];
static __device__ __half g_hph[(size_t)HPR*DFFX], g_hpl[(size_t)HPR*DFFX];
static __device__ __half g_wqh[3*DD*DD], g_wkh[3*DD*DD], g_wvh[3*DD*DD];
static __device__ __half g_wph[3*DD*DD], g_woh[3*DD*DD];
static __device__ __half g_w1h[3*DFFX*DD];
static __device__ __half g_w2h[3*3*DD*DFFX];

// ---------------- PTX helpers --------------------------------------------------------
__device__ __forceinline__ uint32_t smem_u32(const void* p) {
    uint32_t a;
    asm("{ .reg .u64 t; cvta.to.shared.u64 t, %1; cvt.u32.u64 %0, t; }" : "=r"(a) : "l"(p));
    return a;
}
__device__ __forceinline__ void cp16(uint32_t dst, const void* src) {
    asm volatile("cp.async.cg.shared.global [%0], [%1], 16;" :: "r"(dst), "l"(src) : "memory");
}
#define CP_COMMIT() asm volatile("cp.async.commit_group;" ::: "memory")
#define CP_WAIT1()  asm volatile("cp.async.wait_group 1;" ::: "memory")
#define CP_WAIT0()  asm volatile("cp.async.wait_group 0;" ::: "memory")

__device__ __forceinline__ void mma16816(float* c, const uint32_t* a, const uint32_t* b) {
    asm volatile(
        "mma.sync.aligned.m16n8k16.row.col.f32.f16.f16.f32 "
        "{%0,%1,%2,%3}, {%4,%5,%6,%7}, {%8,%9}, {%0,%1,%2,%3};"
        : "+f"(c[0]), "+f"(c[1]), "+f"(c[2]), "+f"(c[3])
        : "r"(a[0]), "r"(a[1]), "r"(a[2]), "r"(a[3]), "r"(b[0]), "r"(b[1]));
}
__device__ __forceinline__ void ldsm4(uint32_t* r, uint32_t addr) {
    asm volatile("ldmatrix.sync.aligned.m8n8.x4.shared.b16 {%0,%1,%2,%3}, [%4];"
        : "=r"(r[0]), "=r"(r[1]), "=r"(r[2]), "=r"(r[3]) : "r"(addr));
}
__device__ __forceinline__ uint32_t packh(float a, float b) {
    __half2 h = __floats2half2_rn(a, b);
    return *reinterpret_cast<uint32_t*>(&h);
}
__device__ __forceinline__ uint32_t packl(float a, float b) {
    float ra = a - __half2float(__float2half_rn(a));
    float rb = b - __half2float(__float2half_rn(b));
    return packh(ra, rb);
}

// ---------------- conversion kernels -------------------------------------------------
struct Ptr5 { const float* s0; const float* s1; const float* s2; const float* s3; const float* s4; };
__global__ void cvt5(Ptr5 p, __half* d0, __half* d1, __half* d2, __half* d3, __half* d4, int n4) {
    int i = blockIdx.x * 256 + threadIdx.x;
    if (i >= n4) return;
    const float* s; __half* d;
    switch (blockIdx.y) {
        case 0: s = p.s0; d = d0; break;
        case 1: s = p.s1; d = d1; break;
        case 2: s = p.s2; d = d2; break;
        case 3: s = p.s3; d = d3; break;
        default: s = p.s4; d = d4; break;
    }
    float4 v = ((const float4*)s)[i];
    __half2 a = __floats2half2_rn(v.x, v.y), b = __floats2half2_rn(v.z, v.w);
    uint2 st; st.x = *(uint32_t*)&a; st.y = *(uint32_t*)&b;
    ((uint2*)d)[i] = st;
}
__global__ void cvt_half(const float* __restrict__ in, __half* __restrict__ out, int n4) {
    int i = blockIdx.x * 256 + threadIdx.x;
    if (i >= n4) return;
    float4 v = ((const float4*)in)[i];
    __half2 a = __floats2half2_rn(v.x, v.y), b = __floats2half2_rn(v.z, v.w);
    uint2 st; st.x = *(uint32_t*)&a; st.y = *(uint32_t*)&b;
    ((uint2*)out)[i] = st;
}
__global__ void cvt_split(const float* __restrict__ in, __half* __restrict__ hi,
                          __half* __restrict__ lo, int n4) {
    int i = blockIdx.x * 256 + threadIdx.x;
    if (i >= n4) return;
    float4 v = ((const float4*)in)[i];
    uint2 h, l;
    h.x = packh(v.x, v.y); h.y = packh(v.z, v.w);
    l.x = packl(v.x, v.y); l.y = packl(v.z, v.w);
    ((uint2*)hi)[i] = h;
    ((uint2*)lo)[i] = l;
}
// W2 in: [l][n][k][s] -> out [l][s][n][k] (hi only)
__global__ void cvt_w2(const float* __restrict__ in, __half* __restrict__ hi) {
    int idx = blockIdx.x * 256 + threadIdx.x;
    const int per_l = 3 * DD * DFFX;
    if (idx >= 3 * per_l) return;
    int l = idx / per_l; int r = idx - l * per_l;
    int s = r / (DD * DFFX); int r2 = r - s * (DD * DFFX);
    int n = r2 / DFFX; int k2 = r2 - n * DFFX;
    hi[idx] = __float2half_rn(in[(((size_t)l * DD + n) * DFFX + k2) * 3 + s]);
}

// ---------------- HMMA 2-term fp16 GEMM (ldmatrix) -----------------------------------
// C = [relu](A@B^T + bias)[+C].  A split hi/lo, B hi only.
// MODE 0: fp32 C (+ACC). MODE 1: split-fp16 padded-H (FF1). MODE 2: dual head-major.
// MODE 3: single head-major hi. MODE 4: transposed head-major hi.
template<int TAPS, bool ACC, bool RELU, int MODE>
__global__ __launch_bounds__(256, 2)
void hmma_gemm(const __half* __restrict__ Ahi, const __half* __restrict__ Alo,
               const __half* __restrict__ Bhi,
               const float* __restrict__ bias, const float* __restrict__ bias2,
               const float* __restrict__ bias3,
               float* __restrict__ Cf,
               __half* __restrict__ O1h, __half* __restrict__ O1l,
               __half* __restrict__ O2h, __half* __restrict__ O2l,
               int Mstore, int N, int K) {
    extern __shared__ char sm[];
    uint32_t dbase = smem_u32(sm);
    int tid = threadIdx.x, lane = tid & 31, w = tid >> 5;
    int wm = (w & 1) << 6, wn = (w >> 1) << 5;
    int bm = blockIdx.y << 7, bn = blockIdx.x << 7;

    uint32_t so[2]; long ga[2], gb[2];
#pragma unroll
    for (int j = 0; j < 2; j++) {
        int idx = tid + 256 * j; int row = idx >> 2, c16 = idx & 3;
        so[j] = row * 80 + c16 * 16;
        int grow = bm + row;
        long arow;
        if (TAPS == 3) { int b = grow / 351; int t = grow - b * 351; arow = (long)b * 353 + t; }
        else arow = grow;
        ga[j] = arow * (long)K + c16 * 8;
        gb[j] = (long)(bn + row) * K + c16 * 8;
    }
    const int kch = K >> 5;
    const int nch = TAPS * kch;

#define LOAD_CHUNK(c, stg) do { \
        int s_ = (c) / kch; int kb_ = ((c) - s_ * kch) << 5; \
        long sK_ = (TAPS == 3) ? (long)s_ * K : 0; \
        long sNK_ = (TAPS == 3) ? (long)s_ * N * K : 0; \
        uint32_t sb_ = dbase + (stg) * STAGE_BYTES; \
        _Pragma("unroll") \
        for (int j = 0; j < 2; j++) { \
            cp16(sb_ + so[j],         Ahi + sK_ + ga[j] + kb_); \
            cp16(sb_ + 10240 + so[j], Alo + sK_ + ga[j] + kb_); \
            cp16(sb_ + 20480 + so[j], Bhi + sNK_ + gb[j] + kb_); \
        } \
    } while (0)

    float acc[4][4][4];
#pragma unroll
    for (int a = 0; a < 4; a++)
#pragma unroll
        for (int b = 0; b < 4; b++)
#pragma unroll
            for (int q2 = 0; q2 < 4; q2++) acc[a][b][q2] = 0.0f;

    int bq = lane & 3, bg = lane >> 2;
    uint32_t aoff = (uint32_t)(wm + (lane & 15)) * 80 + (uint32_t)(((lane >> 4) & 1) << 4);
    uint32_t boff = 20480u + (uint32_t)(wn + ((lane >> 4) << 3) + (lane & 7)) * 80
                  + (uint32_t)(((lane >> 3) & 1) << 4);

    LOAD_CHUNK(0, 0);
    CP_COMMIT();
#pragma unroll 1
    for (int c = 0; c < nch; c++) {
        if (c + 1 < nch) LOAD_CHUNK(c + 1, (c + 1) & 1);
        CP_COMMIT();
        CP_WAIT1();
        __syncthreads();
        uint32_t sb = dbase + (c & 1) * STAGE_BYTES;
#pragma unroll
        for (int k16 = 0; k16 < 2; k16++) {
            uint32_t kof = k16 * 32;
            uint32_t bh[4][2], t[4];
            ldsm4(t, sb + boff + kof);
            bh[0][0] = t[0]; bh[0][1] = t[1]; bh[1][0] = t[2]; bh[1][1] = t[3];
            ldsm4(t, sb + boff + 1280 + kof);
            bh[2][0] = t[0]; bh[2][1] = t[1]; bh[3][0] = t[2]; bh[3][1] = t[3];
#pragma unroll
            for (int mi = 0; mi < 4; mi++) {
                uint32_t ah[4], al[4];
                ldsm4(ah, sb + aoff + mi * 1280 + kof);
                ldsm4(al, sb + aoff + mi * 1280 + 10240 + kof);
#pragma unroll
                for (int ni = 0; ni < 4; ni++) {
                    mma16816(acc[mi][ni], ah, bh[ni]);
                    mma16816(acc[mi][ni], al, bh[ni]);
                }
            }
        }
        __syncthreads();
    }
#undef LOAD_CHUNK

#pragma unroll
    for (int mi = 0; mi < 4; mi++) {
#pragma unroll
        for (int half = 0; half < 2; half++) {
            int m = bm + wm + mi * 16 + bg + half * 8;
            if (m >= Mstore) continue;
            int b = 0, t = 0; long crow = m;
            if (MODE == 1) { b = m / 351; t = m - b * 351; crow = (long)b * 353 + 1 + t; }
            if (MODE >= 2) { b = m / 351; t = m - b * 351; }
#pragma unroll
            for (int ni = 0; ni < 4; ni++) {
                int col = bn + wn + ni * 8 + bq * 2;
                float v0 = acc[mi][ni][half * 2 + 0];
                float v1 = acc[mi][ni][half * 2 + 1];
                if (bias) { v0 += bias[col]; v1 += bias[col + 1]; }
                if (RELU) { v0 = fmaxf(v0, 0.0f); v1 = fmaxf(v1, 0.0f); }
                if (MODE == 0) {
                    float* cp = Cf + (long)m * N + col;
                    if (ACC) { v0 += cp[0]; v1 += cp[1]; }
                    float2 st; st.x = v0; st.y = v1;
                    *(float2*)cp = st;
                } else if (MODE == 1) {
                    *(uint32_t*)(O1h + crow * (long)N + col) = packh(v0, v1);
                    *(uint32_t*)(O1l + crow * (long)N + col) = packl(v0, v1);
                } else if (MODE == 2 || MODE == 3) {
                    int h = col >> 6, d = col & 63;
                    long base = ((long)(b * 8 + h) * TP + t) * 64 + d;
                    float u0 = v0, u1 = v1;
                    if (bias2) { u0 += bias2[col]; u1 += bias2[col + 1]; }
                    *(uint32_t*)(O1h + base) = packh(u0, u1);
                    if (MODE == 2) {
                        *(uint32_t*)(O1l + base) = packl(u0, u1);
                        float w0 = v0 + bias3[col], w1 = v1 + bias3[col + 1];
                        *(uint32_t*)(O2h + base) = packh(w0, w1);
                        *(uint32_t*)(O2l + base) = packl(w0, w1);
                    }
                } else { // MODE 4: transposed hi only
                    int h = col >> 6, d = col & 63;
                    O1h[((long)(b * 8 + h) * 64 + d) * TP + t]     = __float2half_rn(v0);
                    O1h[((long)(b * 8 + h) * 64 + d + 1) * TP + t] = __float2half_rn(v1);
                }
            }
        }
    }
}

// ---------------- fused attention ----------------------------------------------------
__global__ __launch_bounds__(256, 1)
void attn_fused(const __half* __restrict__ quh, const __half* __restrict__ qul,
                const __half* __restrict__ qvh, const __half* __restrict__ qvl,
                const __half* __restrict__ kkh, const __half* __restrict__ pph,
                __half* __restrict__ ath, __half* __restrict__ atl) {
    extern __shared__ char sm[];
    uint32_t dbase = smem_u32(sm);
    float* S = (float*)sm;
    int z = blockIdx.y, q0 = blockIdx.x << 6;
    int tid = threadIdx.x, lane = tid & 31, w = tid >> 5;
    int wn = w << 4;
    int bq = lane & 3, bg = lane >> 2;

    for (int i = tid; i < 640; i += 256) {
        int r = i >> 3, c = i & 7;
        int gq = q0 + r; if (gq >= TP) gq = q0;
        long off = ((long)z * TP + gq) * 64 + c * 8;
        uint32_t so = r * 144 + c * 16;
        cp16(dbase + FS_QU  + so, quh + off);
        cp16(dbase + FS_QUL + so, qul + off);
        cp16(dbase + FS_QV  + so, qvh + off);
        cp16(dbase + FS_QVL + so, qvl + off);
    }
    CP_COMMIT();

    // phase 1: content scores
#pragma unroll 1
    for (int c = 0; c < 3; c++) {
        for (int i = tid; i < 1024; i += 256) {
            int r = i >> 3, cc = i & 7;
            long off = ((long)z * TP + c * 128 + r) * 64 + cc * 8;
            cp16(dbase + FS_B + r * 144 + cc * 16, kkh + off);
        }
        CP_COMMIT(); CP_WAIT0(); __syncthreads();
        float acc[4][2][4];
#pragma unroll
        for (int a = 0; a < 4; a++)
#pragma unroll
            for (int b = 0; b < 2; b++)
#pragma unroll
                for (int e = 0; e < 4; e++) acc[a][b][e] = 0.0f;
#pragma unroll
        for (int k16 = 0; k16 < 4; k16++) {
            int kb = k16 * 32 + bq * 4;
            uint32_t bh[2][2];
#pragma unroll
            for (int ni = 0; ni < 2; ni++) {
                const char* pb = sm + FS_B + (wn + ni * 8 + bg) * 144 + kb;
                bh[ni][0] = *(const uint32_t*)pb;
                bh[ni][1] = *(const uint32_t*)(pb + 16);
            }
#pragma unroll
            for (int mi = 0; mi < 4; mi++) {
                const char* pa = sm + FS_QU + (mi * 16 + bg) * 144 + kb;
                uint32_t ah[4], al[4];
                ah[0] = *(const uint32_t*)pa;
                ah[1] = *(const uint32_t*)(pa + 8 * 144);
                ah[2] = *(const uint32_t*)(pa + 16);
                ah[3] = *(const uint32_t*)(pa + 8 * 144 + 16);
                al[0] = *(const uint32_t*)(pa + FS_QSZ);
                al[1] = *(const uint32_t*)(pa + FS_QSZ + 8 * 144);
                al[2] = *(const uint32_t*)(pa + FS_QSZ + 16);
                al[3] = *(const uint32_t*)(pa + FS_QSZ + 8 * 144 + 16);
#pragma unroll
                for (int ni = 0; ni < 2; ni++) {
                    mma16816(acc[mi][ni], ah, bh[ni]);
                    mma16816(acc[mi][ni], al, bh[ni]);
                }
            }
        }
#pragma unroll
        for (int mi = 0; mi < 4; mi++)
#pragma unroll
            for (int half = 0; half < 2; half++) {
                int r = mi * 16 + bg + half * 8;
#pragma unroll
                for (int ni = 0; ni < 2; ni++) {
                    int col = c * 128 + wn + ni * 8 + bq * 2;
                    S[r * FS_PITCH + col]     = acc[mi][ni][half * 2 + 0];
                    S[r * FS_PITCH + col + 1] = acc[mi][ni][half * 2 + 1];
                }
            }
        __syncthreads();
    }

    // phase 2: pos scores + rel-shift scatter
#pragma unroll 1
    for (int c = 0; c < 3; c++) {
        for (int i = tid; i < 1024; i += 256) {
            int r = i >> 3, cc = i & 7;
            long off = ((long)z * TP + c * 128 + r) * 64 + cc * 8;
            cp16(dbase + FS_B + r * 144 + cc * 16, pph + off);
        }
        CP_COMMIT(); CP_WAIT0(); __syncthreads();
        float acc[5][2][4];
#pragma unroll
        for (int a = 0; a < 5; a++)
#pragma unroll
            for (int b = 0; b < 2; b++)
#pragma unroll
                for (int e = 0; e < 4; e++) acc[a][b][e] = 0.0f;
#pragma unroll
        for (int k16 = 0; k16 < 4; k16++) {
            int kb = k16 * 32 + bq * 4;
            uint32_t bh[2][2];
#pragma unroll
            for (int ni = 0; ni < 2; ni++) {
                const char* pb = sm + FS_B + (wn + ni * 8 + bg) * 144 + kb;
                bh[ni][0] = *(const uint32_t*)pb;
                bh[ni][1] = *(const uint32_t*)(pb + 16);
            }
#pragma unroll
            for (int mi = 0; mi < 5; mi++) {
                const char* pa = sm + FS_QV + (mi * 16 + bg) * 144 + kb;
                uint32_t ah[4], al[4];
                ah[0] = *(const uint32_t*)pa;
                ah[1] = *(const uint32_t*)(pa + 8 * 144);
                ah[2] = *(const uint32_t*)(pa + 16);
                ah[3] = *(const uint32_t*)(pa + 8 * 144 + 16);
                al[0] = *(const uint32_t*)(pa + FS_QSZ);
                al[1] = *(const uint32_t*)(pa + FS_QSZ + 8 * 144);
                al[2] = *(const uint32_t*)(pa + FS_QSZ + 16);
                al[3] = *(const uint32_t*)(pa + FS_QSZ + 8 * 144 + 16);
#pragma unroll
                for (int ni = 0; ni < 2; ni++) {
                    mma16816(acc[mi][ni], ah, bh[ni]);
                    mma16816(acc[mi][ni], al, bh[ni]);
                }
            }
        }
#pragma unroll
        for (int mi = 0; mi < 5; mi++)
#pragma unroll
            for (int half = 0; half < 2; half++) {
                int r = mi * 16 + bg + half * 8;
                if (r > 64) continue;
                int rp = q0 + r;
#pragma unroll
                for (int ni = 0; ni < 2; ni++)
#pragma unroll
                    for (int e = 0; e < 2; e++) {
                        int jj = c * 128 + wn + ni * 8 + bq * 2 + e;
                        if (jj >= TT) continue;
                        float v = acc[mi][ni][half * 2 + e];
                        if (jj >= 350 - rp) {
                            if (r < 64) atomicAdd(&S[r * FS_PITCH + jj - 350 + rp], v);
                        } else if (r >= 1) {
                            atomicAdd(&S[(r - 1) * FS_PITCH + jj + rp + 1], v);
                        }
                    }
            }
        __syncthreads();
    }

    // softmax + split-fp16 store
    {
        int r = tid >> 2, qu = tid & 3;
        int gq = q0 + r;
        long rowbase = ((long)z * TP + gq) * TP;
        const float scale = 0.044194173824159216f;
        float* Srow = S + r * FS_PITCH;
        int c0 = qu * 96;
        if (gq >= TT) {
            for (int cc = c0; cc < c0 + 96; cc += 2) {
                *(uint32_t*)(ath + rowbase + cc) = 0u;
                *(uint32_t*)(atl + rowbase + cc) = 0u;
            }
        } else {
            float mx = -1e30f;
            for (int cc = c0; cc < c0 + 96; cc++)
                if (cc < TT) mx = fmaxf(mx, Srow[cc]);
            mx = fmaxf(mx, __shfl_xor_sync(0xffffffffu, mx, 1));
            mx = fmaxf(mx, __shfl_xor_sync(0xffffffffu, mx, 2));
            float mxs = mx * scale;
            float sum = 0.0f;
            for (int cc = c0; cc < c0 + 96; cc++)
                if (cc < TT) {
                    float e = __expf(Srow[cc] * scale - mxs);
                    Srow[cc] = e;
                    sum += e;
                }
            sum += __shfl_xor_sync(0xffffffffu, sum, 1);
            sum += __shfl_xor_sync(0xffffffffu, sum, 2);
            float inv = 1.0f / sum;
            for (int cc = c0; cc < c0 + 96; cc += 2) {
                float v0 = (cc < TT)     ? Srow[cc] * inv     : 0.0f;
                float v1 = (cc + 1 < TT) ? Srow[cc + 1] * inv : 0.0f;
                *(uint32_t*)(ath + rowbase + cc) = packh(v0, v1);
                *(uint32_t*)(atl + rowbase + cc) = packl(v0, v1);
            }
        }
    }
}

// ---------------- batched attn·V -----------------------------------------------------
__global__ __launch_bounds__(256, 2)
void attnv_hmma(const __half* __restrict__ Ahg, const __half* __restrict__ Alg,
                const __half* __restrict__ Bhg,
                __half* __restrict__ Ch, __half* __restrict__ Cl) {
    extern __shared__ char sm[];
    uint32_t dbase = smem_u32(sm);
    int tid = threadIdx.x, lane = tid & 31, w = tid >> 5;
    int wm = (w & 3) << 5, wn = (w >> 2) << 5;
    int z = blockIdx.z, q0 = blockIdx.y << 7;
    const __half* Ah = Ahg + (long)z * TP * TP;
    const __half* Al = Alg + (long)z * TP * TP;
    const __half* Bh = Bhg + (long)z * 64 * TP;

    uint32_t soA[2]; long gaA[2];
#pragma unroll
    for (int j = 0; j < 2; j++) {
        int idx = tid + 256 * j; int row = idx >> 2, c16 = idx & 3;
        soA[j] = row * 80 + c16 * 16;
        gaA[j] = (long)(q0 + row) * TP + c16 * 8;
    }
    uint32_t soB = (tid >> 2) * 80 + (tid & 3) * 16;
    long gB = (long)(tid >> 2) * TP + (tid & 3) * 8;

#define AV_LOAD(c, stg) do { \
        int kb_ = (c) << 5; \
        uint32_t sb_ = dbase + (stg) * AV_STAGE; \
        _Pragma("unroll") \
        for (int j = 0; j < 2; j++) { \
            cp16(sb_ + soA[j],         Ah + gaA[j] + kb_); \
            cp16(sb_ + 10240 + soA[j], Al + gaA[j] + kb_); \
        } \
        cp16(sb_ + 20480 + soB, Bh + gB + kb_); \
    } while (0)

    float acc[2][4][4];
#pragma unroll
    for (int a = 0; a < 2; a++)
#pragma unroll
        for (int b = 0; b < 4; b++)
#pragma unroll
            for (int q2 = 0; q2 < 4; q2++) acc[a][b][q2] = 0.0f;
    int bq = lane & 3, bg = lane >> 2;
    uint32_t aoff = (uint32_t)(wm + (lane & 15)) * 80 + (uint32_t)(((lane >> 4) & 1) << 4);
    uint32_t boff = 20480u + (uint32_t)(wn + ((lane >> 4) << 3) + (lane & 7)) * 80
                  + (uint32_t)(((lane >> 3) & 1) << 4);

    AV_LOAD(0, 0);
    CP_COMMIT();
#pragma unroll 1
    for (int c = 0; c < 12; c++) {
        if (c + 1 < 12) AV_LOAD(c + 1, (c + 1) & 1);
        CP_COMMIT();
        CP_WAIT1();
        __syncthreads();
        uint32_t sb = dbase + (c & 1) * AV_STAGE;
#pragma unroll
        for (int k16 = 0; k16 < 2; k16++) {
            uint32_t kof = k16 * 32;
            uint32_t bh[4][2], t[4];
            ldsm4(t, sb + boff + kof);
            bh[0][0] = t[0]; bh[0][1] = t[1]; bh[1][0] = t[2]; bh[1][1] = t[3];
            ldsm4(t, sb + boff + 1280 + kof);
            bh[2][0] = t[0]; bh[2][1] = t[1]; bh[3][0] = t[2]; bh[3][1] = t[3];
#pragma unroll
            for (int mi = 0; mi < 2; mi++) {
                uint32_t ah[4], al[4];
                ldsm4(ah, sb + aoff + mi * 1280 + kof);
                ldsm4(al, sb + aoff + mi * 1280 + 10240 + kof);
#pragma unroll
                for (int ni = 0; ni < 4; ni++) {
                    mma16816(acc[mi][ni], ah, bh[ni]);
                    mma16816(acc[mi][ni], al, bh[ni]);
                }
            }
        }
        __syncthreads();
    }
#undef AV_LOAD

    int b = z >> 3, h = z & 7;
#pragma unroll
    for (int mi = 0; mi < 2; mi++) {
#pragma unroll
        for (int half = 0; half < 2; half++) {
            int q = q0 + wm + mi * 16 + bg + half * 8;
            if (q >= TT) continue;
#pragma unroll
            for (int ni = 0; ni < 4; ni++) {
                int col = wn + ni * 8 + bq * 2;
                float v0 = acc[mi][ni][half * 2 + 0];
                float v1 = acc[mi][ni][half * 2 + 1];
                long addr = ((long)(b * 351 + q)) * DD + h * 64 + col;
                *(uint32_t*)(Ch + addr) = packh(v0, v1);
                *(uint32_t*)(Cl + addr) = packl(v0, v1);
            }
        }
    }
}

// ---------------- add pos-emb + LayerNorm --------------------------------------------
template<bool F16O>
__global__ void addln_kernel(const float* __restrict__ xin, float* __restrict__ xupd,
                             const float* __restrict__ pe,
                             const float* __restrict__ ga, const float* __restrict__ gb,
                             float* __restrict__ out, __half* __restrict__ ohi,
                             __half* __restrict__ olo) {
    int row = blockIdx.x;
    int t   = row % TT;
    const float* xr = xin + (size_t)row * DD;
    int tid = threadIdx.x;
    float vals[4];
#pragma unroll
    for (int i = 0; i < 4; i++) {
        int c = tid + i * 128;
        float vv = xr[c];
        if (pe) vv += pe[(size_t)t * DD + c];
        vals[i] = vv;
    }
    if (pe) {
        float* xw = xupd + (size_t)row * DD;
#pragma unroll
        for (int i = 0; i < 4; i++) xw[tid + i * 128] = vals[i];
    }
    __shared__ float sh[4];
    float s = vals[0] + vals[1] + vals[2] + vals[3];
#pragma unroll
    for (int o = 16; o > 0; o >>= 1) s += __shfl_xor_sync(0xffffffffu, s, o);
    if ((tid & 31) == 0) sh[tid >> 5] = s;
    __syncthreads();
    float mean = (sh[0] + sh[1] + sh[2] + sh[3]) * (1.0f / DD);
    __syncthreads();
    float sq = 0.0f;
#pragma unroll
    for (int i = 0; i < 4; i++) { float d = vals[i] - mean; sq += d * d; }
#pragma unroll
    for (int o = 16; o > 0; o >>= 1) sq += __shfl_xor_sync(0xffffffffu, sq, o);
    if ((tid & 31) == 0) sh[tid >> 5] = sq;
    __syncthreads();
    float var  = sh[0] + sh[1] + sh[2] + sh[3];
    float stdv = sqrtf(var * (1.0f / (DD - 1)));
    float inv  = 1.0f / (stdv + 1e-6f);
#pragma unroll
    for (int i = 0; i < 4; i++) {
        int c = tid + i * 128;
        float v = ga[c] * (vals[i] - mean) * inv + gb[c];
        if (F16O) {
            __half h = __float2half_rn(v);
            ohi[(size_t)row * DD + c] = h;
            olo[(size_t)row * DD + c] = __float2half_rn(v - __half2float(h));
        } else {
            out[(size_t)row * DD + c] = v;
        }
    }
}

// ------------------------------------ launch -----------------------------------------
extern "C" void kernel_launch(void* const* d_in, const int* in_sizes, int n_in,
                              void* d_out, int out_size) {
    const float* X0  = (const float*)d_in[0];
    const float* MSK = (const float*)d_in[1];
    const float* PE  = (const float*)d_in[2];
    const float* Wq  = (const float*)d_in[3];
    const float* bq  = (const float*)d_in[4];
    const float* Wk  = (const float*)d_in[5];
    const float* bk  = (const float*)d_in[6];
    const float* Wv  = (const float*)d_in[7];
    const float* bv  = (const float*)d_in[8];
    const float* Wp  = (const float*)d_in[9];
    const float* Ub  = (const float*)d_in[10];
    const float* Vb  = (const float*)d_in[11];
    const float* Wo  = (const float*)d_in[12];
    const float* bo  = (const float*)d_in[13];
    const float* l1a = (const float*)d_in[14];
    const float* l1b = (const float*)d_in[15];
    const float* l2a = (const float*)d_in[16];
    const float* l2b = (const float*)d_in[17];
    const float* W1  = (const float*)d_in[18];
    const float* b1  = (const float*)d_in[19];
    const float* W2  = (const float*)d_in[20];
    const float* b2  = (const float*)d_in[21];
    const float* fna = (const float*)d_in[22];
    const float* fnb = (const float*)d_in[23];
    float* x = (float*)d_out;

    __half *ath, *atl, *quh, *qul, *qvh, *qvl, *kkh, *pph, *vth;
    __half *xnh, *xnl, *mkh, *mkl, *cxh, *cxl, *hph, *hpl;
    __half *wqh, *wkh, *wvh, *wph, *woh, *w1h, *w2h;
    cudaGetSymbolAddress((void**)&ath, g_ath); cudaGetSymbolAddress((void**)&atl, g_atl);
    cudaGetSymbolAddress((void**)&quh, g_quh); cudaGetSymbolAddress((void**)&qul, g_qul);
    cudaGetSymbolAddress((void**)&qvh, g_qvh); cudaGetSymbolAddress((void**)&qvl, g_qvl);
    cudaGetSymbolAddress((void**)&kkh, g_kkh); cudaGetSymbolAddress((void**)&pph, g_pph);
    cudaGetSymbolAddress((void**)&vth, g_vth);
    cudaGetSymbolAddress((void**)&xnh, g_xnh); cudaGetSymbolAddress((void**)&xnl, g_xnl);
    cudaGetSymbolAddress((void**)&mkh, g_mkh); cudaGetSymbolAddress((void**)&mkl, g_mkl);
    cudaGetSymbolAddress((void**)&cxh, g_cxh); cudaGetSymbolAddress((void**)&cxl, g_cxl);
    cudaGetSymbolAddress((void**)&hph, g_hph); cudaGetSymbolAddress((void**)&hpl, g_hpl);
    cudaGetSymbolAddress((void**)&wqh, g_wqh); cudaGetSymbolAddress((void**)&wkh, g_wkh);
    cudaGetSymbolAddress((void**)&wvh, g_wvh); cudaGetSymbolAddress((void**)&wph, g_wph);
    cudaGetSymbolAddress((void**)&woh, g_woh);
    cudaGetSymbolAddress((void**)&w1h, g_w1h); cudaGetSymbolAddress((void**)&w2h, g_w2h);

    cudaFuncSetAttribute(hmma_gemm<1, true,  false, 0>, cudaFuncAttributeMaxDynamicSharedMemorySize, SMEMSZ);
    cudaFuncSetAttribute(hmma_gemm<3, true,  false, 0>, cudaFuncAttributeMaxDynamicSharedMemorySize, SMEMSZ);
    cudaFuncSetAttribute(hmma_gemm<1, false, true,  1>, cudaFuncAttributeMaxDynamicSharedMemorySize, SMEMSZ);
    cudaFuncSetAttribute(hmma_gemm<1, false, false, 2>, cudaFuncAttributeMaxDynamicSharedMemorySize, SMEMSZ);
    cudaFuncSetAttribute(hmma_gemm<1, false, false, 3>, cudaFuncAttributeMaxDynamicSharedMemorySize, SMEMSZ);
    cudaFuncSetAttribute(hmma_gemm<1, false, false, 4>, cudaFuncAttributeMaxDynamicSharedMemorySize, SMEMSZ);
    cudaFuncSetAttribute(attn_fused, cudaFuncAttributeMaxDynamicSharedMemorySize, FS_TOT);
    cudaFuncSetAttribute(attnv_hmma, cudaFuncAttributeMaxDynamicSharedMemorySize, AV_SMEM);

    // conversions (4 launches so ncu -s 5 lands on the first real GEMM)
    int nW = 3 * DD * DD / 4;
    Ptr5 p5; p5.s0 = Wq; p5.s1 = Wk; p5.s2 = Wv; p5.s3 = Wp; p5.s4 = Wo;
    cvt5<<<dim3((nW + 255) / 256, 5), 256>>>(p5, wqh, wkh, wvh, wph, woh, nW);
    int n1 = 3 * DFFX * DD / 4;
    cvt_half<<<(n1 + 255) / 256, 256>>>(W1, w1h, n1);
    int nM = BT * DD / 4;
    cvt_split<<<(nM + 255) / 256, 256>>>(MSK, mkh, mkl, nM);
    int n2 = 3 * 3 * DD * DFFX;
    cvt_w2<<<(n2 + 255) / 256, 256>>>(W2, w2h);

    dim3 gP(4, MP / 128);
    dim3 gF(8, MP / 128);
    dim3 gAt(6, ZZ);
    dim3 gAV(1, 3, ZZ);

    for (int i = 0; i < 3; i++) {
        size_t oD = (size_t)i * DD, oDD = (size_t)i * DD * DD;
        addln_kernel<true><<<BT, 128>>>(i == 0 ? X0 : x, x, PE + (size_t)i * TT * DD,
                                        l1a + oD, l1b + oD, nullptr, xnh, xnl);
        hmma_gemm<1, false, false, 2><<<gP, 256, SMEMSZ>>>(
            xnh, xnl, wqh + oDD, bq + oD, Ub + oD, Vb + oD,
            nullptr, quh, qul, qvh, qvl, BT, DD, DD);
        hmma_gemm<1, false, false, 3><<<gP, 256, SMEMSZ>>>(
            xnh, xnl, wkh + oDD, bk + oD, nullptr, nullptr,
            nullptr, kkh, nullptr, nullptr, nullptr, BT, DD, DD);
        hmma_gemm<1, false, false, 3><<<gP, 256, SMEMSZ>>>(
            mkh, mkl, wph + oDD, nullptr, nullptr, nullptr,
            nullptr, pph, nullptr, nullptr, nullptr, BT, DD, DD);
        hmma_gemm<1, false, false, 4><<<gP, 256, SMEMSZ>>>(
            xnh, xnl, wvh + oDD, bv + oD, nullptr, nullptr,
            nullptr, vth, nullptr, nullptr, nullptr, BT, DD, DD);
        attn_fused<<<gAt, 256, FS_TOT>>>(quh, qul, qvh, qvl, kkh, pph, ath, atl);
        attnv_hmma<<<gAV, 256, AV_SMEM>>>(ath, atl, vth, cxh, cxl);
        hmma_gemm<1, true, false, 0><<<gP, 256, SMEMSZ>>>(
            cxh, cxl, woh + oDD, bo + oD, nullptr, nullptr,
            x, nullptr, nullptr, nullptr, nullptr, BT, DD, DD);
        addln_kernel<true><<<BT, 128>>>(x, nullptr, nullptr,
                                        l2a + oD, l2b + oD, nullptr, xnh, xnl);
        hmma_gemm<1, false, true, 1><<<gF, 256, SMEMSZ>>>(
            xnh, xnl, w1h + (size_t)i * DFFX * DD,
            b1 + (size_t)i * DFFX, nullptr, nullptr,
            nullptr, hph, hpl, nullptr, nullptr, BT, DFFX, DD);
        hmma_gemm<3, true, false, 0><<<gP, 256, SMEMSZ>>>(
            hph, hpl, w2h + (size_t)i * 3 * DD * DFFX,
            b2 + oD, nullptr, nullptr,
            x, nullptr, nullptr, nullptr, nullptr, BT, DD, DFFX);
    }
    addln_kernel<false><<<BT, 128>>>(x, nullptr, nullptr, fna, fnb, x, nullptr, nullptr);
}

// round 7
// speedup vs baseline: 3.1587x; 1.1042x over previous
#include <cuda_runtime.h>
#include <cuda_fp16.h>
#include <math.h>
#include <stdint.h>

#define BB   64
#define TT   351
#define DD   512
#define HH   8
#define DFFX 1024
#define BT   (BB*TT)       // 22464
#define MP   22528
#define HPR  22784
#define TP   384
#define ZZ   (BB*HH)       // 512
#define STAGE_BYTES 30720  // Ah 10240 + Al 10240 + Bh 10240
#define SMEMSZ (2*STAGE_BYTES)
#define AV_STAGE 25600     // Ah 10240 + Al 10240 + Bh 5120
#define AV_SMEM (2*AV_STAGE)

// fused-attention smem layout (bytes), q-block = 48 rows
#define FS_PITCH 392
#define FS_Q     75264               // 48*392*4 score bytes before this
#define FS_QSZ   9216                // 64 rows * 144B
#define FS_QL    (FS_Q + FS_QSZ)     // 84480
#define FS_B     93696
#define FS_BSZ   18432               // 128 rows * 144B
#define FS_TOT   112128              // fits 2 blocks/SM (224.3KB < 228KB)

// ---------------- scratch ------------------------------------------------------------
static __device__ __half g_ath[(size_t)ZZ*TP*TP], g_atl[(size_t)ZZ*TP*TP];
static __device__ __half g_quh[(size_t)ZZ*TP*64], g_qul[(size_t)ZZ*TP*64];
static __device__ __half g_qvh[(size_t)ZZ*TP*64], g_qvl[(size_t)ZZ*TP*64];
static __device__ __half g_kkh[(size_t)ZZ*TP*64];
static __device__ __half g_pph[(size_t)ZZ*TP*64];
static __device__ __half g_vth[(size_t)ZZ*64*TP];
static __device__ __half g_xnh[MP*(size_t)DD], g_xnl[MP*(size_t)DD];
static __device__ __half g_mkh[MP*(size_t)DD], g_mkl[MP*(size_t)DD];
static __device__ __half g_cxh[MP*(size_t)DD], g_cxl[MP*(size_t)DD];
static __device__ __half g_hph[(size_t)HPR*DFFX], g_hpl[(size_t)HPR*DFFX];
static __device__ __half g_wqh[3*DD*DD], g_wkh[3*DD*DD], g_wvh[3*DD*DD];
static __device__ __half g_wph[3*DD*DD], g_woh[3*DD*DD];
static __device__ __half g_w1h[3*DFFX*DD];
static __device__ __half g_w2h[3*3*DD*DFFX];

// ---------------- PTX helpers --------------------------------------------------------
__device__ __forceinline__ uint32_t smem_u32(const void* p) {
    uint32_t a;
    asm("{ .reg .u64 t; cvta.to.shared.u64 t, %1; cvt.u32.u64 %0, t; }" : "=r"(a) : "l"(p));
    return a;
}
__device__ __forceinline__ void cp16(uint32_t dst, const void* src) {
    asm volatile("cp.async.cg.shared.global [%0], [%1], 16;" :: "r"(dst), "l"(src) : "memory");
}
#define CP_COMMIT() asm volatile("cp.async.commit_group;" ::: "memory")
#define CP_WAIT1()  asm volatile("cp.async.wait_group 1;" ::: "memory")
#define CP_WAIT0()  asm volatile("cp.async.wait_group 0;" ::: "memory")

__device__ __forceinline__ void mma16816(float* c, const uint32_t* a, const uint32_t* b) {
    asm volatile(
        "mma.sync.aligned.m16n8k16.row.col.f32.f16.f16.f32 "
        "{%0,%1,%2,%3}, {%4,%5,%6,%7}, {%8,%9}, {%0,%1,%2,%3};"
        : "+f"(c[0]), "+f"(c[1]), "+f"(c[2]), "+f"(c[3])
        : "r"(a[0]), "r"(a[1]), "r"(a[2]), "r"(a[3]), "r"(b[0]), "r"(b[1]));
}
__device__ __forceinline__ void ldsm4(uint32_t* r, uint32_t addr) {
    asm volatile("ldmatrix.sync.aligned.m8n8.x4.shared.b16 {%0,%1,%2,%3}, [%4];"
        : "=r"(r[0]), "=r"(r[1]), "=r"(r[2]), "=r"(r[3]) : "r"(addr));
}
__device__ __forceinline__ uint32_t packh(float a, float b) {
    __half2 h = __floats2half2_rn(a, b);
    return *reinterpret_cast<uint32_t*>(&h);
}
__device__ __forceinline__ uint32_t packl(float a, float b) {
    float ra = a - __half2float(__float2half_rn(a));
    float rb = b - __half2float(__float2half_rn(b));
    return packh(ra, rb);
}

// ---------------- conversion kernels -------------------------------------------------
struct Ptr5 { const float* s0; const float* s1; const float* s2; const float* s3; const float* s4; };
__global__ void cvt5(Ptr5 p, __half* d0, __half* d1, __half* d2, __half* d3, __half* d4, int n4) {
    int i = blockIdx.x * 256 + threadIdx.x;
    if (i >= n4) return;
    const float* s; __half* d;
    switch (blockIdx.y) {
        case 0: s = p.s0; d = d0; break;
        case 1: s = p.s1; d = d1; break;
        case 2: s = p.s2; d = d2; break;
        case 3: s = p.s3; d = d3; break;
        default: s = p.s4; d = d4; break;
    }
    float4 v = ((const float4*)s)[i];
    __half2 a = __floats2half2_rn(v.x, v.y), b = __floats2half2_rn(v.z, v.w);
    uint2 st; st.x = *(uint32_t*)&a; st.y = *(uint32_t*)&b;
    ((uint2*)d)[i] = st;
}
__global__ void cvt_half(const float* __restrict__ in, __half* __restrict__ out, int n4) {
    int i = blockIdx.x * 256 + threadIdx.x;
    if (i >= n4) return;
    float4 v = ((const float4*)in)[i];
    __half2 a = __floats2half2_rn(v.x, v.y), b = __floats2half2_rn(v.z, v.w);
    uint2 st; st.x = *(uint32_t*)&a; st.y = *(uint32_t*)&b;
    ((uint2*)out)[i] = st;
}
__global__ void cvt_split(const float* __restrict__ in, __half* __restrict__ hi,
                          __half* __restrict__ lo, int n4) {
    int i = blockIdx.x * 256 + threadIdx.x;
    if (i >= n4) return;
    float4 v = ((const float4*)in)[i];
    uint2 h, l;
    h.x = packh(v.x, v.y); h.y = packh(v.z, v.w);
    l.x = packl(v.x, v.y); l.y = packl(v.z, v.w);
    ((uint2*)hi)[i] = h;
    ((uint2*)lo)[i] = l;
}
// W2 in: [l][n][k][s] -> out [l][s][n][k] (hi only)
__global__ void cvt_w2(const float* __restrict__ in, __half* __restrict__ hi) {
    int idx = blockIdx.x * 256 + threadIdx.x;
    const int per_l = 3 * DD * DFFX;
    if (idx >= 3 * per_l) return;
    int l = idx / per_l; int r = idx - l * per_l;
    int s = r / (DD * DFFX); int r2 = r - s * (DD * DFFX);
    int n = r2 / DFFX; int k2 = r2 - n * DFFX;
    hi[idx] = __float2half_rn(in[(((size_t)l * DD + n) * DFFX + k2) * 3 + s]);
}

// ---------------- HMMA 2-term fp16 GEMM (ldmatrix) -----------------------------------
template<int TAPS, bool ACC, bool RELU, int MODE>
__global__ __launch_bounds__(256, 2)
void hmma_gemm(const __half* __restrict__ Ahi, const __half* __restrict__ Alo,
               const __half* __restrict__ Bhi,
               const float* __restrict__ bias, const float* __restrict__ bias2,
               const float* __restrict__ bias3,
               float* __restrict__ Cf,
               __half* __restrict__ O1h, __half* __restrict__ O1l,
               __half* __restrict__ O2h, __half* __restrict__ O2l,
               int Mstore, int N, int K) {
    extern __shared__ char sm[];
    uint32_t dbase = smem_u32(sm);
    int tid = threadIdx.x, lane = tid & 31, w = tid >> 5;
    int wm = (w & 1) << 6, wn = (w >> 1) << 5;
    int bm = blockIdx.y << 7, bn = blockIdx.x << 7;

    uint32_t so[2]; long ga[2], gb[2];
#pragma unroll
    for (int j = 0; j < 2; j++) {
        int idx = tid + 256 * j; int row = idx >> 2, c16 = idx & 3;
        so[j] = row * 80 + c16 * 16;
        int grow = bm + row;
        long arow;
        if (TAPS == 3) { int b = grow / 351; int t = grow - b * 351; arow = (long)b * 353 + t; }
        else arow = grow;
        ga[j] = arow * (long)K + c16 * 8;
        gb[j] = (long)(bn + row) * K + c16 * 8;
    }
    const int kch = K >> 5;
    const int nch = TAPS * kch;

#define LOAD_CHUNK(c, stg) do { \
        int s_ = (c) / kch; int kb_ = ((c) - s_ * kch) << 5; \
        long sK_ = (TAPS == 3) ? (long)s_ * K : 0; \
        long sNK_ = (TAPS == 3) ? (long)s_ * N * K : 0; \
        uint32_t sb_ = dbase + (stg) * STAGE_BYTES; \
        _Pragma("unroll") \
        for (int j = 0; j < 2; j++) { \
            cp16(sb_ + so[j],         Ahi + sK_ + ga[j] + kb_); \
            cp16(sb_ + 10240 + so[j], Alo + sK_ + ga[j] + kb_); \
            cp16(sb_ + 20480 + so[j], Bhi + sNK_ + gb[j] + kb_); \
        } \
    } while (0)

    float acc[4][4][4];
#pragma unroll
    for (int a = 0; a < 4; a++)
#pragma unroll
        for (int b = 0; b < 4; b++)
#pragma unroll
            for (int q2 = 0; q2 < 4; q2++) acc[a][b][q2] = 0.0f;

    int bq = lane & 3, bg = lane >> 2;
    uint32_t aoff = (uint32_t)(wm + (lane & 15)) * 80 + (uint32_t)(((lane >> 4) & 1) << 4);
    uint32_t boff = 20480u + (uint32_t)(wn + ((lane >> 4) << 3) + (lane & 7)) * 80
                  + (uint32_t)(((lane >> 3) & 1) << 4);

    LOAD_CHUNK(0, 0);
    CP_COMMIT();
#pragma unroll 1
    for (int c = 0; c < nch; c++) {
        if (c + 1 < nch) LOAD_CHUNK(c + 1, (c + 1) & 1);
        CP_COMMIT();
        CP_WAIT1();
        __syncthreads();
        uint32_t sb = dbase + (c & 1) * STAGE_BYTES;
#pragma unroll
        for (int k16 = 0; k16 < 2; k16++) {
            uint32_t kof = k16 * 32;
            uint32_t bh[4][2], t[4];
            ldsm4(t, sb + boff + kof);
            bh[0][0] = t[0]; bh[0][1] = t[1]; bh[1][0] = t[2]; bh[1][1] = t[3];
            ldsm4(t, sb + boff + 1280 + kof);
            bh[2][0] = t[0]; bh[2][1] = t[1]; bh[3][0] = t[2]; bh[3][1] = t[3];
#pragma unroll
            for (int mi = 0; mi < 4; mi++) {
                uint32_t ah[4], al[4];
                ldsm4(ah, sb + aoff + mi * 1280 + kof);
                ldsm4(al, sb + aoff + mi * 1280 + 10240 + kof);
#pragma unroll
                for (int ni = 0; ni < 4; ni++) {
                    mma16816(acc[mi][ni], ah, bh[ni]);
                    mma16816(acc[mi][ni], al, bh[ni]);
                }
            }
        }
        __syncthreads();
    }
#undef LOAD_CHUNK

#pragma unroll
    for (int mi = 0; mi < 4; mi++) {
#pragma unroll
        for (int half = 0; half < 2; half++) {
            int m = bm + wm + mi * 16 + bg + half * 8;
            if (m >= Mstore) continue;
            int b = 0, t = 0; long crow = m;
            if (MODE == 1) { b = m / 351; t = m - b * 351; crow = (long)b * 353 + 1 + t; }
            if (MODE >= 2) { b = m / 351; t = m - b * 351; }
#pragma unroll
            for (int ni = 0; ni < 4; ni++) {
                int col = bn + wn + ni * 8 + bq * 2;
                float v0 = acc[mi][ni][half * 2 + 0];
                float v1 = acc[mi][ni][half * 2 + 1];
                if (bias) { v0 += bias[col]; v1 += bias[col + 1]; }
                if (RELU) { v0 = fmaxf(v0, 0.0f); v1 = fmaxf(v1, 0.0f); }
                if (MODE == 0) {
                    float* cp = Cf + (long)m * N + col;
                    if (ACC) { v0 += cp[0]; v1 += cp[1]; }
                    float2 st; st.x = v0; st.y = v1;
                    *(float2*)cp = st;
                } else if (MODE == 1) {
                    *(uint32_t*)(O1h + crow * (long)N + col) = packh(v0, v1);
                    *(uint32_t*)(O1l + crow * (long)N + col) = packl(v0, v1);
                } else if (MODE == 2 || MODE == 3) {
                    int h = col >> 6, d = col & 63;
                    long base = ((long)(b * 8 + h) * TP + t) * 64 + d;
                    float u0 = v0, u1 = v1;
                    if (bias2) { u0 += bias2[col]; u1 += bias2[col + 1]; }
                    *(uint32_t*)(O1h + base) = packh(u0, u1);
                    if (MODE == 2) {
                        *(uint32_t*)(O1l + base) = packl(u0, u1);
                        float w0 = v0 + bias3[col], w1 = v1 + bias3[col + 1];
                        *(uint32_t*)(O2h + base) = packh(w0, w1);
                        *(uint32_t*)(O2l + base) = packl(w0, w1);
                    }
                } else { // MODE 4: transposed hi only
                    int h = col >> 6, d = col & 63;
                    O1h[((long)(b * 8 + h) * 64 + d) * TP + t]     = __float2half_rn(v0);
                    O1h[((long)(b * 8 + h) * 64 + d + 1) * TP + t] = __float2half_rn(v1);
                }
            }
        }
    }
}

// ---------------- fused attention (q-block 48, occ 2, no atomics) --------------------
__global__ __launch_bounds__(256, 2)
void attn_fused(const __half* __restrict__ quh, const __half* __restrict__ qul,
                const __half* __restrict__ qvh, const __half* __restrict__ qvl,
                const __half* __restrict__ kkh, const __half* __restrict__ pph,
                __half* __restrict__ ath, __half* __restrict__ atl) {
    extern __shared__ char sm[];
    uint32_t dbase = smem_u32(sm);
    float* S = (float*)sm;
    int z = blockIdx.y, q0 = blockIdx.x * 48;
    int tid = threadIdx.x, lane = tid & 31, w = tid >> 5;
    int wn = w << 4;
    int bq = lane & 3, bg = lane >> 2;

    // load QU (hi/lo), 64 rows (48 live + pad, clamped)
    for (int i = tid; i < 512; i += 256) {
        int r = i >> 3, c = i & 7;
        int gq = q0 + r; if (gq >= TP) gq = q0;
        long off = ((long)z * TP + gq) * 64 + c * 8;
        uint32_t so = r * 144 + c * 16;
        cp16(dbase + FS_Q  + so, quh + off);
        cp16(dbase + FS_QL + so, qul + off);
    }
    CP_COMMIT();

    // ---- phase 1: content scores -> S (direct store) ----
#pragma unroll 1
    for (int c = 0; c < 3; c++) {
        for (int i = tid; i < 1024; i += 256) {
            int r = i >> 3, cc = i & 7;
            long off = ((long)z * TP + c * 128 + r) * 64 + cc * 8;
            cp16(dbase + FS_B + r * 144 + cc * 16, kkh + off);
        }
        CP_COMMIT(); CP_WAIT0(); __syncthreads();
        float acc[3][2][4];
#pragma unroll
        for (int a = 0; a < 3; a++)
#pragma unroll
            for (int b = 0; b < 2; b++)
#pragma unroll
                for (int e = 0; e < 4; e++) acc[a][b][e] = 0.0f;
#pragma unroll
        for (int k16 = 0; k16 < 4; k16++) {
            int kb = k16 * 32 + bq * 4;
            uint32_t bh[2][2];
#pragma unroll
            for (int ni = 0; ni < 2; ni++) {
                const char* pb = sm + FS_B + (wn + ni * 8 + bg) * 144 + kb;
                bh[ni][0] = *(const uint32_t*)pb;
                bh[ni][1] = *(const uint32_t*)(pb + 16);
            }
#pragma unroll
            for (int mi = 0; mi < 3; mi++) {
                const char* pa = sm + FS_Q + (mi * 16 + bg) * 144 + kb;
                uint32_t ah[4], al[4];
                ah[0] = *(const uint32_t*)pa;
                ah[1] = *(const uint32_t*)(pa + 8 * 144);
                ah[2] = *(const uint32_t*)(pa + 16);
                ah[3] = *(const uint32_t*)(pa + 8 * 144 + 16);
                al[0] = *(const uint32_t*)(pa + FS_QSZ);
                al[1] = *(const uint32_t*)(pa + FS_QSZ + 8 * 144);
                al[2] = *(const uint32_t*)(pa + FS_QSZ + 16);
                al[3] = *(const uint32_t*)(pa + FS_QSZ + 8 * 144 + 16);
#pragma unroll
                for (int ni = 0; ni < 2; ni++) {
                    mma16816(acc[mi][ni], ah, bh[ni]);
                    mma16816(acc[mi][ni], al, bh[ni]);
                }
            }
        }
#pragma unroll
        for (int mi = 0; mi < 3; mi++)
#pragma unroll
            for (int half = 0; half < 2; half++) {
                int r = mi * 16 + bg + half * 8;
#pragma unroll
                for (int ni = 0; ni < 2; ni++) {
                    int col = c * 128 + wn + ni * 8 + bq * 2;
                    S[r * FS_PITCH + col]     = acc[mi][ni][half * 2 + 0];
                    S[r * FS_PITCH + col + 1] = acc[mi][ni][half * 2 + 1];
                }
            }
        __syncthreads();
    }

    // reload Q buffer with QV (phase 1 done reading it)
    for (int i = tid; i < 512; i += 256) {
        int r = i >> 3, c = i & 7;
        int gq = q0 + r; if (gq >= TP) gq = q0;
        long off = ((long)z * TP + gq) * 64 + c * 8;
        uint32_t so = r * 144 + c * 16;
        cp16(dbase + FS_Q  + so, qvh + off);
        cp16(dbase + FS_QL + so, qvl + off);
    }
    CP_COMMIT();

    // ---- phase 2: pos scores + rel-shift scatter (bijection -> plain +=) ----
#pragma unroll 1
    for (int c = 0; c < 3; c++) {
        for (int i = tid; i < 1024; i += 256) {
            int r = i >> 3, cc = i & 7;
            long off = ((long)z * TP + c * 128 + r) * 64 + cc * 8;
            cp16(dbase + FS_B + r * 144 + cc * 16, pph + off);
        }
        CP_COMMIT(); CP_WAIT0(); __syncthreads();
        float acc[4][2][4];
#pragma unroll
        for (int a = 0; a < 4; a++)
#pragma unroll
            for (int b = 0; b < 2; b++)
#pragma unroll
                for (int e = 0; e < 4; e++) acc[a][b][e] = 0.0f;
#pragma unroll
        for (int k16 = 0; k16 < 4; k16++) {
            int kb = k16 * 32 + bq * 4;
            uint32_t bh[2][2];
#pragma unroll
            for (int ni = 0; ni < 2; ni++) {
                const char* pb = sm + FS_B + (wn + ni * 8 + bg) * 144 + kb;
                bh[ni][0] = *(const uint32_t*)pb;
                bh[ni][1] = *(const uint32_t*)(pb + 16);
            }
#pragma unroll
            for (int mi = 0; mi < 4; mi++) {
                const char* pa = sm + FS_Q + (mi * 16 + bg) * 144 + kb;
                uint32_t ah[4], al[4];
                ah[0] = *(const uint32_t*)pa;
                ah[1] = *(const uint32_t*)(pa + 8 * 144);
                ah[2] = *(const uint32_t*)(pa + 16);
                ah[3] = *(const uint32_t*)(pa + 8 * 144 + 16);
                al[0] = *(const uint32_t*)(pa + FS_QSZ);
                al[1] = *(const uint32_t*)(pa + FS_QSZ + 8 * 144);
                al[2] = *(const uint32_t*)(pa + FS_QSZ + 16);
                al[3] = *(const uint32_t*)(pa + FS_QSZ + 8 * 144 + 16);
#pragma unroll
                for (int ni = 0; ni < 2; ni++) {
                    mma16816(acc[mi][ni], ah, bh[ni]);
                    mma16816(acc[mi][ni], al, bh[ni]);
                }
            }
        }
#pragma unroll
        for (int mi = 0; mi < 4; mi++)
#pragma unroll
            for (int half = 0; half < 2; half++) {
                int r = mi * 16 + bg + half * 8;
                if (r > 48) continue;
                int rp = q0 + r;
#pragma unroll
                for (int ni = 0; ni < 2; ni++)
#pragma unroll
                    for (int e = 0; e < 2; e++) {
                        int jj = c * 128 + wn + ni * 8 + bq * 2 + e;
                        if (jj >= TT) continue;
                        float v = acc[mi][ni][half * 2 + e];
                        if (jj >= 350 - rp) {
                            if (r < 48) S[r * FS_PITCH + jj - 350 + rp] += v;
                        } else if (r >= 1) {
                            S[(r - 1) * FS_PITCH + jj + rp + 1] += v;
                        }
                    }
            }
        __syncthreads();
    }

    // ---- softmax + split-fp16 store (48 rows, 4 threads/row) ----
    if (tid < 192) {
        int r = tid >> 2, qu = tid & 3;
        int gq = q0 + r;
        long rowbase = ((long)z * TP + gq) * TP;
        const float scale = 0.044194173824159216f;
        float* Srow = S + r * FS_PITCH;
        int c0 = qu * 96;
        if (gq >= TT) {
            for (int cc = c0; cc < c0 + 96; cc += 2) {
                *(uint32_t*)(ath + rowbase + cc) = 0u;
                *(uint32_t*)(atl + rowbase + cc) = 0u;
            }
        } else {
            float mx = -1e30f;
            for (int cc = c0; cc < c0 + 96; cc++)
                if (cc < TT) mx = fmaxf(mx, Srow[cc]);
            mx = fmaxf(mx, __shfl_xor_sync(0xffffffffu, mx, 1));
            mx = fmaxf(mx, __shfl_xor_sync(0xffffffffu, mx, 2));
            float mxs = mx * scale;
            float sum = 0.0f;
            for (int cc = c0; cc < c0 + 96; cc++)
                if (cc < TT) {
                    float e = __expf(Srow[cc] * scale - mxs);
                    Srow[cc] = e;
                    sum += e;
                }
            sum += __shfl_xor_sync(0xffffffffu, sum, 1);
            sum += __shfl_xor_sync(0xffffffffu, sum, 2);
            float inv = 1.0f / sum;
            for (int cc = c0; cc < c0 + 96; cc += 2) {
                float v0 = (cc < TT)     ? Srow[cc] * inv     : 0.0f;
                float v1 = (cc + 1 < TT) ? Srow[cc + 1] * inv : 0.0f;
                *(uint32_t*)(ath + rowbase + cc) = packh(v0, v1);
                *(uint32_t*)(atl + rowbase + cc) = packl(v0, v1);
            }
        }
    }
}

// ---------------- batched attn·V -----------------------------------------------------
__global__ __launch_bounds__(256, 2)
void attnv_hmma(const __half* __restrict__ Ahg, const __half* __restrict__ Alg,
                const __half* __restrict__ Bhg,
                __half* __restrict__ Ch, __half* __restrict__ Cl) {
    extern __shared__ char sm[];
    uint32_t dbase = smem_u32(sm);
    int tid = threadIdx.x, lane = tid & 31, w = tid >> 5;
    int wm = (w & 3) << 5, wn = (w >> 2) << 5;
    int z = blockIdx.z, q0 = blockIdx.y << 7;
    const __half* Ah = Ahg + (long)z * TP * TP;
    const __half* Al = Alg + (long)z * TP * TP;
    const __half* Bh = Bhg + (long)z * 64 * TP;

    uint32_t soA[2]; long gaA[2];
#pragma unroll
    for (int j = 0; j < 2; j++) {
        int idx = tid + 256 * j; int row = idx >> 2, c16 = idx & 3;
        soA[j] = row * 80 + c16 * 16;
        gaA[j] = (long)(q0 + row) * TP + c16 * 8;
    }
    uint32_t soB = (tid >> 2) * 80 + (tid & 3) * 16;
    long gB = (long)(tid >> 2) * TP + (tid & 3) * 8;

#define AV_LOAD(c, stg) do { \
        int kb_ = (c) << 5; \
        uint32_t sb_ = dbase + (stg) * AV_STAGE; \
        _Pragma("unroll") \
        for (int j = 0; j < 2; j++) { \
            cp16(sb_ + soA[j],         Ah + gaA[j] + kb_); \
            cp16(sb_ + 10240 + soA[j], Al + gaA[j] + kb_); \
        } \
        cp16(sb_ + 20480 + soB, Bh + gB + kb_); \
    } while (0)

    float acc[2][4][4];
#pragma unroll
    for (int a = 0; a < 2; a++)
#pragma unroll
        for (int b = 0; b < 4; b++)
#pragma unroll
            for (int q2 = 0; q2 < 4; q2++) acc[a][b][q2] = 0.0f;
    int bq = lane & 3, bg = lane >> 2;
    uint32_t aoff = (uint32_t)(wm + (lane & 15)) * 80 + (uint32_t)(((lane >> 4) & 1) << 4);
    uint32_t boff = 20480u + (uint32_t)(wn + ((lane >> 4) << 3) + (lane & 7)) * 80
                  + (uint32_t)(((lane >> 3) & 1) << 4);

    AV_LOAD(0, 0);
    CP_COMMIT();
#pragma unroll 1
    for (int c = 0; c < 12; c++) {
        if (c + 1 < 12) AV_LOAD(c + 1, (c + 1) & 1);
        CP_COMMIT();
        CP_WAIT1();
        __syncthreads();
        uint32_t sb = dbase + (c & 1) * AV_STAGE;
#pragma unroll
        for (int k16 = 0; k16 < 2; k16++) {
            uint32_t kof = k16 * 32;
            uint32_t bh[4][2], t[4];
            ldsm4(t, sb + boff + kof);
            bh[0][0] = t[0]; bh[0][1] = t[1]; bh[1][0] = t[2]; bh[1][1] = t[3];
            ldsm4(t, sb + boff + 1280 + kof);
            bh[2][0] = t[0]; bh[2][1] = t[1]; bh[3][0] = t[2]; bh[3][1] = t[3];
#pragma unroll
            for (int mi = 0; mi < 2; mi++) {
                uint32_t ah[4], al[4];
                ldsm4(ah, sb + aoff + mi * 1280 + kof);
                ldsm4(al, sb + aoff + mi * 1280 + 10240 + kof);
#pragma unroll
                for (int ni = 0; ni < 4; ni++) {
                    mma16816(acc[mi][ni], ah, bh[ni]);
                    mma16816(acc[mi][ni], al, bh[ni]);
                }
            }
        }
        __syncthreads();
    }
#undef AV_LOAD

    int b = z >> 3, h = z & 7;
#pragma unroll
    for (int mi = 0; mi < 2; mi++) {
#pragma unroll
        for (int half = 0; half < 2; half++) {
            int q = q0 + wm + mi * 16 + bg + half * 8;
            if (q >= TT) continue;
#pragma unroll
            for (int ni = 0; ni < 4; ni++) {
                int col = wn + ni * 8 + bq * 2;
                float v0 = acc[mi][ni][half * 2 + 0];
                float v1 = acc[mi][ni][half * 2 + 1];
                long addr = ((long)(b * 351 + q)) * DD + h * 64 + col;
                *(uint32_t*)(Ch + addr) = packh(v0, v1);
                *(uint32_t*)(Cl + addr) = packl(v0, v1);
            }
        }
    }
}

// ---------------- add pos-emb + LayerNorm --------------------------------------------
template<bool F16O>
__global__ void addln_kernel(const float* __restrict__ xin, float* __restrict__ xupd,
                             const float* __restrict__ pe,
                             const float* __restrict__ ga, const float* __restrict__ gb,
                             float* __restrict__ out, __half* __restrict__ ohi,
                             __half* __restrict__ olo) {
    int row = blockIdx.x;
    int t   = row % TT;
    const float* xr = xin + (size_t)row * DD;
    int tid = threadIdx.x;
    float vals[4];
#pragma unroll
    for (int i = 0; i < 4; i++) {
        int c = tid + i * 128;
        float vv = xr[c];
        if (pe) vv += pe[(size_t)t * DD + c];
        vals[i] = vv;
    }
    if (pe) {
        float* xw = xupd + (size_t)row * DD;
#pragma unroll
        for (int i = 0; i < 4; i++) xw[tid + i * 128] = vals[i];
    }
    __shared__ float sh[4];
    float s = vals[0] + vals[1] + vals[2] + vals[3];
#pragma unroll
    for (int o = 16; o > 0; o >>= 1) s += __shfl_xor_sync(0xffffffffu, s, o);
    if ((tid & 31) == 0) sh[tid >> 5] = s;
    __syncthreads();
    float mean = (sh[0] + sh[1] + sh[2] + sh[3]) * (1.0f / DD);
    __syncthreads();
    float sq = 0.0f;
#pragma unroll
    for (int i = 0; i < 4; i++) { float d = vals[i] - mean; sq += d * d; }
#pragma unroll
    for (int o = 16; o > 0; o >>= 1) sq += __shfl_xor_sync(0xffffffffu, sq, o);
    if ((tid & 31) == 0) sh[tid >> 5] = sq;
    __syncthreads();
    float var  = sh[0] + sh[1] + sh[2] + sh[3];
    float stdv = sqrtf(var * (1.0f / (DD - 1)));
    float inv  = 1.0f / (stdv + 1e-6f);
#pragma unroll
    for (int i = 0; i < 4; i++) {
        int c = tid + i * 128;
        float v = ga[c] * (vals[i] - mean) * inv + gb[c];
        if (F16O) {
            __half h = __float2half_rn(v);
            ohi[(size_t)row * DD + c] = h;
            olo[(size_t)row * DD + c] = __float2half_rn(v - __half2float(h));
        } else {
            out[(size_t)row * DD + c] = v;
        }
    }
}

// ------------------------------------ launch -----------------------------------------
extern "C" void kernel_launch(void* const* d_in, const int* in_sizes, int n_in,
                              void* d_out, int out_size) {
    const float* X0  = (const float*)d_in[0];
    const float* MSK = (const float*)d_in[1];
    const float* PE  = (const float*)d_in[2];
    const float* Wq  = (const float*)d_in[3];
    const float* bq  = (const float*)d_in[4];
    const float* Wk  = (const float*)d_in[5];
    const float* bk  = (const float*)d_in[6];
    const float* Wv  = (const float*)d_in[7];
    const float* bv  = (const float*)d_in[8];
    const float* Wp  = (const float*)d_in[9];
    const float* Ub  = (const float*)d_in[10];
    const float* Vb  = (const float*)d_in[11];
    const float* Wo  = (const float*)d_in[12];
    const float* bo  = (const float*)d_in[13];
    const float* l1a = (const float*)d_in[14];
    const float* l1b = (const float*)d_in[15];
    const float* l2a = (const float*)d_in[16];
    const float* l2b = (const float*)d_in[17];
    const float* W1  = (const float*)d_in[18];
    const float* b1  = (const float*)d_in[19];
    const float* W2  = (const float*)d_in[20];
    const float* b2  = (const float*)d_in[21];
    const float* fna = (const float*)d_in[22];
    const float* fnb = (const float*)d_in[23];
    float* x = (float*)d_out;

    __half *ath, *atl, *quh, *qul, *qvh, *qvl, *kkh, *pph, *vth;
    __half *xnh, *xnl, *mkh, *mkl, *cxh, *cxl, *hph, *hpl;
    __half *wqh, *wkh, *wvh, *wph, *woh, *w1h, *w2h;
    cudaGetSymbolAddress((void**)&ath, g_ath); cudaGetSymbolAddress((void**)&atl, g_atl);
    cudaGetSymbolAddress((void**)&quh, g_quh); cudaGetSymbolAddress((void**)&qul, g_qul);
    cudaGetSymbolAddress((void**)&qvh, g_qvh); cudaGetSymbolAddress((void**)&qvl, g_qvl);
    cudaGetSymbolAddress((void**)&kkh, g_kkh); cudaGetSymbolAddress((void**)&pph, g_pph);
    cudaGetSymbolAddress((void**)&vth, g_vth);
    cudaGetSymbolAddress((void**)&xnh, g_xnh); cudaGetSymbolAddress((void**)&xnl, g_xnl);
    cudaGetSymbolAddress((void**)&mkh, g_mkh); cudaGetSymbolAddress((void**)&mkl, g_mkl);
    cudaGetSymbolAddress((void**)&cxh, g_cxh); cudaGetSymbolAddress((void**)&cxl, g_cxl);
    cudaGetSymbolAddress((void**)&hph, g_hph); cudaGetSymbolAddress((void**)&hpl, g_hpl);
    cudaGetSymbolAddress((void**)&wqh, g_wqh); cudaGetSymbolAddress((void**)&wkh, g_wkh);
    cudaGetSymbolAddress((void**)&wvh, g_wvh); cudaGetSymbolAddress((void**)&wph, g_wph);
    cudaGetSymbolAddress((void**)&woh, g_woh);
    cudaGetSymbolAddress((void**)&w1h, g_w1h); cudaGetSymbolAddress((void**)&w2h, g_w2h);

    cudaFuncSetAttribute(hmma_gemm<1, true,  false, 0>, cudaFuncAttributeMaxDynamicSharedMemorySize, SMEMSZ);
    cudaFuncSetAttribute(hmma_gemm<3, true,  false, 0>, cudaFuncAttributeMaxDynamicSharedMemorySize, SMEMSZ);
    cudaFuncSetAttribute(hmma_gemm<1, false, true,  1>, cudaFuncAttributeMaxDynamicSharedMemorySize, SMEMSZ);
    cudaFuncSetAttribute(hmma_gemm<1, false, false, 2>, cudaFuncAttributeMaxDynamicSharedMemorySize, SMEMSZ);
    cudaFuncSetAttribute(hmma_gemm<1, false, false, 3>, cudaFuncAttributeMaxDynamicSharedMemorySize, SMEMSZ);
    cudaFuncSetAttribute(hmma_gemm<1, false, false, 4>, cudaFuncAttributeMaxDynamicSharedMemorySize, SMEMSZ);
    cudaFuncSetAttribute(attn_fused, cudaFuncAttributeMaxDynamicSharedMemorySize, FS_TOT);
    cudaFuncSetAttribute(attnv_hmma, cudaFuncAttributeMaxDynamicSharedMemorySize, AV_SMEM);

    int nW = 3 * DD * DD / 4;
    Ptr5 p5; p5.s0 = Wq; p5.s1 = Wk; p5.s2 = Wv; p5.s3 = Wp; p5.s4 = Wo;
    cvt5<<<dim3((nW + 255) / 256, 5), 256>>>(p5, wqh, wkh, wvh, wph, woh, nW);
    int n1 = 3 * DFFX * DD / 4;
    cvt_half<<<(n1 + 255) / 256, 256>>>(W1, w1h, n1);
    int nM = BT * DD / 4;
    cvt_split<<<(nM + 255) / 256, 256>>>(MSK, mkh, mkl, nM);
    int n2 = 3 * 3 * DD * DFFX;
    cvt_w2<<<(n2 + 255) / 256, 256>>>(W2, w2h);

    dim3 gP(4, MP / 128);
    dim3 gF(8, MP / 128);
    dim3 gAt(8, ZZ);
    dim3 gAV(1, 3, ZZ);

    for (int i = 0; i < 3; i++) {
        size_t oD = (size_t)i * DD, oDD = (size_t)i * DD * DD;
        addln_kernel<true><<<BT, 128>>>(i == 0 ? X0 : x, x, PE + (size_t)i * TT * DD,
                                        l1a + oD, l1b + oD, nullptr, xnh, xnl);
        hmma_gemm<1, false, false, 2><<<gP, 256, SMEMSZ>>>(
            xnh, xnl, wqh + oDD, bq + oD, Ub + oD, Vb + oD,
            nullptr, quh, qul, qvh, qvl, BT, DD, DD);
        hmma_gemm<1, false, false, 3><<<gP, 256, SMEMSZ>>>(
            xnh, xnl, wkh + oDD, bk + oD, nullptr, nullptr,
            nullptr, kkh, nullptr, nullptr, nullptr, BT, DD, DD);
        hmma_gemm<1, false, false, 3><<<gP, 256, SMEMSZ>>>(
            mkh, mkl, wph + oDD, nullptr, nullptr, nullptr,
            nullptr, pph, nullptr, nullptr, nullptr, BT, DD, DD);
        hmma_gemm<1, false, false, 4><<<gP, 256, SMEMSZ>>>(
            xnh, xnl, wvh + oDD, bv + oD, nullptr, nullptr,
            nullptr, vth, nullptr, nullptr, nullptr, BT, DD, DD);
        attn_fused<<<gAt, 256, FS_TOT>>>(quh, qul, qvh, qvl, kkh, pph, ath, atl);
        attnv_hmma<<<gAV, 256, AV_SMEM>>>(ath, atl, vth, cxh, cxl);
        hmma_gemm<1, true, false, 0><<<gP, 256, SMEMSZ>>>(
            cxh, cxl, woh + oDD, bo + oD, nullptr, nullptr,
            x, nullptr, nullptr, nullptr, nullptr, BT, DD, DD);
        addln_kernel<true><<<BT, 128>>>(x, nullptr, nullptr,
                                        l2a + oD, l2b + oD, nullptr, xnh, xnl);
        hmma_gemm<1, false, true, 1><<<gF, 256, SMEMSZ>>>(
            xnh, xnl, w1h + (size_t)i * DFFX * DD,
            b1 + (size_t)i * DFFX, nullptr, nullptr,
            nullptr, hph, hpl, nullptr, nullptr, BT, DFFX, DD);
        hmma_gemm<3, true, false, 0><<<gP, 256, SMEMSZ>>>(
            hph, hpl, w2h + (size_t)i * 3 * DD * DFFX,
            b2 + oD, nullptr, nullptr,
            x, nullptr, nullptr, nullptr, nullptr, BT, DD, DFFX);
    }
    addln_kernel<false><<<BT, 128>>>(x, nullptr, nullptr, fna, fnb, x, nullptr, nullptr);
}

// round 8
// speedup vs baseline: 4.6881x; 1.4842x over previous
#include <cuda_runtime.h>
#include <cuda_fp16.h>
#include <math.h>
#include <stdint.h>

#define BB   64
#define TT   351
#define DD   512
#define HH   8
#define DFFX 1024
#define BT   (BB*TT)       // 22464
#define MP   22528
#define HPR  22784
#define TP   384
#define ZZ   (BB*HH)       // 512
#define STAGE_BYTES 20480  // Ah 10240 + Bh 10240
#define SMEMSZ (2*STAGE_BYTES)
#define AV_STAGE 15360     // Ah 10240 + Bh 5120
#define AV_SMEM (2*AV_STAGE)

// fused-attention smem layout (bytes), q-block = 48 rows
#define FS_PITCH 392
#define FS_Q     75264               // 48*392*4 score bytes before this
#define FS_QSZ   9216                // 64 rows * 144B
#define FS_B     (FS_Q + FS_QSZ)     // 84480
#define FS_BSZ   18432               // 128 rows * 144B
#define FS_TOT   (FS_B + FS_BSZ)     // 102912 -> 2 blocks/SM

// ---------------- scratch ------------------------------------------------------------
static __device__ __half g_ath[(size_t)ZZ*TP*TP];
static __device__ __half g_quh[(size_t)ZZ*TP*64];
static __device__ __half g_qvh[(size_t)ZZ*TP*64];
static __device__ __half g_kkh[(size_t)ZZ*TP*64];
static __device__ __half g_pph[(size_t)ZZ*TP*64];
static __device__ __half g_vth[(size_t)ZZ*64*TP];
static __device__ __half g_xnh[MP*(size_t)DD];
static __device__ __half g_mkh[MP*(size_t)DD];
static __device__ __half g_cxh[MP*(size_t)DD];
static __device__ __half g_hph[(size_t)HPR*DFFX];
static __device__ __half g_wqh[3*DD*DD], g_wkh[3*DD*DD], g_wvh[3*DD*DD];
static __device__ __half g_wph[3*DD*DD], g_woh[3*DD*DD];
static __device__ __half g_w1h[3*DFFX*DD];
static __device__ __half g_w2h[3*3*DD*DFFX];

// ---------------- PTX helpers --------------------------------------------------------
__device__ __forceinline__ uint32_t smem_u32(const void* p) {
    uint32_t a;
    asm("{ .reg .u64 t; cvta.to.shared.u64 t, %1; cvt.u32.u64 %0, t; }" : "=r"(a) : "l"(p));
    return a;
}
__device__ __forceinline__ void cp16(uint32_t dst, const void* src) {
    asm volatile("cp.async.cg.shared.global [%0], [%1], 16;" :: "r"(dst), "l"(src) : "memory");
}
#define CP_COMMIT() asm volatile("cp.async.commit_group;" ::: "memory")
#define CP_WAIT1()  asm volatile("cp.async.wait_group 1;" ::: "memory")
#define CP_WAIT0()  asm volatile("cp.async.wait_group 0;" ::: "memory")

__device__ __forceinline__ void mma16816(float* c, const uint32_t* a, const uint32_t* b) {
    asm volatile(
        "mma.sync.aligned.m16n8k16.row.col.f32.f16.f16.f32 "
        "{%0,%1,%2,%3}, {%4,%5,%6,%7}, {%8,%9}, {%0,%1,%2,%3};"
        : "+f"(c[0]), "+f"(c[1]), "+f"(c[2]), "+f"(c[3])
        : "r"(a[0]), "r"(a[1]), "r"(a[2]), "r"(a[3]), "r"(b[0]), "r"(b[1]));
}
__device__ __forceinline__ void ldsm4(uint32_t* r, uint32_t addr) {
    asm volatile("ldmatrix.sync.aligned.m8n8.x4.shared.b16 {%0,%1,%2,%3}, [%4];"
        : "=r"(r[0]), "=r"(r[1]), "=r"(r[2]), "=r"(r[3]) : "r"(addr));
}
__device__ __forceinline__ uint32_t packh(float a, float b) {
    __half2 h = __floats2half2_rn(a, b);
    return *reinterpret_cast<uint32_t*>(&h);
}

// ---------------- conversion kernels -------------------------------------------------
struct Ptr5 { const float* s0; const float* s1; const float* s2; const float* s3; const float* s4; };
__global__ void cvt5(Ptr5 p, __half* d0, __half* d1, __half* d2, __half* d3, __half* d4, int n4) {
    int i = blockIdx.x * 256 + threadIdx.x;
    if (i >= n4) return;
    const float* s; __half* d;
    switch (blockIdx.y) {
        case 0: s = p.s0; d = d0; break;
        case 1: s = p.s1; d = d1; break;
        case 2: s = p.s2; d = d2; break;
        case 3: s = p.s3; d = d3; break;
        default: s = p.s4; d = d4; break;
    }
    float4 v = ((const float4*)s)[i];
    uint2 st; st.x = packh(v.x, v.y); st.y = packh(v.z, v.w);
    ((uint2*)d)[i] = st;
}
__global__ void cvt_half(const float* __restrict__ in, __half* __restrict__ out, int n4) {
    int i = blockIdx.x * 256 + threadIdx.x;
    if (i >= n4) return;
    float4 v = ((const float4*)in)[i];
    uint2 st; st.x = packh(v.x, v.y); st.y = packh(v.z, v.w);
    ((uint2*)out)[i] = st;
}
// W2 in: [l][n][k][s] -> out [l][s][n][k]
__global__ void cvt_w2(const float* __restrict__ in, __half* __restrict__ hi) {
    int idx = blockIdx.x * 256 + threadIdx.x;
    const int per_l = 3 * DD * DFFX;
    if (idx >= 3 * per_l) return;
    int l = idx / per_l; int r = idx - l * per_l;
    int s = r / (DD * DFFX); int r2 = r - s * (DD * DFFX);
    int n = r2 / DFFX; int k2 = r2 - n * DFFX;
    hi[idx] = __float2half_rn(in[(((size_t)l * DD + n) * DFFX + k2) * 3 + s]);
}

// ---------------- HMMA 1-term fp16 GEMM (ldmatrix) -----------------------------------
// MODE 0: fp32 C (+ACC). MODE 1: fp16 padded-H remap (FF1). MODE 2: dual head-major.
// MODE 3: single head-major. MODE 4: transposed head-major.
template<int TAPS, bool ACC, bool RELU, int MODE>
__global__ __launch_bounds__(256, 2)
void hmma_gemm(const __half* __restrict__ Ahi, const __half* __restrict__ Bhi,
               const float* __restrict__ bias, const float* __restrict__ bias2,
               const float* __restrict__ bias3,
               float* __restrict__ Cf,
               __half* __restrict__ O1h, __half* __restrict__ O2h,
               int Mstore, int N, int K) {
    extern __shared__ char sm[];
    uint32_t dbase = smem_u32(sm);
    int tid = threadIdx.x, lane = tid & 31, w = tid >> 5;
    int wm = (w & 1) << 6, wn = (w >> 1) << 5;
    int bm = blockIdx.y << 7, bn = blockIdx.x << 7;

    uint32_t so[2]; long ga[2], gb[2];
#pragma unroll
    for (int j = 0; j < 2; j++) {
        int idx = tid + 256 * j; int row = idx >> 2, c16 = idx & 3;
        so[j] = row * 80 + c16 * 16;
        int grow = bm + row;
        long arow;
        if (TAPS == 3) { int b = grow / 351; int t = grow - b * 351; arow = (long)b * 353 + t; }
        else arow = grow;
        ga[j] = arow * (long)K + c16 * 8;
        gb[j] = (long)(bn + row) * K + c16 * 8;
    }
    const int kch = K >> 5;
    const int nch = TAPS * kch;

#define LOAD_CHUNK(c, stg) do { \
        int s_ = (c) / kch; int kb_ = ((c) - s_ * kch) << 5; \
        long sK_ = (TAPS == 3) ? (long)s_ * K : 0; \
        long sNK_ = (TAPS == 3) ? (long)s_ * N * K : 0; \
        uint32_t sb_ = dbase + (stg) * STAGE_BYTES; \
        _Pragma("unroll") \
        for (int j = 0; j < 2; j++) { \
            cp16(sb_ + so[j],         Ahi + sK_ + ga[j] + kb_); \
            cp16(sb_ + 10240 + so[j], Bhi + sNK_ + gb[j] + kb_); \
        } \
    } while (0)

    float acc[4][4][4];
#pragma unroll
    for (int a = 0; a < 4; a++)
#pragma unroll
        for (int b = 0; b < 4; b++)
#pragma unroll
            for (int q2 = 0; q2 < 4; q2++) acc[a][b][q2] = 0.0f;

    int bq = lane & 3, bg = lane >> 2;
    uint32_t aoff = (uint32_t)(wm + (lane & 15)) * 80 + (uint32_t)(((lane >> 4) & 1) << 4);
    uint32_t boff = 10240u + (uint32_t)(wn + ((lane >> 4) << 3) + (lane & 7)) * 80
                  + (uint32_t)(((lane >> 3) & 1) << 4);

    LOAD_CHUNK(0, 0);
    CP_COMMIT();
#pragma unroll 1
    for (int c = 0; c < nch; c++) {
        if (c + 1 < nch) LOAD_CHUNK(c + 1, (c + 1) & 1);
        CP_COMMIT();
        CP_WAIT1();
        __syncthreads();
        uint32_t sb = dbase + (c & 1) * STAGE_BYTES;
#pragma unroll
        for (int k16 = 0; k16 < 2; k16++) {
            uint32_t kof = k16 * 32;
            uint32_t bh[4][2], t[4];
            ldsm4(t, sb + boff + kof);
            bh[0][0] = t[0]; bh[0][1] = t[1]; bh[1][0] = t[2]; bh[1][1] = t[3];
            ldsm4(t, sb + boff + 1280 + kof);
            bh[2][0] = t[0]; bh[2][1] = t[1]; bh[3][0] = t[2]; bh[3][1] = t[3];
#pragma unroll
            for (int mi = 0; mi < 4; mi++) {
                uint32_t ah[4];
                ldsm4(ah, sb + aoff + mi * 1280 + kof);
#pragma unroll
                for (int ni = 0; ni < 4; ni++)
                    mma16816(acc[mi][ni], ah, bh[ni]);
            }
        }
        __syncthreads();
    }
#undef LOAD_CHUNK

#pragma unroll
    for (int mi = 0; mi < 4; mi++) {
#pragma unroll
        for (int half = 0; half < 2; half++) {
            int m = bm + wm + mi * 16 + bg + half * 8;
            if (m >= Mstore) continue;
            int b = 0, t = 0; long crow = m;
            if (MODE == 1) { b = m / 351; t = m - b * 351; crow = (long)b * 353 + 1 + t; }
            if (MODE >= 2) { b = m / 351; t = m - b * 351; }
#pragma unroll
            for (int ni = 0; ni < 4; ni++) {
                int col = bn + wn + ni * 8 + bq * 2;
                float v0 = acc[mi][ni][half * 2 + 0];
                float v1 = acc[mi][ni][half * 2 + 1];
                if (bias) { v0 += bias[col]; v1 += bias[col + 1]; }
                if (RELU) { v0 = fmaxf(v0, 0.0f); v1 = fmaxf(v1, 0.0f); }
                if (MODE == 0) {
                    float* cp = Cf + (long)m * N + col;
                    if (ACC) { v0 += cp[0]; v1 += cp[1]; }
                    float2 st; st.x = v0; st.y = v1;
                    *(float2*)cp = st;
                } else if (MODE == 1) {
                    *(uint32_t*)(O1h + crow * (long)N + col) = packh(v0, v1);
                } else if (MODE == 2 || MODE == 3) {
                    int h = col >> 6, d = col & 63;
                    long base = ((long)(b * 8 + h) * TP + t) * 64 + d;
                    float u0 = v0, u1 = v1;
                    if (bias2) { u0 += bias2[col]; u1 += bias2[col + 1]; }
                    *(uint32_t*)(O1h + base) = packh(u0, u1);
                    if (MODE == 2) {
                        float w0 = v0 + bias3[col], w1 = v1 + bias3[col + 1];
                        *(uint32_t*)(O2h + base) = packh(w0, w1);
                    }
                } else { // MODE 4: transposed
                    int h = col >> 6, d = col & 63;
                    O1h[((long)(b * 8 + h) * 64 + d) * TP + t]     = __float2half_rn(v0);
                    O1h[((long)(b * 8 + h) * 64 + d + 1) * TP + t] = __float2half_rn(v1);
                }
            }
        }
    }
}

// ---------------- fused attention (q-block 48, occ 2, 1-term) ------------------------
__global__ __launch_bounds__(256, 2)
void attn_fused(const __half* __restrict__ quh, const __half* __restrict__ qvh,
                const __half* __restrict__ kkh, const __half* __restrict__ pph,
                __half* __restrict__ ath) {
    extern __shared__ char sm[];
    uint32_t dbase = smem_u32(sm);
    float* S = (float*)sm;
    int z = blockIdx.y, q0 = blockIdx.x * 48;
    int tid = threadIdx.x, lane = tid & 31, w = tid >> 5;
    int wn = w << 4;
    int bq = lane & 3, bg = lane >> 2;

    // load QU (64 rows, clamped)
    for (int i = tid; i < 512; i += 256) {
        int r = i >> 3, c = i & 7;
        int gq = q0 + r; if (gq >= TP) gq = q0;
        cp16(dbase + FS_Q + r * 144 + c * 16, quh + ((long)z * TP + gq) * 64 + c * 8);
    }
    CP_COMMIT();

    // ---- phase 1: content scores -> S ----
#pragma unroll 1
    for (int c = 0; c < 3; c++) {
        for (int i = tid; i < 1024; i += 256) {
            int r = i >> 3, cc = i & 7;
            cp16(dbase + FS_B + r * 144 + cc * 16,
                 kkh + ((long)z * TP + c * 128 + r) * 64 + cc * 8);
        }
        CP_COMMIT(); CP_WAIT0(); __syncthreads();
        float acc[3][2][4];
#pragma unroll
        for (int a = 0; a < 3; a++)
#pragma unroll
            for (int b = 0; b < 2; b++)
#pragma unroll
                for (int e = 0; e < 4; e++) acc[a][b][e] = 0.0f;
#pragma unroll
        for (int k16 = 0; k16 < 4; k16++) {
            int kb = k16 * 32 + bq * 4;
            uint32_t bh[2][2];
#pragma unroll
            for (int ni = 0; ni < 2; ni++) {
                const char* pb = sm + FS_B + (wn + ni * 8 + bg) * 144 + kb;
                bh[ni][0] = *(const uint32_t*)pb;
                bh[ni][1] = *(const uint32_t*)(pb + 16);
            }
#pragma unroll
            for (int mi = 0; mi < 3; mi++) {
                const char* pa = sm + FS_Q + (mi * 16 + bg) * 144 + kb;
                uint32_t ah[4];
                ah[0] = *(const uint32_t*)pa;
                ah[1] = *(const uint32_t*)(pa + 8 * 144);
                ah[2] = *(const uint32_t*)(pa + 16);
                ah[3] = *(const uint32_t*)(pa + 8 * 144 + 16);
#pragma unroll
                for (int ni = 0; ni < 2; ni++)
                    mma16816(acc[mi][ni], ah, bh[ni]);
            }
        }
#pragma unroll
        for (int mi = 0; mi < 3; mi++)
#pragma unroll
            for (int half = 0; half < 2; half++) {
                int r = mi * 16 + bg + half * 8;
#pragma unroll
                for (int ni = 0; ni < 2; ni++) {
                    int col = c * 128 + wn + ni * 8 + bq * 2;
                    S[r * FS_PITCH + col]     = acc[mi][ni][half * 2 + 0];
                    S[r * FS_PITCH + col + 1] = acc[mi][ni][half * 2 + 1];
                }
            }
        __syncthreads();
    }

    // reload Q buffer with QV
    for (int i = tid; i < 512; i += 256) {
        int r = i >> 3, c = i & 7;
        int gq = q0 + r; if (gq >= TP) gq = q0;
        cp16(dbase + FS_Q + r * 144 + c * 16, qvh + ((long)z * TP + gq) * 64 + c * 8);
    }
    CP_COMMIT();

    // ---- phase 2: pos scores + rel-shift scatter (bijection, plain +=) ----
#pragma unroll 1
    for (int c = 0; c < 3; c++) {
        for (int i = tid; i < 1024; i += 256) {
            int r = i >> 3, cc = i & 7;
            cp16(dbase + FS_B + r * 144 + cc * 16,
                 pph + ((long)z * TP + c * 128 + r) * 64 + cc * 8);
        }
        CP_COMMIT(); CP_WAIT0(); __syncthreads();
        float acc[4][2][4];
#pragma unroll
        for (int a = 0; a < 4; a++)
#pragma unroll
            for (int b = 0; b < 2; b++)
#pragma unroll
                for (int e = 0; e < 4; e++) acc[a][b][e] = 0.0f;
#pragma unroll
        for (int k16 = 0; k16 < 4; k16++) {
            int kb = k16 * 32 + bq * 4;
            uint32_t bh[2][2];
#pragma unroll
            for (int ni = 0; ni < 2; ni++) {
                const char* pb = sm + FS_B + (wn + ni * 8 + bg) * 144 + kb;
                bh[ni][0] = *(const uint32_t*)pb;
                bh[ni][1] = *(const uint32_t*)(pb + 16);
            }
#pragma unroll
            for (int mi = 0; mi < 4; mi++) {
                const char* pa = sm + FS_Q + (mi * 16 + bg) * 144 + kb;
                uint32_t ah[4];
                ah[0] = *(const uint32_t*)pa;
                ah[1] = *(const uint32_t*)(pa + 8 * 144);
                ah[2] = *(const uint32_t*)(pa + 16);
                ah[3] = *(const uint32_t*)(pa + 8 * 144 + 16);
#pragma unroll
                for (int ni = 0; ni < 2; ni++)
                    mma16816(acc[mi][ni], ah, bh[ni]);
            }
        }
#pragma unroll
        for (int mi = 0; mi < 4; mi++)
#pragma unroll
            for (int half = 0; half < 2; half++) {
                int r = mi * 16 + bg + half * 8;
                if (r > 48) continue;
                int rp = q0 + r;
#pragma unroll
                for (int ni = 0; ni < 2; ni++)
#pragma unroll
                    for (int e = 0; e < 2; e++) {
                        int jj = c * 128 + wn + ni * 8 + bq * 2 + e;
                        if (jj >= TT) continue;
                        float v = acc[mi][ni][half * 2 + e];
                        if (jj >= 350 - rp) {
                            if (r < 48) S[r * FS_PITCH + jj - 350 + rp] += v;
                        } else if (r >= 1) {
                            S[(r - 1) * FS_PITCH + jj + rp + 1] += v;
                        }
                    }
            }
        __syncthreads();
    }

    // ---- softmax + fp16 store ----
    if (tid < 192) {
        int r = tid >> 2, qu = tid & 3;
        int gq = q0 + r;
        long rowbase = ((long)z * TP + gq) * TP;
        const float scale = 0.044194173824159216f;
        float* Srow = S + r * FS_PITCH;
        int c0 = qu * 96;
        if (gq >= TT) {
            for (int cc = c0; cc < c0 + 96; cc += 2)
                *(uint32_t*)(ath + rowbase + cc) = 0u;
        } else {
            float mx = -1e30f;
            for (int cc = c0; cc < c0 + 96; cc++)
                if (cc < TT) mx = fmaxf(mx, Srow[cc]);
            mx = fmaxf(mx, __shfl_xor_sync(0xffffffffu, mx, 1));
            mx = fmaxf(mx, __shfl_xor_sync(0xffffffffu, mx, 2));
            float mxs = mx * scale;
            float sum = 0.0f;
            for (int cc = c0; cc < c0 + 96; cc++)
                if (cc < TT) {
                    float e = __expf(Srow[cc] * scale - mxs);
                    Srow[cc] = e;
                    sum += e;
                }
            sum += __shfl_xor_sync(0xffffffffu, sum, 1);
            sum += __shfl_xor_sync(0xffffffffu, sum, 2);
            float inv = 1.0f / sum;
            for (int cc = c0; cc < c0 + 96; cc += 2) {
                float v0 = (cc < TT)     ? Srow[cc] * inv     : 0.0f;
                float v1 = (cc + 1 < TT) ? Srow[cc + 1] * inv : 0.0f;
                *(uint32_t*)(ath + rowbase + cc) = packh(v0, v1);
            }
        }
    }
}

// ---------------- batched attn·V (1-term) --------------------------------------------
__global__ __launch_bounds__(256, 2)
void attnv_hmma(const __half* __restrict__ Ahg, const __half* __restrict__ Bhg,
                __half* __restrict__ Ch) {
    extern __shared__ char sm[];
    uint32_t dbase = smem_u32(sm);
    int tid = threadIdx.x, lane = tid & 31, w = tid >> 5;
    int wm = (w & 3) << 5, wn = (w >> 2) << 5;
    int z = blockIdx.z, q0 = blockIdx.y << 7;
    const __half* Ah = Ahg + (long)z * TP * TP;
    const __half* Bh = Bhg + (long)z * 64 * TP;

    uint32_t soA[2]; long gaA[2];
#pragma unroll
    for (int j = 0; j < 2; j++) {
        int idx = tid + 256 * j; int row = idx >> 2, c16 = idx & 3;
        soA[j] = row * 80 + c16 * 16;
        gaA[j] = (long)(q0 + row) * TP + c16 * 8;
    }
    uint32_t soB = (tid >> 2) * 80 + (tid & 3) * 16;
    long gB = (long)(tid >> 2) * TP + (tid & 3) * 8;

#define AV_LOAD(c, stg) do { \
        int kb_ = (c) << 5; \
        uint32_t sb_ = dbase + (stg) * AV_STAGE; \
        _Pragma("unroll") \
        for (int j = 0; j < 2; j++) \
            cp16(sb_ + soA[j], Ah + gaA[j] + kb_); \
        cp16(sb_ + 10240 + soB, Bh + gB + kb_); \
    } while (0)

    float acc[2][4][4];
#pragma unroll
    for (int a = 0; a < 2; a++)
#pragma unroll
        for (int b = 0; b < 4; b++)
#pragma unroll
            for (int q2 = 0; q2 < 4; q2++) acc[a][b][q2] = 0.0f;
    int bq = lane & 3, bg = lane >> 2;
    uint32_t aoff = (uint32_t)(wm + (lane & 15)) * 80 + (uint32_t)(((lane >> 4) & 1) << 4);
    uint32_t boff = 10240u + (uint32_t)(wn + ((lane >> 4) << 3) + (lane & 7)) * 80
                  + (uint32_t)(((lane >> 3) & 1) << 4);

    AV_LOAD(0, 0);
    CP_COMMIT();
#pragma unroll 1
    for (int c = 0; c < 12; c++) {
        if (c + 1 < 12) AV_LOAD(c + 1, (c + 1) & 1);
        CP_COMMIT();
        CP_WAIT1();
        __syncthreads();
        uint32_t sb = dbase + (c & 1) * AV_STAGE;
#pragma unroll
        for (int k16 = 0; k16 < 2; k16++) {
            uint32_t kof = k16 * 32;
            uint32_t bh[4][2], t[4];
            ldsm4(t, sb + boff + kof);
            bh[0][0] = t[0]; bh[0][1] = t[1]; bh[1][0] = t[2]; bh[1][1] = t[3];
            ldsm4(t, sb + boff + 1280 + kof);
            bh[2][0] = t[0]; bh[2][1] = t[1]; bh[3][0] = t[2]; bh[3][1] = t[3];
#pragma unroll
            for (int mi = 0; mi < 2; mi++) {
                uint32_t ah[4];
                ldsm4(ah, sb + aoff + mi * 1280 + kof);
#pragma unroll
                for (int ni = 0; ni < 4; ni++)
                    mma16816(acc[mi][ni], ah, bh[ni]);
            }
        }
        __syncthreads();
    }
#undef AV_LOAD

    int b = z >> 3, h = z & 7;
#pragma unroll
    for (int mi = 0; mi < 2; mi++) {
#pragma unroll
        for (int half = 0; half < 2; half++) {
            int q = q0 + wm + mi * 16 + bg + half * 8;
            if (q >= TT) continue;
#pragma unroll
            for (int ni = 0; ni < 4; ni++) {
                int col = wn + ni * 8 + bq * 2;
                float v0 = acc[mi][ni][half * 2 + 0];
                float v1 = acc[mi][ni][half * 2 + 1];
                long addr = ((long)(b * 351 + q)) * DD + h * 64 + col;
                *(uint32_t*)(Ch + addr) = packh(v0, v1);
            }
        }
    }
}

// ---------------- add pos-emb + LayerNorm --------------------------------------------
template<bool F16O>
__global__ void addln_kernel(const float* __restrict__ xin, float* __restrict__ xupd,
                             const float* __restrict__ pe,
                             const float* __restrict__ ga, const float* __restrict__ gb,
                             float* __restrict__ out, __half* __restrict__ ohi) {
    int row = blockIdx.x;
    int t   = row % TT;
    const float* xr = xin + (size_t)row * DD;
    int tid = threadIdx.x;
    float vals[4];
#pragma unroll
    for (int i = 0; i < 4; i++) {
        int c = tid + i * 128;
        float vv = xr[c];
        if (pe) vv += pe[(size_t)t * DD + c];
        vals[i] = vv;
    }
    if (pe) {
        float* xw = xupd + (size_t)row * DD;
#pragma unroll
        for (int i = 0; i < 4; i++) xw[tid + i * 128] = vals[i];
    }
    __shared__ float sh[4];
    float s = vals[0] + vals[1] + vals[2] + vals[3];
#pragma unroll
    for (int o = 16; o > 0; o >>= 1) s += __shfl_xor_sync(0xffffffffu, s, o);
    if ((tid & 31) == 0) sh[tid >> 5] = s;
    __syncthreads();
    float mean = (sh[0] + sh[1] + sh[2] + sh[3]) * (1.0f / DD);
    __syncthreads();
    float sq = 0.0f;
#pragma unroll
    for (int i = 0; i < 4; i++) { float d = vals[i] - mean; sq += d * d; }
#pragma unroll
    for (int o = 16; o > 0; o >>= 1) sq += __shfl_xor_sync(0xffffffffu, sq, o);
    if ((tid & 31) == 0) sh[tid >> 5] = sq;
    __syncthreads();
    float var  = sh[0] + sh[1] + sh[2] + sh[3];
    float stdv = sqrtf(var * (1.0f / (DD - 1)));
    float inv  = 1.0f / (stdv + 1e-6f);
#pragma unroll
    for (int i = 0; i < 4; i++) {
        int c = tid + i * 128;
        float v = ga[c] * (vals[i] - mean) * inv + gb[c];
        if (F16O) ohi[(size_t)row * DD + c] = __float2half_rn(v);
        else      out[(size_t)row * DD + c] = v;
    }
}

// ------------------------------------ launch -----------------------------------------
extern "C" void kernel_launch(void* const* d_in, const int* in_sizes, int n_in,
                              void* d_out, int out_size) {
    const float* X0  = (const float*)d_in[0];
    const float* MSK = (const float*)d_in[1];
    const float* PE  = (const float*)d_in[2];
    const float* Wq  = (const float*)d_in[3];
    const float* bq  = (const float*)d_in[4];
    const float* Wk  = (const float*)d_in[5];
    const float* bk  = (const float*)d_in[6];
    const float* Wv  = (const float*)d_in[7];
    const float* bv  = (const float*)d_in[8];
    const float* Wp  = (const float*)d_in[9];
    const float* Ub  = (const float*)d_in[10];
    const float* Vb  = (const float*)d_in[11];
    const float* Wo  = (const float*)d_in[12];
    const float* bo  = (const float*)d_in[13];
    const float* l1a = (const float*)d_in[14];
    const float* l1b = (const float*)d_in[15];
    const float* l2a = (const float*)d_in[16];
    const float* l2b = (const float*)d_in[17];
    const float* W1  = (const float*)d_in[18];
    const float* b1  = (const float*)d_in[19];
    const float* W2  = (const float*)d_in[20];
    const float* b2  = (const float*)d_in[21];
    const float* fna = (const float*)d_in[22];
    const float* fnb = (const float*)d_in[23];
    float* x = (float*)d_out;

    __half *ath, *quh, *qvh, *kkh, *pph, *vth;
    __half *xnh, *mkh, *cxh, *hph;
    __half *wqh, *wkh, *wvh, *wph, *woh, *w1h, *w2h;
    cudaGetSymbolAddress((void**)&ath, g_ath);
    cudaGetSymbolAddress((void**)&quh, g_quh); cudaGetSymbolAddress((void**)&qvh, g_qvh);
    cudaGetSymbolAddress((void**)&kkh, g_kkh); cudaGetSymbolAddress((void**)&pph, g_pph);
    cudaGetSymbolAddress((void**)&vth, g_vth);
    cudaGetSymbolAddress((void**)&xnh, g_xnh); cudaGetSymbolAddress((void**)&mkh, g_mkh);
    cudaGetSymbolAddress((void**)&cxh, g_cxh); cudaGetSymbolAddress((void**)&hph, g_hph);
    cudaGetSymbolAddress((void**)&wqh, g_wqh); cudaGetSymbolAddress((void**)&wkh, g_wkh);
    cudaGetSymbolAddress((void**)&wvh, g_wvh); cudaGetSymbolAddress((void**)&wph, g_wph);
    cudaGetSymbolAddress((void**)&woh, g_woh);
    cudaGetSymbolAddress((void**)&w1h, g_w1h); cudaGetSymbolAddress((void**)&w2h, g_w2h);

    cudaFuncSetAttribute(hmma_gemm<1, true,  false, 0>, cudaFuncAttributeMaxDynamicSharedMemorySize, SMEMSZ);
    cudaFuncSetAttribute(hmma_gemm<3, true,  false, 0>, cudaFuncAttributeMaxDynamicSharedMemorySize, SMEMSZ);
    cudaFuncSetAttribute(hmma_gemm<1, false, true,  1>, cudaFuncAttributeMaxDynamicSharedMemorySize, SMEMSZ);
    cudaFuncSetAttribute(hmma_gemm<1, false, false, 2>, cudaFuncAttributeMaxDynamicSharedMemorySize, SMEMSZ);
    cudaFuncSetAttribute(hmma_gemm<1, false, false, 3>, cudaFuncAttributeMaxDynamicSharedMemorySize, SMEMSZ);
    cudaFuncSetAttribute(hmma_gemm<1, false, false, 4>, cudaFuncAttributeMaxDynamicSharedMemorySize, SMEMSZ);
    cudaFuncSetAttribute(attn_fused, cudaFuncAttributeMaxDynamicSharedMemorySize, FS_TOT);
    cudaFuncSetAttribute(attnv_hmma, cudaFuncAttributeMaxDynamicSharedMemorySize, AV_SMEM);

    int nW = 3 * DD * DD / 4;
    Ptr5 p5; p5.s0 = Wq; p5.s1 = Wk; p5.s2 = Wv; p5.s3 = Wp; p5.s4 = Wo;
    cvt5<<<dim3((nW + 255) / 256, 5), 256>>>(p5, wqh, wkh, wvh, wph, woh, nW);
    int n1 = 3 * DFFX * DD / 4;
    cvt_half<<<(n1 + 255) / 256, 256>>>(W1, w1h, n1);
    int nM = BT * DD / 4;
    cvt_half<<<(nM + 255) / 256, 256>>>(MSK, mkh, nM);
    int n2 = 3 * 3 * DD * DFFX;
    cvt_w2<<<(n2 + 255) / 256, 256>>>(W2, w2h);

    dim3 gP(4, MP / 128);
    dim3 gF(8, MP / 128);
    dim3 gAt(8, ZZ);
    dim3 gAV(1, 3, ZZ);

    for (int i = 0; i < 3; i++) {
        size_t oD = (size_t)i * DD, oDD = (size_t)i * DD * DD;
        addln_kernel<true><<<BT, 128>>>(i == 0 ? X0 : x, x, PE + (size_t)i * TT * DD,
                                        l1a + oD, l1b + oD, nullptr, xnh);
        hmma_gemm<1, false, false, 2><<<gP, 256, SMEMSZ>>>(
            xnh, wqh + oDD, bq + oD, Ub + oD, Vb + oD,
            nullptr, quh, qvh, BT, DD, DD);
        hmma_gemm<1, false, false, 3><<<gP, 256, SMEMSZ>>>(
            xnh, wkh + oDD, bk + oD, nullptr, nullptr,
            nullptr, kkh, nullptr, BT, DD, DD);
        hmma_gemm<1, false, false, 3><<<gP, 256, SMEMSZ>>>(
            mkh, wph + oDD, nullptr, nullptr, nullptr,
            nullptr, pph, nullptr, BT, DD, DD);
        hmma_gemm<1, false, false, 4><<<gP, 256, SMEMSZ>>>(
            xnh, wvh + oDD, bv + oD, nullptr, nullptr,
            nullptr, vth, nullptr, BT, DD, DD);
        attn_fused<<<gAt, 256, FS_TOT>>>(quh, qvh, kkh, pph, ath);
        attnv_hmma<<<gAV, 256, AV_SMEM>>>(ath, vth, cxh);
        hmma_gemm<1, true, false, 0><<<gP, 256, SMEMSZ>>>(
            cxh, woh + oDD, bo + oD, nullptr, nullptr,
            x, nullptr, nullptr, BT, DD, DD);
        addln_kernel<true><<<BT, 128>>>(x, nullptr, nullptr,
                                        l2a + oD, l2b + oD, nullptr, xnh);
        hmma_gemm<1, false, true, 1><<<gF, 256, SMEMSZ>>>(
            xnh, w1h + (size_t)i * DFFX * DD,
            b1 + (size_t)i * DFFX, nullptr, nullptr,
            nullptr, hph, nullptr, BT, DFFX, DD);
        hmma_gemm<3, true, false, 0><<<gP, 256, SMEMSZ>>>(
            hph, w2h + (size_t)i * 3 * DD * DFFX,
            b2 + oD, nullptr, nullptr,
            x, nullptr, nullptr, BT, DD, DFFX);
    }
    addln_kernel<false><<<BT, 128>>>(x, nullptr, nullptr, fna, fnb, x, nullptr);
}

// round 10
// speedup vs baseline: 5.5906x; 1.1925x over previous
#include <cuda_runtime.h>
#include <cuda_fp16.h>
#include <math.h>
#include <stdint.h>

#define BB   64
#define TT   351
#define DD   512
#define HH   8
#define DFFX 1024
#define BT   (BB*TT)       // 22464
#define MP   22528
#define HPR  22784
#define TP   384
#define ZZ   (BB*HH)       // 512
#define STAGE_BYTES 36864  // Ah 18432 + Bh 18432 (128 rows x 144B each)
#define SMEMSZ (2*STAGE_BYTES)

// fused-attention smem layout (bytes), q-block = 48 rows
#define FS_PITCH 392
#define FS_Q     75264               // 48*392*4 score bytes before this
#define FS_QSZ   9216                // 64 rows * 144B
#define FS_B     (FS_Q + FS_QSZ)     // 84480
// after softmax: A fp16 (48 x pitch784) at 75264, V tile (64 x pitch784) at 0
#define AF_A     75264
#define AF_PITCH 784
#define FS_TOT   112896              // occ 2

// ---------------- scratch ------------------------------------------------------------
static __device__ __half g_quh[(size_t)ZZ*TP*64];
static __device__ __half g_qvh[(size_t)ZZ*TP*64];
static __device__ __half g_kkh[(size_t)ZZ*TP*64];
static __device__ __half g_pph[(size_t)ZZ*TP*64];
static __device__ __half g_vth[(size_t)ZZ*64*TP];
static __device__ __half g_xnh[MP*(size_t)DD];
static __device__ __half g_mkh[MP*(size_t)DD];
static __device__ __half g_cxh[MP*(size_t)DD];
static __device__ __half g_hph[(size_t)HPR*DFFX];
static __device__ __half g_wqh[3*DD*DD], g_wkh[3*DD*DD], g_wvh[3*DD*DD];
static __device__ __half g_wph[3*DD*DD], g_woh[3*DD*DD];
static __device__ __half g_w1h[3*DFFX*DD];
static __device__ __half g_w2h[3*3*DD*DFFX];

// ---------------- PTX helpers --------------------------------------------------------
__device__ __forceinline__ uint32_t smem_u32(const void* p) {
    uint32_t a;
    asm("{ .reg .u64 t; cvta.to.shared.u64 t, %1; cvt.u32.u64 %0, t; }" : "=r"(a) : "l"(p));
    return a;
}
__device__ __forceinline__ void cp16(uint32_t dst, const void* src) {
    asm volatile("cp.async.cg.shared.global [%0], [%1], 16;" :: "r"(dst), "l"(src) : "memory");
}
#define CP_COMMIT() asm volatile("cp.async.commit_group;" ::: "memory")
#define CP_WAIT1()  asm volatile("cp.async.wait_group 1;" ::: "memory")
#define CP_WAIT0()  asm volatile("cp.async.wait_group 0;" ::: "memory")

__device__ __forceinline__ void mma16816(float* c, const uint32_t* a, const uint32_t* b) {
    asm volatile(
        "mma.sync.aligned.m16n8k16.row.col.f32.f16.f16.f32 "
        "{%0,%1,%2,%3}, {%4,%5,%6,%7}, {%8,%9}, {%0,%1,%2,%3};"
        : "+f"(c[0]), "+f"(c[1]), "+f"(c[2]), "+f"(c[3])
        : "r"(a[0]), "r"(a[1]), "r"(a[2]), "r"(a[3]), "r"(b[0]), "r"(b[1]));
}
__device__ __forceinline__ void ldsm4(uint32_t* r, uint32_t addr) {
    asm volatile("ldmatrix.sync.aligned.m8n8.x4.shared.b16 {%0,%1,%2,%3}, [%4];"
        : "=r"(r[0]), "=r"(r[1]), "=r"(r[2]), "=r"(r[3]) : "r"(addr));
}
__device__ __forceinline__ uint32_t packh(float a, float b) {
    __half2 h = __floats2half2_rn(a, b);
    return *reinterpret_cast<uint32_t*>(&h);
}

// ---------------- conversion kernels -------------------------------------------------
struct Ptr5 { const float* s0; const float* s1; const float* s2; const float* s3; const float* s4; };
__global__ void cvt5(Ptr5 p, __half* d0, __half* d1, __half* d2, __half* d3, __half* d4, int n4) {
    int i = blockIdx.x * 256 + threadIdx.x;
    if (i >= n4) return;
    const float* s; __half* d;
    switch (blockIdx.y) {
        case 0: s = p.s0; d = d0; break;
        case 1: s = p.s1; d = d1; break;
        case 2: s = p.s2; d = d2; break;
        case 3: s = p.s3; d = d3; break;
        default: s = p.s4; d = d4; break;
    }
    float4 v = ((const float4*)s)[i];
    uint2 st; st.x = packh(v.x, v.y); st.y = packh(v.z, v.w);
    ((uint2*)d)[i] = st;
}
__global__ void cvt_half(const float* __restrict__ in, __half* __restrict__ out, int n4) {
    int i = blockIdx.x * 256 + threadIdx.x;
    if (i >= n4) return;
    float4 v = ((const float4*)in)[i];
    uint2 st; st.x = packh(v.x, v.y); st.y = packh(v.z, v.w);
    ((uint2*)out)[i] = st;
}
// W2 in: [l][n][k][s] -> out [l][s][n][k]
__global__ void cvt_w2(const float* __restrict__ in, __half* __restrict__ hi) {
    int idx = blockIdx.x * 256 + threadIdx.x;
    const int per_l = 3 * DD * DFFX;
    if (idx >= 3 * per_l) return;
    int l = idx / per_l; int r = idx - l * per_l;
    int s = r / (DD * DFFX); int r2 = r - s * (DD * DFFX);
    int n = r2 / DFFX; int k2 = r2 - n * DFFX;
    hi[idx] = __float2half_rn(in[(((size_t)l * DD + n) * DFFX + k2) * 3 + s]);
}

// ---------------- HMMA 1-term fp16 GEMM, K-chunk 64 (ldmatrix) -----------------------
// MODE 0: fp32 C (+ACC). MODE 1: fp16 padded-H remap (FF1). MODE 2: dual head-major.
// MODE 3: single head-major. MODE 4: transposed head-major.
template<int TAPS, bool ACC, bool RELU, int MODE>
__global__ __launch_bounds__(256, 2)
void hmma_gemm(const __half* __restrict__ Ahi, const __half* __restrict__ Bhi,
               const float* __restrict__ bias, const float* __restrict__ bias2,
               const float* __restrict__ bias3,
               float* __restrict__ Cf,
               __half* __restrict__ O1h, __half* __restrict__ O2h,
               int Mstore, int N, int K) {
    extern __shared__ char sm[];
    uint32_t dbase = smem_u32(sm);
    int tid = threadIdx.x, lane = tid & 31, w = tid >> 5;
    int wm = (w & 1) << 6, wn = (w >> 1) << 5;
    int bm = blockIdx.y << 7, bn = blockIdx.x << 7;

    uint32_t so[4]; long ga[4], gb[4];
#pragma unroll
    for (int j = 0; j < 4; j++) {
        int idx = tid + 256 * j; int row = idx >> 3, c16 = idx & 7;
        so[j] = row * 144 + c16 * 16;
        int grow = bm + row;
        long arow;
        if (TAPS == 3) { int b = grow / 351; int t = grow - b * 351; arow = (long)b * 353 + t; }
        else arow = grow;
        ga[j] = arow * (long)K + c16 * 8;
        gb[j] = (long)(bn + row) * K + c16 * 8;
    }
    const int kch = K >> 6;
    const int nch = TAPS * kch;

#define LOAD_CHUNK(c, stg) do { \
        int s_ = (c) / kch; int kb_ = ((c) - s_ * kch) << 6; \
        long sK_ = (TAPS == 3) ? (long)s_ * K : 0; \
        long sNK_ = (TAPS == 3) ? (long)s_ * N * K : 0; \
        uint32_t sb_ = dbase + (stg) * STAGE_BYTES; \
        _Pragma("unroll") \
        for (int j = 0; j < 4; j++) { \
            cp16(sb_ + so[j],         Ahi + sK_ + ga[j] + kb_); \
            cp16(sb_ + 18432 + so[j], Bhi + sNK_ + gb[j] + kb_); \
        } \
    } while (0)

    float acc[4][4][4];
#pragma unroll
    for (int a = 0; a < 4; a++)
#pragma unroll
        for (int b = 0; b < 4; b++)
#pragma unroll
            for (int q2 = 0; q2 < 4; q2++) acc[a][b][q2] = 0.0f;

    int bq = lane & 3, bg = lane >> 2;
    uint32_t aoff = (uint32_t)(wm + (lane & 15)) * 144 + (uint32_t)(((lane >> 4) & 1) << 4);
    uint32_t boff = 18432u + (uint32_t)(wn + ((lane >> 4) << 3) + (lane & 7)) * 144
                  + (uint32_t)(((lane >> 3) & 1) << 4);

    LOAD_CHUNK(0, 0);
    CP_COMMIT();
#pragma unroll 1
    for (int c = 0; c < nch; c++) {
        if (c + 1 < nch) LOAD_CHUNK(c + 1, (c + 1) & 1);
        CP_COMMIT();
        CP_WAIT1();
        __syncthreads();
        uint32_t sb = dbase + (c & 1) * STAGE_BYTES;
#pragma unroll
        for (int k16 = 0; k16 < 4; k16++) {
            uint32_t kof = k16 * 32;
            uint32_t bh[4][2], t[4];
            ldsm4(t, sb + boff + kof);
            bh[0][0] = t[0]; bh[0][1] = t[1]; bh[1][0] = t[2]; bh[1][1] = t[3];
            ldsm4(t, sb + boff + 2304 + kof);
            bh[2][0] = t[0]; bh[2][1] = t[1]; bh[3][0] = t[2]; bh[3][1] = t[3];
#pragma unroll
            for (int mi = 0; mi < 4; mi++) {
                uint32_t ah[4];
                ldsm4(ah, sb + aoff + mi * 2304 + kof);
#pragma unroll
                for (int ni = 0; ni < 4; ni++)
                    mma16816(acc[mi][ni], ah, bh[ni]);
            }
        }
        __syncthreads();
    }
#undef LOAD_CHUNK

#pragma unroll
    for (int mi = 0; mi < 4; mi++) {
#pragma unroll
        for (int half = 0; half < 2; half++) {
            int m = bm + wm + mi * 16 + bg + half * 8;
            if (m >= Mstore) continue;
            int b = 0, t = 0; long crow = m;
            if (MODE == 1) { b = m / 351; t = m - b * 351; crow = (long)b * 353 + 1 + t; }
            if (MODE >= 2) { b = m / 351; t = m - b * 351; }
#pragma unroll
            for (int ni = 0; ni < 4; ni++) {
                int col = bn + wn + ni * 8 + bq * 2;
                float v0 = acc[mi][ni][half * 2 + 0];
                float v1 = acc[mi][ni][half * 2 + 1];
                if (bias) { v0 += bias[col]; v1 += bias[col + 1]; }
                if (RELU) { v0 = fmaxf(v0, 0.0f); v1 = fmaxf(v1, 0.0f); }
                if (MODE == 0) {
                    float* cp = Cf + (long)m * N + col;
                    if (ACC) { v0 += cp[0]; v1 += cp[1]; }
                    float2 st; st.x = v0; st.y = v1;
                    *(float2*)cp = st;
                } else if (MODE == 1) {
                    *(uint32_t*)(O1h + crow * (long)N + col) = packh(v0, v1);
                } else if (MODE == 2 || MODE == 3) {
                    int h = col >> 6, d = col & 63;
                    long base = ((long)(b * 8 + h) * TP + t) * 64 + d;
                    float u0 = v0, u1 = v1;
                    if (bias2) { u0 += bias2[col]; u1 += bias2[col + 1]; }
                    *(uint32_t*)(O1h + base) = packh(u0, u1);
                    if (MODE == 2) {
                        float w0 = v0 + bias3[col], w1 = v1 + bias3[col + 1];
                        *(uint32_t*)(O2h + base) = packh(w0, w1);
                    }
                } else { // MODE 4: transposed
                    int h = col >> 6, d = col & 63;
                    O1h[((long)(b * 8 + h) * 64 + d) * TP + t]     = __float2half_rn(v0);
                    O1h[((long)(b * 8 + h) * 64 + d + 1) * TP + t] = __float2half_rn(v1);
                }
            }
        }
    }
}

// ---------------- fully fused attention (scores + shift + softmax + attn·V) ----------
__global__ __launch_bounds__(256, 2)
void attn_fused(const __half* __restrict__ quh, const __half* __restrict__ qvh,
                const __half* __restrict__ kkh, const __half* __restrict__ pph,
                const __half* __restrict__ vth, __half* __restrict__ Ch) {
    extern __shared__ char sm[];
    uint32_t dbase = smem_u32(sm);
    float* S = (float*)sm;
    int z = blockIdx.y, q0 = blockIdx.x * 48;
    int tid = threadIdx.x, lane = tid & 31, w = tid >> 5;
    int wn = w << 4;
    int bq = lane & 3, bg = lane >> 2;

    // load QU (64 rows, clamped)
    for (int i = tid; i < 512; i += 256) {
        int r = i >> 3, c = i & 7;
        int gq = q0 + r; if (gq >= TP) gq = q0;
        cp16(dbase + FS_Q + r * 144 + c * 16, quh + ((long)z * TP + gq) * 64 + c * 8);
    }
    CP_COMMIT();

    // ---- phase 1: content scores -> S ----
#pragma unroll 1
    for (int c = 0; c < 3; c++) {
        for (int i = tid; i < 1024; i += 256) {
            int r = i >> 3, cc = i & 7;
            cp16(dbase + FS_B + r * 144 + cc * 16,
                 kkh + ((long)z * TP + c * 128 + r) * 64 + cc * 8);
        }
        CP_COMMIT(); CP_WAIT0(); __syncthreads();
        float acc[3][2][4];
#pragma unroll
        for (int a = 0; a < 3; a++)
#pragma unroll
            for (int b = 0; b < 2; b++)
#pragma unroll
                for (int e = 0; e < 4; e++) acc[a][b][e] = 0.0f;
#pragma unroll
        for (int k16 = 0; k16 < 4; k16++) {
            int kb = k16 * 32 + bq * 4;
            uint32_t bh[2][2];
#pragma unroll
            for (int ni = 0; ni < 2; ni++) {
                const char* pb = sm + FS_B + (wn + ni * 8 + bg) * 144 + kb;
                bh[ni][0] = *(const uint32_t*)pb;
                bh[ni][1] = *(const uint32_t*)(pb + 16);
            }
#pragma unroll
            for (int mi = 0; mi < 3; mi++) {
                const char* pa = sm + FS_Q + (mi * 16 + bg) * 144 + kb;
                uint32_t ah[4];
                ah[0] = *(const uint32_t*)pa;
                ah[1] = *(const uint32_t*)(pa + 8 * 144);
                ah[2] = *(const uint32_t*)(pa + 16);
                ah[3] = *(const uint32_t*)(pa + 8 * 144 + 16);
#pragma unroll
                for (int ni = 0; ni < 2; ni++)
                    mma16816(acc[mi][ni], ah, bh[ni]);
            }
        }
#pragma unroll
        for (int mi = 0; mi < 3; mi++)
#pragma unroll
            for (int half = 0; half < 2; half++) {
                int r = mi * 16 + bg + half * 8;
#pragma unroll
                for (int ni = 0; ni < 2; ni++) {
                    int col = c * 128 + wn + ni * 8 + bq * 2;
                    S[r * FS_PITCH + col]     = acc[mi][ni][half * 2 + 0];
                    S[r * FS_PITCH + col + 1] = acc[mi][ni][half * 2 + 1];
                }
            }
        __syncthreads();
    }

    // reload Q buffer with QV
    for (int i = tid; i < 512; i += 256) {
        int r = i >> 3, c = i & 7;
        int gq = q0 + r; if (gq >= TP) gq = q0;
        cp16(dbase + FS_Q + r * 144 + c * 16, qvh + ((long)z * TP + gq) * 64 + c * 8);
    }
    CP_COMMIT();

    // ---- phase 2: pos scores + rel-shift scatter (bijection, plain +=) ----
#pragma unroll 1
    for (int c = 0; c < 3; c++) {
        for (int i = tid; i < 1024; i += 256) {
            int r = i >> 3, cc = i & 7;
            cp16(dbase + FS_B + r * 144 + cc * 16,
                 pph + ((long)z * TP + c * 128 + r) * 64 + cc * 8);
        }
        CP_COMMIT(); CP_WAIT0(); __syncthreads();
        float acc[4][2][4];
#pragma unroll
        for (int a = 0; a < 4; a++)
#pragma unroll
            for (int b = 0; b < 2; b++)
#pragma unroll
                for (int e = 0; e < 4; e++) acc[a][b][e] = 0.0f;
#pragma unroll
        for (int k16 = 0; k16 < 4; k16++) {
            int kb = k16 * 32 + bq * 4;
            uint32_t bh[2][2];
#pragma unroll
            for (int ni = 0; ni < 2; ni++) {
                const char* pb = sm + FS_B + (wn + ni * 8 + bg) * 144 + kb;
                bh[ni][0] = *(const uint32_t*)pb;
                bh[ni][1] = *(const uint32_t*)(pb + 16);
            }
#pragma unroll
            for (int mi = 0; mi < 4; mi++) {
                const char* pa = sm + FS_Q + (mi * 16 + bg) * 144 + kb;
                uint32_t ah[4];
                ah[0] = *(const uint32_t*)pa;
                ah[1] = *(const uint32_t*)(pa + 8 * 144);
                ah[2] = *(const uint32_t*)(pa + 16);
                ah[3] = *(const uint32_t*)(pa + 8 * 144 + 16);
#pragma unroll
                for (int ni = 0; ni < 2; ni++)
                    mma16816(acc[mi][ni], ah, bh[ni]);
            }
        }
#pragma unroll
        for (int mi = 0; mi < 4; mi++)
#pragma unroll
            for (int half = 0; half < 2; half++) {
                int r = mi * 16 + bg + half * 8;
                if (r > 48) continue;
                int rp = q0 + r;
#pragma unroll
                for (int ni = 0; ni < 2; ni++)
#pragma unroll
                    for (int e = 0; e < 2; e++) {
                        int jj = c * 128 + wn + ni * 8 + bq * 2 + e;
                        if (jj >= TT) continue;
                        float v = acc[mi][ni][half * 2 + e];
                        if (jj >= 350 - rp) {
                            if (r < 48) S[r * FS_PITCH + jj - 350 + rp] += v;
                        } else if (r >= 1) {
                            S[(r - 1) * FS_PITCH + jj + rp + 1] += v;
                        }
                    }
            }
        __syncthreads();
    }

    // ---- softmax -> fp16 A tile in smem (fully convergent; garbage rows are
    //      computed too — their outputs are discarded by the gq<TT store guard) ----
    if (tid < 192) {
        int r = tid >> 2, qu = tid & 3;
        const float scale = 0.044194173824159216f;
        float* Srow = S + r * FS_PITCH;
        char* Arow = sm + AF_A + r * AF_PITCH;
        int c0 = qu * 96;
        float mx = -1e30f;
        for (int cc = c0; cc < c0 + 96; cc++)
            if (cc < TT) mx = fmaxf(mx, Srow[cc]);
        mx = fmaxf(mx, __shfl_xor_sync(0xffffffffu, mx, 1));
        mx = fmaxf(mx, __shfl_xor_sync(0xffffffffu, mx, 2));
        float mxs = mx * scale;
        float sum = 0.0f;
        for (int cc = c0; cc < c0 + 96; cc++)
            if (cc < TT) {
                float e = __expf(Srow[cc] * scale - mxs);
                Srow[cc] = e;
                sum += e;
            }
        sum += __shfl_xor_sync(0xffffffffu, sum, 1);
        sum += __shfl_xor_sync(0xffffffffu, sum, 2);
        float inv = 1.0f / sum;
        for (int cc = c0; cc < c0 + 96; cc += 2) {
            float v0 = (cc < TT)     ? Srow[cc] * inv     : 0.0f;
            float v1 = (cc + 1 < TT) ? Srow[cc + 1] * inv : 0.0f;
            *(uint32_t*)(Arow + cc * 2) = packh(v0, v1);
        }
    }
    __syncthreads();

    // ---- load V tile (64 x 384 fp16, pitch 784) over dead score region ----
    for (int i = tid; i < 3072; i += 256) {
        int d = i / 48, c16 = i - d * 48;
        cp16(dbase + d * AF_PITCH + c16 * 16,
             vth + ((long)z * 64 + d) * TP + c16 * 8);
    }
    CP_COMMIT(); CP_WAIT0(); __syncthreads();

    // ---- ctx GEMM: out[48 x 64] = A[48 x 384] @ V^T, 6 warps ----
    if (w < 6) {
        int wr = w % 3, wc = w / 3;
        float acc[4][4];
#pragma unroll
        for (int a = 0; a < 4; a++)
#pragma unroll
            for (int e = 0; e < 4; e++) acc[a][e] = 0.0f;
#pragma unroll 1
        for (int k16 = 0; k16 < 24; k16++) {
            int kb = k16 * 32 + bq * 4;
            const char* pa = sm + AF_A + (wr * 16 + bg) * AF_PITCH + kb;
            uint32_t ah[4];
            ah[0] = *(const uint32_t*)pa;
            ah[1] = *(const uint32_t*)(pa + 8 * AF_PITCH);
            ah[2] = *(const uint32_t*)(pa + 16);
            ah[3] = *(const uint32_t*)(pa + 8 * AF_PITCH + 16);
#pragma unroll
            for (int ni = 0; ni < 4; ni++) {
                const char* pb = sm + (wc * 32 + ni * 8 + bg) * AF_PITCH + kb;
                uint32_t bh[2];
                bh[0] = *(const uint32_t*)pb;
                bh[1] = *(const uint32_t*)(pb + 16);
                mma16816(acc[ni], ah, bh);
            }
        }
        int b = z >> 3, h = z & 7;
#pragma unroll
        for (int half = 0; half < 2; half++) {
            int gq = q0 + wr * 16 + bg + half * 8;
            if (gq >= TT) continue;
#pragma unroll
            for (int ni = 0; ni < 4; ni++) {
                int col = wc * 32 + ni * 8 + bq * 2;
                long addr = ((long)(b * 351 + gq)) * DD + h * 64 + col;
                *(uint32_t*)(Ch + addr) = packh(acc[ni][half * 2], acc[ni][half * 2 + 1]);
            }
        }
    }
}

// ---------------- add pos-emb + LayerNorm --------------------------------------------
template<bool F16O>
__global__ void addln_kernel(const float* __restrict__ xin, float* __restrict__ xupd,
                             const float* __restrict__ pe,
                             const float* __restrict__ ga, const float* __restrict__ gb,
                             float* __restrict__ out, __half* __restrict__ ohi) {
    int row = blockIdx.x;
    int t   = row % TT;
    const float* xr = xin + (size_t)row * DD;
    int tid = threadIdx.x;
    float vals[4];
#pragma unroll
    for (int i = 0; i < 4; i++) {
        int c = tid + i * 128;
        float vv = xr[c];
        if (pe) vv += pe[(size_t)t * DD + c];
        vals[i] = vv;
    }
    if (pe) {
        float* xw = xupd + (size_t)row * DD;
#pragma unroll
        for (int i = 0; i < 4; i++) xw[tid + i * 128] = vals[i];
    }
    __shared__ float sh[4];
    float s = vals[0] + vals[1] + vals[2] + vals[3];
#pragma unroll
    for (int o = 16; o > 0; o >>= 1) s += __shfl_xor_sync(0xffffffffu, s, o);
    if ((tid & 31) == 0) sh[tid >> 5] = s;
    __syncthreads();
    float mean = (sh[0] + sh[1] + sh[2] + sh[3]) * (1.0f / DD);
    __syncthreads();
    float sq = 0.0f;
#pragma unroll
    for (int i = 0; i < 4; i++) { float d = vals[i] - mean; sq += d * d; }
#pragma unroll
    for (int o = 16; o > 0; o >>= 1) sq += __shfl_xor_sync(0xffffffffu, sq, o);
    if ((tid & 31) == 0) sh[tid >> 5] = sq;
    __syncthreads();
    float var  = sh[0] + sh[1] + sh[2] + sh[3];
    float stdv = sqrtf(var * (1.0f / (DD - 1)));
    float inv  = 1.0f / (stdv + 1e-6f);
#pragma unroll
    for (int i = 0; i < 4; i++) {
        int c = tid + i * 128;
        float v = ga[c] * (vals[i] - mean) * inv + gb[c];
        if (F16O) ohi[(size_t)row * DD + c] = __float2half_rn(v);
        else      out[(size_t)row * DD + c] = v;
    }
}

// ------------------------------------ launch -----------------------------------------
extern "C" void kernel_launch(void* const* d_in, const int* in_sizes, int n_in,
                              void* d_out, int out_size) {
    const float* X0  = (const float*)d_in[0];
    const float* MSK = (const float*)d_in[1];
    const float* PE  = (const float*)d_in[2];
    const float* Wq  = (const float*)d_in[3];
    const float* bq  = (const float*)d_in[4];
    const float* Wk  = (const float*)d_in[5];
    const float* bk  = (const float*)d_in[6];
    const float* Wv  = (const float*)d_in[7];
    const float* bv  = (const float*)d_in[8];
    const float* Wp  = (const float*)d_in[9];
    const float* Ub  = (const float*)d_in[10];
    const float* Vb  = (const float*)d_in[11];
    const float* Wo  = (const float*)d_in[12];
    const float* bo  = (const float*)d_in[13];
    const float* l1a = (const float*)d_in[14];
    const float* l1b = (const float*)d_in[15];
    const float* l2a = (const float*)d_in[16];
    const float* l2b = (const float*)d_in[17];
    const float* W1  = (const float*)d_in[18];
    const float* b1  = (const float*)d_in[19];
    const float* W2  = (const float*)d_in[20];
    const float* b2  = (const float*)d_in[21];
    const float* fna = (const float*)d_in[22];
    const float* fnb = (const float*)d_in[23];
    float* x = (float*)d_out;

    __half *quh, *qvh, *kkh, *pph, *vth;
    __half *xnh, *mkh, *cxh, *hph;
    __half *wqh, *wkh, *wvh, *wph, *woh, *w1h, *w2h;
    cudaGetSymbolAddress((void**)&quh, g_quh); cudaGetSymbolAddress((void**)&qvh, g_qvh);
    cudaGetSymbolAddress((void**)&kkh, g_kkh); cudaGetSymbolAddress((void**)&pph, g_pph);
    cudaGetSymbolAddress((void**)&vth, g_vth);
    cudaGetSymbolAddress((void**)&xnh, g_xnh); cudaGetSymbolAddress((void**)&mkh, g_mkh);
    cudaGetSymbolAddress((void**)&cxh, g_cxh); cudaGetSymbolAddress((void**)&hph, g_hph);
    cudaGetSymbolAddress((void**)&wqh, g_wqh); cudaGetSymbolAddress((void**)&wkh, g_wkh);
    cudaGetSymbolAddress((void**)&wvh, g_wvh); cudaGetSymbolAddress((void**)&wph, g_wph);
    cudaGetSymbolAddress((void**)&woh, g_woh);
    cudaGetSymbolAddress((void**)&w1h, g_w1h); cudaGetSymbolAddress((void**)&w2h, g_w2h);

    cudaFuncSetAttribute(hmma_gemm<1, true,  false, 0>, cudaFuncAttributeMaxDynamicSharedMemorySize, SMEMSZ);
    cudaFuncSetAttribute(hmma_gemm<3, true,  false, 0>, cudaFuncAttributeMaxDynamicSharedMemorySize, SMEMSZ);
    cudaFuncSetAttribute(hmma_gemm<1, false, true,  1>, cudaFuncAttributeMaxDynamicSharedMemorySize, SMEMSZ);
    cudaFuncSetAttribute(hmma_gemm<1, false, false, 2>, cudaFuncAttributeMaxDynamicSharedMemorySize, SMEMSZ);
    cudaFuncSetAttribute(hmma_gemm<1, false, false, 3>, cudaFuncAttributeMaxDynamicSharedMemorySize, SMEMSZ);
    cudaFuncSetAttribute(hmma_gemm<1, false, false, 4>, cudaFuncAttributeMaxDynamicSharedMemorySize, SMEMSZ);
    cudaFuncSetAttribute(attn_fused, cudaFuncAttributeMaxDynamicSharedMemorySize, FS_TOT);

    int nW = 3 * DD * DD / 4;
    Ptr5 p5; p5.s0 = Wq; p5.s1 = Wk; p5.s2 = Wv; p5.s3 = Wp; p5.s4 = Wo;
    cvt5<<<dim3((nW + 255) / 256, 5), 256>>>(p5, wqh, wkh, wvh, wph, woh, nW);
    int n1 = 3 * DFFX * DD / 4;
    cvt_half<<<(n1 + 255) / 256, 256>>>(W1, w1h, n1);
    int nM = BT * DD / 4;
    cvt_half<<<(nM + 255) / 256, 256>>>(MSK, mkh, nM);
    int n2 = 3 * 3 * DD * DFFX;
    cvt_w2<<<(n2 + 255) / 256, 256>>>(W2, w2h);

    dim3 gP(4, MP / 128);
    dim3 gF(8, MP / 128);
    dim3 gAt(8, ZZ);

    for (int i = 0; i < 3; i++) {
        size_t oD = (size_t)i * DD, oDD = (size_t)i * DD * DD;
        addln_kernel<true><<<BT, 128>>>(i == 0 ? X0 : x, x, PE + (size_t)i * TT * DD,
                                        l1a + oD, l1b + oD, nullptr, xnh);
        hmma_gemm<1, false, false, 2><<<gP, 256, SMEMSZ>>>(
            xnh, wqh + oDD, bq + oD, Ub + oD, Vb + oD,
            nullptr, quh, qvh, BT, DD, DD);
        hmma_gemm<1, false, false, 3><<<gP, 256, SMEMSZ>>>(
            xnh, wkh + oDD, bk + oD, nullptr, nullptr,
            nullptr, kkh, nullptr, BT, DD, DD);
        hmma_gemm<1, false, false, 3><<<gP, 256, SMEMSZ>>>(
            mkh, wph + oDD, nullptr, nullptr, nullptr,
            nullptr, pph, nullptr, BT, DD, DD);
        hmma_gemm<1, false, false, 4><<<gP, 256, SMEMSZ>>>(
            xnh, wvh + oDD, bv + oD, nullptr, nullptr,
            nullptr, vth, nullptr, BT, DD, DD);
        attn_fused<<<gAt, 256, FS_TOT>>>(quh, qvh, kkh, pph, vth, cxh);
        hmma_gemm<1, true, false, 0><<<gP, 256, SMEMSZ>>>(
            cxh, woh + oDD, bo + oD, nullptr, nullptr,
            x, nullptr, nullptr, BT, DD, DD);
        addln_kernel<true><<<BT, 128>>>(x, nullptr, nullptr,
                                        l2a + oD, l2b + oD, nullptr, xnh);
        hmma_gemm<1, false, true, 1><<<gF, 256, SMEMSZ>>>(
            xnh, w1h + (size_t)i * DFFX * DD,
            b1 + (size_t)i * DFFX, nullptr, nullptr,
            nullptr, hph, nullptr, BT, DFFX, DD);
        hmma_gemm<3, true, false, 0><<<gP, 256, SMEMSZ>>>(
            hph, w2h + (size_t)i * 3 * DD * DFFX,
            b2 + oD, nullptr, nullptr,
            x, nullptr, nullptr, BT, DD, DFFX);
    }
    addln_kernel<false><<<BT, 128>>>(x, nullptr, nullptr, fna, fnb, x, nullptr);
}

// round 11
// speedup vs baseline: 5.6055x; 1.0027x over previous
#include <cuda_runtime.h>
#include <cuda_fp16.h>
#include <math.h>
#include <stdint.h>

#define BB   64
#define TT   351
#define DD   512
#define HH   8
#define DFFX 1024
#define BT   (BB*TT)       // 22464
#define MP   22528
#define HPR  22784
#define TP   384
#define ZZ   (BB*HH)       // 512
#define STAGE_BYTES 36864  // Ah 18432 + Bh 18432 (128 rows x 144B each)
#define SMEMSZ (3*STAGE_BYTES)

// fused-attention smem layout (bytes), q-block = 48 rows
#define FS_PITCH 392
#define AT_QU 75264               // 64 rows * 144B
#define AT_QV 84480
#define AT_B0 93696               // 64-row B chunk, double buffered
#define AT_B1 102912
#define AF_A  75264               // fp16 A tile 48 x pitch784 (over dead QU/QV/B)
#define AF_PITCH 784
#define FS_TOT 112896             // occ 2

// ---------------- scratch ------------------------------------------------------------
static __device__ __half g_quh[(size_t)ZZ*TP*64];
static __device__ __half g_qvh[(size_t)ZZ*TP*64];
static __device__ __half g_kkh[(size_t)ZZ*TP*64];
static __device__ __half g_pph[(size_t)ZZ*TP*64];
static __device__ __half g_vth[(size_t)ZZ*64*TP];
static __device__ __half g_xnh[MP*(size_t)DD];
static __device__ __half g_mkh[MP*(size_t)DD];
static __device__ __half g_cxh[MP*(size_t)DD];
static __device__ __half g_hph[(size_t)HPR*DFFX];
static __device__ __half g_wqh[3*DD*DD], g_wkh[3*DD*DD], g_wvh[3*DD*DD];
static __device__ __half g_wph[3*DD*DD], g_woh[3*DD*DD];
static __device__ __half g_w1h[3*DFFX*DD];
static __device__ __half g_w2h[3*3*DD*DFFX];

// ---------------- PTX helpers --------------------------------------------------------
__device__ __forceinline__ uint32_t smem_u32(const void* p) {
    uint32_t a;
    asm("{ .reg .u64 t; cvta.to.shared.u64 t, %1; cvt.u32.u64 %0, t; }" : "=r"(a) : "l"(p));
    return a;
}
__device__ __forceinline__ void cp16(uint32_t dst, const void* src) {
    asm volatile("cp.async.cg.shared.global [%0], [%1], 16;" :: "r"(dst), "l"(src) : "memory");
}
#define CP_COMMIT() asm volatile("cp.async.commit_group;" ::: "memory")
#define CP_WAIT2()  asm volatile("cp.async.wait_group 2;" ::: "memory")
#define CP_WAIT1()  asm volatile("cp.async.wait_group 1;" ::: "memory")
#define CP_WAIT0()  asm volatile("cp.async.wait_group 0;" ::: "memory")

__device__ __forceinline__ void mma16816(float* c, const uint32_t* a, const uint32_t* b) {
    asm volatile(
        "mma.sync.aligned.m16n8k16.row.col.f32.f16.f16.f32 "
        "{%0,%1,%2,%3}, {%4,%5,%6,%7}, {%8,%9}, {%0,%1,%2,%3};"
        : "+f"(c[0]), "+f"(c[1]), "+f"(c[2]), "+f"(c[3])
        : "r"(a[0]), "r"(a[1]), "r"(a[2]), "r"(a[3]), "r"(b[0]), "r"(b[1]));
}
__device__ __forceinline__ void ldsm4(uint32_t* r, uint32_t addr) {
    asm volatile("ldmatrix.sync.aligned.m8n8.x4.shared.b16 {%0,%1,%2,%3}, [%4];"
        : "=r"(r[0]), "=r"(r[1]), "=r"(r[2]), "=r"(r[3]) : "r"(addr));
}
__device__ __forceinline__ uint32_t packh(float a, float b) {
    __half2 h = __floats2half2_rn(a, b);
    return *reinterpret_cast<uint32_t*>(&h);
}

// ---------------- conversion kernels -------------------------------------------------
struct Ptr5 { const float* s0; const float* s1; const float* s2; const float* s3; const float* s4; };
__global__ void cvt5(Ptr5 p, __half* d0, __half* d1, __half* d2, __half* d3, __half* d4, int n4) {
    int i = blockIdx.x * 256 + threadIdx.x;
    if (i >= n4) return;
    const float* s; __half* d;
    switch (blockIdx.y) {
        case 0: s = p.s0; d = d0; break;
        case 1: s = p.s1; d = d1; break;
        case 2: s = p.s2; d = d2; break;
        case 3: s = p.s3; d = d3; break;
        default: s = p.s4; d = d4; break;
    }
    float4 v = ((const float4*)s)[i];
    uint2 st; st.x = packh(v.x, v.y); st.y = packh(v.z, v.w);
    ((uint2*)d)[i] = st;
}
__global__ void cvt_half(const float* __restrict__ in, __half* __restrict__ out, int n4) {
    int i = blockIdx.x * 256 + threadIdx.x;
    if (i >= n4) return;
    float4 v = ((const float4*)in)[i];
    uint2 st; st.x = packh(v.x, v.y); st.y = packh(v.z, v.w);
    ((uint2*)out)[i] = st;
}
// W2 in: [l][n][k][s] -> out [l][s][n][k]
__global__ void cvt_w2(const float* __restrict__ in, __half* __restrict__ hi) {
    int idx = blockIdx.x * 256 + threadIdx.x;
    const int per_l = 3 * DD * DFFX;
    if (idx >= 3 * per_l) return;
    int l = idx / per_l; int r = idx - l * per_l;
    int s = r / (DD * DFFX); int r2 = r - s * (DD * DFFX);
    int n = r2 / DFFX; int k2 = r2 - n * DFFX;
    hi[idx] = __float2half_rn(in[(((size_t)l * DD + n) * DFFX + k2) * 3 + s]);
}

// ---------------- HMMA 1-term fp16 GEMM, K-chunk 64, 3-stage pipeline ----------------
// MODE 0: fp32 C (+ACC). MODE 1: fp16 padded-H remap (FF1). MODE 2: dual head-major.
// MODE 3: single head-major. MODE 4: transposed head-major.
template<int TAPS, bool ACC, bool RELU, int MODE>
__global__ __launch_bounds__(256, 2)
void hmma_gemm(const __half* __restrict__ Ahi, const __half* __restrict__ Bhi,
               const float* __restrict__ bias, const float* __restrict__ bias2,
               const float* __restrict__ bias3,
               float* __restrict__ Cf,
               __half* __restrict__ O1h, __half* __restrict__ O2h,
               int Mstore, int N, int K) {
    extern __shared__ char sm[];
    uint32_t dbase = smem_u32(sm);
    int tid = threadIdx.x, lane = tid & 31, w = tid >> 5;
    int wm = (w & 1) << 6, wn = (w >> 1) << 5;
    int bm = blockIdx.y << 7, bn = blockIdx.x << 7;

    uint32_t so[4]; long ga[4], gb[4];
#pragma unroll
    for (int j = 0; j < 4; j++) {
        int idx = tid + 256 * j; int row = idx >> 3, c16 = idx & 7;
        so[j] = row * 144 + c16 * 16;
        int grow = bm + row;
        long arow;
        if (TAPS == 3) { int b = grow / 351; int t = grow - b * 351; arow = (long)b * 353 + t; }
        else arow = grow;
        ga[j] = arow * (long)K + c16 * 8;
        gb[j] = (long)(bn + row) * K + c16 * 8;
    }
    const int kch = K >> 6;
    const int nch = TAPS * kch;

#define LOAD_CHUNK(c, stg) do { \
        int s_ = (c) / kch; int kb_ = ((c) - s_ * kch) << 6; \
        long sK_ = (TAPS == 3) ? (long)s_ * K : 0; \
        long sNK_ = (TAPS == 3) ? (long)s_ * N * K : 0; \
        uint32_t sb_ = dbase + (stg) * STAGE_BYTES; \
        _Pragma("unroll") \
        for (int j = 0; j < 4; j++) { \
            cp16(sb_ + so[j],         Ahi + sK_ + ga[j] + kb_); \
            cp16(sb_ + 18432 + so[j], Bhi + sNK_ + gb[j] + kb_); \
        } \
    } while (0)

    float acc[4][4][4];
#pragma unroll
    for (int a = 0; a < 4; a++)
#pragma unroll
        for (int b = 0; b < 4; b++)
#pragma unroll
            for (int q2 = 0; q2 < 4; q2++) acc[a][b][q2] = 0.0f;

    int bq = lane & 3, bg = lane >> 2;
    uint32_t aoff = (uint32_t)(wm + (lane & 15)) * 144 + (uint32_t)(((lane >> 4) & 1) << 4);
    uint32_t boff = 18432u + (uint32_t)(wn + ((lane >> 4) << 3) + (lane & 7)) * 144
                  + (uint32_t)(((lane >> 3) & 1) << 4);

    LOAD_CHUNK(0, 0);
    CP_COMMIT();
    LOAD_CHUNK(1, 1);
    CP_COMMIT();
#pragma unroll 1
    for (int c = 0; c < nch; c++) {
        if (c + 2 < nch) LOAD_CHUNK(c + 2, (c + 2) % 3);
        CP_COMMIT();
        CP_WAIT2();
        __syncthreads();
        uint32_t sb = dbase + (c % 3) * STAGE_BYTES;
#pragma unroll
        for (int k16 = 0; k16 < 4; k16++) {
            uint32_t kof = k16 * 32;
            uint32_t bh[4][2], t[4];
            ldsm4(t, sb + boff + kof);
            bh[0][0] = t[0]; bh[0][1] = t[1]; bh[1][0] = t[2]; bh[1][1] = t[3];
            ldsm4(t, sb + boff + 2304 + kof);
            bh[2][0] = t[0]; bh[2][1] = t[1]; bh[3][0] = t[2]; bh[3][1] = t[3];
#pragma unroll
            for (int mi = 0; mi < 4; mi++) {
                uint32_t ah[4];
                ldsm4(ah, sb + aoff + mi * 2304 + kof);
#pragma unroll
                for (int ni = 0; ni < 4; ni++)
                    mma16816(acc[mi][ni], ah, bh[ni]);
            }
        }
        __syncthreads();
    }
#undef LOAD_CHUNK

#pragma unroll
    for (int mi = 0; mi < 4; mi++) {
#pragma unroll
        for (int half = 0; half < 2; half++) {
            int m = bm + wm + mi * 16 + bg + half * 8;
            if (m >= Mstore) continue;
            int b = 0, t = 0; long crow = m;
            if (MODE == 1) { b = m / 351; t = m - b * 351; crow = (long)b * 353 + 1 + t; }
            if (MODE >= 2) { b = m / 351; t = m - b * 351; }
#pragma unroll
            for (int ni = 0; ni < 4; ni++) {
                int col = bn + wn + ni * 8 + bq * 2;
                float v0 = acc[mi][ni][half * 2 + 0];
                float v1 = acc[mi][ni][half * 2 + 1];
                if (bias) { v0 += bias[col]; v1 += bias[col + 1]; }
                if (RELU) { v0 = fmaxf(v0, 0.0f); v1 = fmaxf(v1, 0.0f); }
                if (MODE == 0) {
                    float* cp = Cf + (long)m * N + col;
                    if (ACC) { v0 += cp[0]; v1 += cp[1]; }
                    float2 st; st.x = v0; st.y = v1;
                    *(float2*)cp = st;
                } else if (MODE == 1) {
                    *(uint32_t*)(O1h + crow * (long)N + col) = packh(v0, v1);
                } else if (MODE == 2 || MODE == 3) {
                    int h = col >> 6, d = col & 63;
                    long base = ((long)(b * 8 + h) * TP + t) * 64 + d;
                    float u0 = v0, u1 = v1;
                    if (bias2) { u0 += bias2[col]; u1 += bias2[col + 1]; }
                    *(uint32_t*)(O1h + base) = packh(u0, u1);
                    if (MODE == 2) {
                        float w0 = v0 + bias3[col], w1 = v1 + bias3[col + 1];
                        *(uint32_t*)(O2h + base) = packh(w0, w1);
                    }
                } else { // MODE 4: transposed
                    int h = col >> 6, d = col & 63;
                    O1h[((long)(b * 8 + h) * 64 + d) * TP + t]     = __float2half_rn(v0);
                    O1h[((long)(b * 8 + h) * 64 + d + 1) * TP + t] = __float2half_rn(v1);
                }
            }
        }
    }
}

// ---------------- fully fused attention, pipelined 64-row B chunks -------------------
__global__ __launch_bounds__(256, 2)
void attn_fused(const __half* __restrict__ quh, const __half* __restrict__ qvh,
                const __half* __restrict__ kkh, const __half* __restrict__ pph,
                const __half* __restrict__ vth, __half* __restrict__ Ch) {
    extern __shared__ char sm[];
    uint32_t dbase = smem_u32(sm);
    float* S = (float*)sm;
    int z = blockIdx.y, q0 = blockIdx.x * 48;
    int tid = threadIdx.x, lane = tid & 31, w = tid >> 5;
    int cb = w << 3;                  // 8 cols per warp
    int bq = lane & 3, bg = lane >> 2;

    // group 0: QU + QV (64 rows each, clamped) + B chunk 0 (kk rows 0..63)
    for (int i = tid; i < 512; i += 256) {
        int r = i >> 3, c = i & 7;
        int gq = q0 + r; if (gq >= TP) gq = q0;
        cp16(dbase + AT_QU + r * 144 + c * 16, quh + ((long)z * TP + gq) * 64 + c * 8);
        cp16(dbase + AT_QV + r * 144 + c * 16, qvh + ((long)z * TP + gq) * 64 + c * 8);
        cp16(dbase + AT_B0 + r * 144 + c * 16, kkh + ((long)z * TP + r) * 64 + c * 8);
    }
    CP_COMMIT();
    CP_WAIT0();
    __syncthreads();

    // hoist A fragments (QU) into registers: afr[mi][k16][0..3]
    uint32_t afr[4][4][4];
#pragma unroll
    for (int mi = 0; mi < 3; mi++)
#pragma unroll
        for (int k16 = 0; k16 < 4; k16++) {
            const char* pa = sm + AT_QU + (mi * 16 + bg) * 144 + k16 * 32 + bq * 4;
            afr[mi][k16][0] = *(const uint32_t*)pa;
            afr[mi][k16][1] = *(const uint32_t*)(pa + 8 * 144);
            afr[mi][k16][2] = *(const uint32_t*)(pa + 16);
            afr[mi][k16][3] = *(const uint32_t*)(pa + 8 * 144 + 16);
        }

#pragma unroll 1
    for (int ch = 0; ch < 12; ch++) {
        if (ch + 1 < 12) {
            const __half* src = (ch + 1 < 6) ? kkh : pph;
            int rows0 = ((ch + 1) % 6) * 64;
            uint32_t bb = ((ch + 1) & 1) ? AT_B1 : AT_B0;
            for (int i = tid; i < 512; i += 256) {
                int r = i >> 3, c = i & 7;
                cp16(dbase + bb + r * 144 + c * 16,
                     src + ((long)z * TP + rows0 + r) * 64 + c * 8);
            }
        }
        CP_COMMIT();
        CP_WAIT1();
        __syncthreads();
        if (ch == 6) {   // switch A fragments to QV (QV smem untouched)
#pragma unroll
            for (int mi = 0; mi < 4; mi++)
#pragma unroll
                for (int k16 = 0; k16 < 4; k16++) {
                    const char* pa = sm + AT_QV + (mi * 16 + bg) * 144 + k16 * 32 + bq * 4;
                    afr[mi][k16][0] = *(const uint32_t*)pa;
                    afr[mi][k16][1] = *(const uint32_t*)(pa + 8 * 144);
                    afr[mi][k16][2] = *(const uint32_t*)(pa + 16);
                    afr[mi][k16][3] = *(const uint32_t*)(pa + 8 * 144 + 16);
                }
        }
        uint32_t bb = (ch & 1) ? AT_B1 : AT_B0;
        int col0 = (ch % 6) * 64;
        if (ch < 6) {
            float acc[3][4];
#pragma unroll
            for (int a = 0; a < 3; a++)
#pragma unroll
                for (int e = 0; e < 4; e++) acc[a][e] = 0.0f;
#pragma unroll
            for (int k16 = 0; k16 < 4; k16++) {
                const char* pb = sm + bb + (cb + bg) * 144 + k16 * 32 + bq * 4;
                uint32_t bh[2];
                bh[0] = *(const uint32_t*)pb;
                bh[1] = *(const uint32_t*)(pb + 16);
#pragma unroll
                for (int mi = 0; mi < 3; mi++)
                    mma16816(acc[mi], afr[mi][k16], bh);
            }
#pragma unroll
            for (int mi = 0; mi < 3; mi++)
#pragma unroll
                for (int half = 0; half < 2; half++) {
                    int r = mi * 16 + bg + half * 8;
                    int col = col0 + cb + bq * 2;
                    S[r * FS_PITCH + col]     = acc[mi][half * 2 + 0];
                    S[r * FS_PITCH + col + 1] = acc[mi][half * 2 + 1];
                }
        } else {
            float acc[4][4];
#pragma unroll
            for (int a = 0; a < 4; a++)
#pragma unroll
                for (int e = 0; e < 4; e++) acc[a][e] = 0.0f;
#pragma unroll
            for (int k16 = 0; k16 < 4; k16++) {
                const char* pb = sm + bb + (cb + bg) * 144 + k16 * 32 + bq * 4;
                uint32_t bh[2];
                bh[0] = *(const uint32_t*)pb;
                bh[1] = *(const uint32_t*)(pb + 16);
#pragma unroll
                for (int mi = 0; mi < 4; mi++)
                    mma16816(acc[mi], afr[mi][k16], bh);
            }
#pragma unroll
            for (int mi = 0; mi < 4; mi++)
#pragma unroll
                for (int half = 0; half < 2; half++) {
                    int r = mi * 16 + bg + half * 8;
                    if (r > 48) continue;
                    int rp = q0 + r;
#pragma unroll
                    for (int e = 0; e < 2; e++) {
                        int jj = col0 + cb + bq * 2 + e;
                        if (jj >= TT) continue;
                        float v = acc[mi][half * 2 + e];
                        if (jj >= 350 - rp) {
                            if (r < 48) S[r * FS_PITCH + jj - 350 + rp] += v;
                        } else if (r >= 1) {
                            S[(r - 1) * FS_PITCH + jj + rp + 1] += v;
                        }
                    }
                }
        }
        __syncthreads();
    }

    // ---- softmax -> fp16 A tile in smem (fully convergent) ----
    if (tid < 192) {
        int r = tid >> 2, qu = tid & 3;
        const float scale = 0.044194173824159216f;
        float* Srow = S + r * FS_PITCH;
        char* Arow = sm + AF_A + r * AF_PITCH;
        int c0 = qu * 96;
        float mx = -1e30f;
        for (int cc = c0; cc < c0 + 96; cc++)
            if (cc < TT) mx = fmaxf(mx, Srow[cc]);
        mx = fmaxf(mx, __shfl_xor_sync(0xffffffffu, mx, 1));
        mx = fmaxf(mx, __shfl_xor_sync(0xffffffffu, mx, 2));
        float mxs = mx * scale;
        float sum = 0.0f;
        for (int cc = c0; cc < c0 + 96; cc++)
            if (cc < TT) {
                float e = __expf(Srow[cc] * scale - mxs);
                Srow[cc] = e;
                sum += e;
            }
        sum += __shfl_xor_sync(0xffffffffu, sum, 1);
        sum += __shfl_xor_sync(0xffffffffu, sum, 2);
        float inv = 1.0f / sum;
        for (int cc = c0; cc < c0 + 96; cc += 2) {
            float v0 = (cc < TT)     ? Srow[cc] * inv     : 0.0f;
            float v1 = (cc + 1 < TT) ? Srow[cc + 1] * inv : 0.0f;
            *(uint32_t*)(Arow + cc * 2) = packh(v0, v1);
        }
    }
    __syncthreads();

    // ---- load V tile (64 x 384 fp16, pitch 784) over dead score region ----
    for (int i = tid; i < 3072; i += 256) {
        int d = i / 48, c16 = i - d * 48;
        cp16(dbase + d * AF_PITCH + c16 * 16,
             vth + ((long)z * 64 + d) * TP + c16 * 8);
    }
    CP_COMMIT(); CP_WAIT0(); __syncthreads();

    // ---- ctx GEMM: out[48 x 64] = A[48 x 384] @ V^T, 6 warps ----
    if (w < 6) {
        int wr = w % 3, wc = w / 3;
        float acc[4][4];
#pragma unroll
        for (int a = 0; a < 4; a++)
#pragma unroll
            for (int e = 0; e < 4; e++) acc[a][e] = 0.0f;
#pragma unroll 1
        for (int k16 = 0; k16 < 24; k16++) {
            int kb = k16 * 32 + bq * 4;
            const char* pa = sm + AF_A + (wr * 16 + bg) * AF_PITCH + kb;
            uint32_t ah[4];
            ah[0] = *(const uint32_t*)pa;
            ah[1] = *(const uint32_t*)(pa + 8 * AF_PITCH);
            ah[2] = *(const uint32_t*)(pa + 16);
            ah[3] = *(const uint32_t*)(pa + 8 * AF_PITCH + 16);
#pragma unroll
            for (int ni = 0; ni < 4; ni++) {
                const char* pb = sm + (wc * 32 + ni * 8 + bg) * AF_PITCH + kb;
                uint32_t bh[2];
                bh[0] = *(const uint32_t*)pb;
                bh[1] = *(const uint32_t*)(pb + 16);
                mma16816(acc[ni], ah, bh);
            }
        }
        int b = z >> 3, h = z & 7;
#pragma unroll
        for (int half = 0; half < 2; half++) {
            int gq = q0 + wr * 16 + bg + half * 8;
            if (gq >= TT) continue;
#pragma unroll
            for (int ni = 0; ni < 4; ni++) {
                int col = wc * 32 + ni * 8 + bq * 2;
                long addr = ((long)(b * 351 + gq)) * DD + h * 64 + col;
                *(uint32_t*)(Ch + addr) = packh(acc[ni][half * 2], acc[ni][half * 2 + 1]);
            }
        }
    }
}

// ---------------- add pos-emb + LayerNorm --------------------------------------------
template<bool F16O>
__global__ void addln_kernel(const float* __restrict__ xin, float* __restrict__ xupd,
                             const float* __restrict__ pe,
                             const float* __restrict__ ga, const float* __restrict__ gb,
                             float* __restrict__ out, __half* __restrict__ ohi) {
    int row = blockIdx.x;
    int t   = row % TT;
    const float* xr = xin + (size_t)row * DD;
    int tid = threadIdx.x;
    float vals[4];
#pragma unroll
    for (int i = 0; i < 4; i++) {
        int c = tid + i * 128;
        float vv = xr[c];
        if (pe) vv += pe[(size_t)t * DD + c];
        vals[i] = vv;
    }
    if (pe) {
        float* xw = xupd + (size_t)row * DD;
#pragma unroll
        for (int i = 0; i < 4; i++) xw[tid + i * 128] = vals[i];
    }
    __shared__ float sh[4];
    float s = vals[0] + vals[1] + vals[2] + vals[3];
#pragma unroll
    for (int o = 16; o > 0; o >>= 1) s += __shfl_xor_sync(0xffffffffu, s, o);
    if ((tid & 31) == 0) sh[tid >> 5] = s;
    __syncthreads();
    float mean = (sh[0] + sh[1] + sh[2] + sh[3]) * (1.0f / DD);
    __syncthreads();
    float sq = 0.0f;
#pragma unroll
    for (int i = 0; i < 4; i++) { float d = vals[i] - mean; sq += d * d; }
#pragma unroll
    for (int o = 16; o > 0; o >>= 1) sq += __shfl_xor_sync(0xffffffffu, sq, o);
    if ((tid & 31) == 0) sh[tid >> 5] = sq;
    __syncthreads();
    float var  = sh[0] + sh[1] + sh[2] + sh[3];
    float stdv = sqrtf(var * (1.0f / (DD - 1)));
    float inv  = 1.0f / (stdv + 1e-6f);
#pragma unroll
    for (int i = 0; i < 4; i++) {
        int c = tid + i * 128;
        float v = ga[c] * (vals[i] - mean) * inv + gb[c];
        if (F16O) ohi[(size_t)row * DD + c] = __float2half_rn(v);
        else      out[(size_t)row * DD + c] = v;
    }
}

// ------------------------------------ launch -----------------------------------------
extern "C" void kernel_launch(void* const* d_in, const int* in_sizes, int n_in,
                              void* d_out, int out_size) {
    const float* X0  = (const float*)d_in[0];
    const float* MSK = (const float*)d_in[1];
    const float* PE  = (const float*)d_in[2];
    const float* Wq  = (const float*)d_in[3];
    const float* bq  = (const float*)d_in[4];
    const float* Wk  = (const float*)d_in[5];
    const float* bk  = (const float*)d_in[6];
    const float* Wv  = (const float*)d_in[7];
    const float* bv  = (const float*)d_in[8];
    const float* Wp  = (const float*)d_in[9];
    const float* Ub  = (const float*)d_in[10];
    const float* Vb  = (const float*)d_in[11];
    const float* Wo  = (const float*)d_in[12];
    const float* bo  = (const float*)d_in[13];
    const float* l1a = (const float*)d_in[14];
    const float* l1b = (const float*)d_in[15];
    const float* l2a = (const float*)d_in[16];
    const float* l2b = (const float*)d_in[17];
    const float* W1  = (const float*)d_in[18];
    const float* b1  = (const float*)d_in[19];
    const float* W2  = (const float*)d_in[20];
    const float* b2  = (const float*)d_in[21];
    const float* fna = (const float*)d_in[22];
    const float* fnb = (const float*)d_in[23];
    float* x = (float*)d_out;

    __half *quh, *qvh, *kkh, *pph, *vth;
    __half *xnh, *mkh, *cxh, *hph;
    __half *wqh, *wkh, *wvh, *wph, *woh, *w1h, *w2h;
    cudaGetSymbolAddress((void**)&quh, g_quh); cudaGetSymbolAddress((void**)&qvh, g_qvh);
    cudaGetSymbolAddress((void**)&kkh, g_kkh); cudaGetSymbolAddress((void**)&pph, g_pph);
    cudaGetSymbolAddress((void**)&vth, g_vth);
    cudaGetSymbolAddress((void**)&xnh, g_xnh); cudaGetSymbolAddress((void**)&mkh, g_mkh);
    cudaGetSymbolAddress((void**)&cxh, g_cxh); cudaGetSymbolAddress((void**)&hph, g_hph);
    cudaGetSymbolAddress((void**)&wqh, g_wqh); cudaGetSymbolAddress((void**)&wkh, g_wkh);
    cudaGetSymbolAddress((void**)&wvh, g_wvh); cudaGetSymbolAddress((void**)&wph, g_wph);
    cudaGetSymbolAddress((void**)&woh, g_woh);
    cudaGetSymbolAddress((void**)&w1h, g_w1h); cudaGetSymbolAddress((void**)&w2h, g_w2h);

    cudaFuncSetAttribute(hmma_gemm<1, true,  false, 0>, cudaFuncAttributeMaxDynamicSharedMemorySize, SMEMSZ);
    cudaFuncSetAttribute(hmma_gemm<3, true,  false, 0>, cudaFuncAttributeMaxDynamicSharedMemorySize, SMEMSZ);
    cudaFuncSetAttribute(hmma_gemm<1, false, true,  1>, cudaFuncAttributeMaxDynamicSharedMemorySize, SMEMSZ);
    cudaFuncSetAttribute(hmma_gemm<1, false, false, 2>, cudaFuncAttributeMaxDynamicSharedMemorySize, SMEMSZ);
    cudaFuncSetAttribute(hmma_gemm<1, false, false, 3>, cudaFuncAttributeMaxDynamicSharedMemorySize, SMEMSZ);
    cudaFuncSetAttribute(hmma_gemm<1, false, false, 4>, cudaFuncAttributeMaxDynamicSharedMemorySize, SMEMSZ);
    cudaFuncSetAttribute(attn_fused, cudaFuncAttributeMaxDynamicSharedMemorySize, FS_TOT);

    int nW = 3 * DD * DD / 4;
    Ptr5 p5; p5.s0 = Wq; p5.s1 = Wk; p5.s2 = Wv; p5.s3 = Wp; p5.s4 = Wo;
    cvt5<<<dim3((nW + 255) / 256, 5), 256>>>(p5, wqh, wkh, wvh, wph, woh, nW);
    int n1 = 3 * DFFX * DD / 4;
    cvt_half<<<(n1 + 255) / 256, 256>>>(W1, w1h, n1);
    int nM = BT * DD / 4;
    cvt_half<<<(nM + 255) / 256, 256>>>(MSK, mkh, nM);
    int n2 = 3 * 3 * DD * DFFX;
    cvt_w2<<<(n2 + 255) / 256, 256>>>(W2, w2h);

    dim3 gP(4, MP / 128);
    dim3 gF(8, MP / 128);
    dim3 gAt(8, ZZ);

    for (int i = 0; i < 3; i++) {
        size_t oD = (size_t)i * DD, oDD = (size_t)i * DD * DD;
        addln_kernel<true><<<BT, 128>>>(i == 0 ? X0 : x, x, PE + (size_t)i * TT * DD,
                                        l1a + oD, l1b + oD, nullptr, xnh);
        hmma_gemm<1, false, false, 2><<<gP, 256, SMEMSZ>>>(
            xnh, wqh + oDD, bq + oD, Ub + oD, Vb + oD,
            nullptr, quh, qvh, BT, DD, DD);
        hmma_gemm<1, false, false, 3><<<gP, 256, SMEMSZ>>>(
            xnh, wkh + oDD, bk + oD, nullptr, nullptr,
            nullptr, kkh, nullptr, BT, DD, DD);
        hmma_gemm<1, false, false, 3><<<gP, 256, SMEMSZ>>>(
            mkh, wph + oDD, nullptr, nullptr, nullptr,
            nullptr, pph, nullptr, BT, DD, DD);
        hmma_gemm<1, false, false, 4><<<gP, 256, SMEMSZ>>>(
            xnh, wvh + oDD, bv + oD, nullptr, nullptr,
            nullptr, vth, nullptr, BT, DD, DD);
        attn_fused<<<gAt, 256, FS_TOT>>>(quh, qvh, kkh, pph, vth, cxh);
        hmma_gemm<1, true, false, 0><<<gP, 256, SMEMSZ>>>(
            cxh, woh + oDD, bo + oD, nullptr, nullptr,
            x, nullptr, nullptr, BT, DD, DD);
        addln_kernel<true><<<BT, 128>>>(x, nullptr, nullptr,
                                        l2a + oD, l2b + oD, nullptr, xnh);
        hmma_gemm<1, false, true, 1><<<gF, 256, SMEMSZ>>>(
            xnh, w1h + (size_t)i * DFFX * DD,
            b1 + (size_t)i * DFFX, nullptr, nullptr,
            nullptr, hph, nullptr, BT, DFFX, DD);
        hmma_gemm<3, true, false, 0><<<gP, 256, SMEMSZ>>>(
            hph, w2h + (size_t)i * 3 * DD * DFFX,
            b2 + oD, nullptr, nullptr,
            x, nullptr, nullptr, BT, DD, DFFX);
    }
    addln_kernel<false><<<BT, 128>>>(x, nullptr, nullptr, fna, fnb, x, nullptr);
}

// round 12
// speedup vs baseline: 6.2532x; 1.1156x over previous
#include <cuda_runtime.h>
#include <cuda_fp16.h>
#include <math.h>
#include <stdint.h>

#define BB   64
#define TT   351
#define DD   512
#define HH   8
#define DFFX 1024
#define BT   (BB*TT)       // 22464
#define MP   22528
#define HPR  22784
#define TP   384
#define ZZ   (BB*HH)       // 512
#define STAGE_BYTES 36864
#define SMEMSZ (3*STAGE_BYTES)

// fused-attention smem layout (bytes), q-block = 48 rows
#define FS_PITCH 392
#define AT_QU 75264
#define AT_QV 84480
#define AT_B0 93696
#define AT_B1 102912
#define AF_A  75264
#define AF_PITCH 784
#define FS_TOT 112896             // occ 2

// ---------------- scratch ------------------------------------------------------------
static __device__ __half g_quh[(size_t)ZZ*TP*64];
static __device__ __half g_qvh[(size_t)ZZ*TP*64];
static __device__ __half g_kkh[(size_t)ZZ*TP*64];
static __device__ __half g_pph[(size_t)ZZ*TP*64];
static __device__ __half g_vth[(size_t)ZZ*64*TP];
static __device__ __half g_xnh[MP*(size_t)DD];
static __device__ __half g_mkh[MP*(size_t)DD];
static __device__ __half g_cxh[MP*(size_t)DD];
static __device__ __half g_hph[(size_t)HPR*DFFX];
static __device__ __half g_wqkv[3*3*DD*DD];         // [l][{q,k,v}*512][512]
static __device__ __half g_wph[3*DD*DD], g_woh[3*DD*DD];
static __device__ __half g_w1h[3*DFFX*DD];
static __device__ __half g_w2h[3*3*DD*DFFX];

// ---------------- PTX helpers --------------------------------------------------------
__device__ __forceinline__ uint32_t smem_u32(const void* p) {
    uint32_t a;
    asm("{ .reg .u64 t; cvta.to.shared.u64 t, %1; cvt.u32.u64 %0, t; }" : "=r"(a) : "l"(p));
    return a;
}
__device__ __forceinline__ void cp16(uint32_t dst, const void* src) {
    asm volatile("cp.async.cg.shared.global [%0], [%1], 16;" :: "r"(dst), "l"(src) : "memory");
}
#define CP_COMMIT() asm volatile("cp.async.commit_group;" ::: "memory")
#define CP_WAIT2()  asm volatile("cp.async.wait_group 2;" ::: "memory")
#define CP_WAIT1()  asm volatile("cp.async.wait_group 1;" ::: "memory")
#define CP_WAIT0()  asm volatile("cp.async.wait_group 0;" ::: "memory")

__device__ __forceinline__ void mma16816(float* c, const uint32_t* a, const uint32_t* b) {
    asm volatile(
        "mma.sync.aligned.m16n8k16.row.col.f32.f16.f16.f32 "
        "{%0,%1,%2,%3}, {%4,%5,%6,%7}, {%8,%9}, {%0,%1,%2,%3};"
        : "+f"(c[0]), "+f"(c[1]), "+f"(c[2]), "+f"(c[3])
        : "r"(a[0]), "r"(a[1]), "r"(a[2]), "r"(a[3]), "r"(b[0]), "r"(b[1]));
}
__device__ __forceinline__ void ldsm4(uint32_t* r, uint32_t addr) {
    asm volatile("ldmatrix.sync.aligned.m8n8.x4.shared.b16 {%0,%1,%2,%3}, [%4];"
        : "=r"(r[0]), "=r"(r[1]), "=r"(r[2]), "=r"(r[3]) : "r"(addr));
}
__device__ __forceinline__ uint32_t packh(float a, float b) {
    __half2 h = __floats2half2_rn(a, b);
    return *reinterpret_cast<uint32_t*>(&h);
}

// ---------------- conversion kernels -------------------------------------------------
__global__ void cvt_qkv(const float* __restrict__ Wq, const float* __restrict__ Wk,
                        const float* __restrict__ Wv, __half* __restrict__ dst, int n4per) {
    int i = blockIdx.x * 256 + threadIdx.x;
    if (i >= n4per) return;
    int tsel = blockIdx.y;
    const float* s = (tsel == 0) ? Wq : (tsel == 1) ? Wk : Wv;
    float4 v = ((const float4*)s)[i];
    const int per_l4 = DD * DD / 4;
    int l = i / per_l4, r = i - l * per_l4;
    long di = (long)l * (3 * per_l4) + (long)tsel * per_l4 + r;
    uint2 st; st.x = packh(v.x, v.y); st.y = packh(v.z, v.w);
    ((uint2*)dst)[di] = st;
}
__global__ void cvt_half(const float* __restrict__ in, __half* __restrict__ out, int n4) {
    int i = blockIdx.x * 256 + threadIdx.x;
    if (i >= n4) return;
    float4 v = ((const float4*)in)[i];
    uint2 st; st.x = packh(v.x, v.y); st.y = packh(v.z, v.w);
    ((uint2*)out)[i] = st;
}
// W2 in: [l][n][k][s] -> out [l][s][n][k]
__global__ void cvt_w2(const float* __restrict__ in, __half* __restrict__ hi) {
    int idx = blockIdx.x * 256 + threadIdx.x;
    const int per_l = 3 * DD * DFFX;
    if (idx >= 3 * per_l) return;
    int l = idx / per_l; int r = idx - l * per_l;
    int s = r / (DD * DFFX); int r2 = r - s * (DD * DFFX);
    int n = r2 / DFFX; int k2 = r2 - n * DFFX;
    hi[idx] = __float2half_rn(in[(((size_t)l * DD + n) * DFFX + k2) * 3 + s]);
}

// ---------------- HMMA 1-term fp16 GEMM, K-chunk 64, 3-stage pipeline ----------------
// MODE 0: fp32 C (+ACC). MODE 1: fp16 padded-H remap (FF1). MODE 3: head-major.
// MODE 5: merged QKV epilogue (seg0 dual head-major, seg1 head-major, seg2 transposed).
template<int TAPS, bool ACC, bool RELU, int MODE>
__global__ __launch_bounds__(256, 2)
void hmma_gemm(const __half* __restrict__ Ahi, const __half* __restrict__ Bhi,
               const float* __restrict__ bias, const float* __restrict__ bias2,
               const float* __restrict__ bias3, const float* __restrict__ bias4,
               const float* __restrict__ bias5,
               float* __restrict__ Cf,
               __half* __restrict__ O1h, __half* __restrict__ O2h,
               __half* __restrict__ O3h, __half* __restrict__ O4h,
               int Mstore, int N, int K) {
    extern __shared__ char sm[];
    uint32_t dbase = smem_u32(sm);
    int tid = threadIdx.x, lane = tid & 31, w = tid >> 5;
    int wm = (w & 1) << 6, wn = (w >> 1) << 5;
    int bm = blockIdx.y << 7, bn = blockIdx.x << 7;

    uint32_t so[4]; long ga[4], gb[4];
#pragma unroll
    for (int j = 0; j < 4; j++) {
        int idx = tid + 256 * j; int row = idx >> 3, c16 = idx & 7;
        so[j] = row * 144 + c16 * 16;
        int grow = bm + row;
        long arow;
        if (TAPS == 3) { int b = grow / 351; int t = grow - b * 351; arow = (long)b * 353 + t; }
        else arow = grow;
        ga[j] = arow * (long)K + c16 * 8;
        gb[j] = (long)(bn + row) * K + c16 * 8;
    }
    const int kch = K >> 6;
    const int nch = TAPS * kch;

#define LOAD_CHUNK(c, stg) do { \
        int s_ = (c) / kch; int kb_ = ((c) - s_ * kch) << 6; \
        long sK_ = (TAPS == 3) ? (long)s_ * K : 0; \
        long sNK_ = (TAPS == 3) ? (long)s_ * N * K : 0; \
        uint32_t sb_ = dbase + (stg) * STAGE_BYTES; \
        _Pragma("unroll") \
        for (int j = 0; j < 4; j++) { \
            cp16(sb_ + so[j],         Ahi + sK_ + ga[j] + kb_); \
            cp16(sb_ + 18432 + so[j], Bhi + sNK_ + gb[j] + kb_); \
        } \
    } while (0)

    float acc[4][4][4];
#pragma unroll
    for (int a = 0; a < 4; a++)
#pragma unroll
        for (int b = 0; b < 4; b++)
#pragma unroll
            for (int q2 = 0; q2 < 4; q2++) acc[a][b][q2] = 0.0f;

    int bq = lane & 3, bg = lane >> 2;
    uint32_t aoff = (uint32_t)(wm + (lane & 15)) * 144 + (uint32_t)(((lane >> 4) & 1) << 4);
    uint32_t boff = 18432u + (uint32_t)(wn + ((lane >> 4) << 3) + (lane & 7)) * 144
                  + (uint32_t)(((lane >> 3) & 1) << 4);

    LOAD_CHUNK(0, 0);
    CP_COMMIT();
    LOAD_CHUNK(1, 1);
    CP_COMMIT();
#pragma unroll 1
    for (int c = 0; c < nch; c++) {
        if (c + 2 < nch) LOAD_CHUNK(c + 2, (c + 2) % 3);
        CP_COMMIT();
        CP_WAIT2();
        __syncthreads();
        uint32_t sb = dbase + (c % 3) * STAGE_BYTES;
#pragma unroll
        for (int k16 = 0; k16 < 4; k16++) {
            uint32_t kof = k16 * 32;
            uint32_t bh[4][2], t[4];
            ldsm4(t, sb + boff + kof);
            bh[0][0] = t[0]; bh[0][1] = t[1]; bh[1][0] = t[2]; bh[1][1] = t[3];
            ldsm4(t, sb + boff + 2304 + kof);
            bh[2][0] = t[0]; bh[2][1] = t[1]; bh[3][0] = t[2]; bh[3][1] = t[3];
#pragma unroll
            for (int mi = 0; mi < 4; mi++) {
                uint32_t ah[4];
                ldsm4(ah, sb + aoff + mi * 2304 + kof);
#pragma unroll
                for (int ni = 0; ni < 4; ni++)
                    mma16816(acc[mi][ni], ah, bh[ni]);
            }
        }
        __syncthreads();
    }
#undef LOAD_CHUNK

#pragma unroll
    for (int mi = 0; mi < 4; mi++) {
#pragma unroll
        for (int half = 0; half < 2; half++) {
            int m = bm + wm + mi * 16 + bg + half * 8;
            if (m >= Mstore) continue;
            int b = 0, t = 0; long crow = m;
            if (MODE == 1) { b = m / 351; t = m - b * 351; crow = (long)b * 353 + 1 + t; }
            if (MODE >= 2) { b = m / 351; t = m - b * 351; }
#pragma unroll
            for (int ni = 0; ni < 4; ni++) {
                int col = bn + wn + ni * 8 + bq * 2;
                float v0 = acc[mi][ni][half * 2 + 0];
                float v1 = acc[mi][ni][half * 2 + 1];
                if (MODE == 0 || MODE == 1 || MODE == 3) {
                    if (bias) { v0 += bias[col]; v1 += bias[col + 1]; }
                }
                if (RELU) { v0 = fmaxf(v0, 0.0f); v1 = fmaxf(v1, 0.0f); }
                if (MODE == 0) {
                    float* cp = Cf + (long)m * N + col;
                    if (ACC) { v0 += cp[0]; v1 += cp[1]; }
                    float2 st; st.x = v0; st.y = v1;
                    *(float2*)cp = st;
                } else if (MODE == 1) {
                    *(uint32_t*)(O1h + crow * (long)N + col) = packh(v0, v1);
                } else if (MODE == 3) {
                    int h = col >> 6, d = col & 63;
                    long base = ((long)(b * 8 + h) * TP + t) * 64 + d;
                    *(uint32_t*)(O1h + base) = packh(v0, v1);
                } else if (MODE == 5) {
                    int seg = col >> 9, cs = col & 511;
                    int h = cs >> 6, d = cs & 63;
                    if (seg == 0) {
                        long base = ((long)(b * 8 + h) * TP + t) * 64 + d;
                        float q0v = v0 + bias[cs], q1v = v1 + bias[cs + 1];
                        *(uint32_t*)(O1h + base) = packh(q0v + bias2[cs], q1v + bias2[cs + 1]);
                        *(uint32_t*)(O2h + base) = packh(q0v + bias3[cs], q1v + bias3[cs + 1]);
                    } else if (seg == 1) {
                        long base = ((long)(b * 8 + h) * TP + t) * 64 + d;
                        *(uint32_t*)(O3h + base) = packh(v0 + bias4[cs], v1 + bias4[cs + 1]);
                    } else {
                        float u0 = v0 + bias5[cs], u1 = v1 + bias5[cs + 1];
                        O4h[((long)(b * 8 + h) * 64 + d) * TP + t]     = __float2half_rn(u0);
                        O4h[((long)(b * 8 + h) * 64 + d + 1) * TP + t] = __float2half_rn(u1);
                    }
                }
            }
        }
    }
}

// ---------------- fully fused attention ----------------------------------------------
__global__ __launch_bounds__(256, 2)
void attn_fused(const __half* __restrict__ quh, const __half* __restrict__ qvh,
                const __half* __restrict__ kkh, const __half* __restrict__ pph,
                const __half* __restrict__ vth, __half* __restrict__ Ch) {
    extern __shared__ char sm[];
    uint32_t dbase = smem_u32(sm);
    float* S = (float*)sm;
    int z = blockIdx.y, q0 = blockIdx.x * 48;
    int tid = threadIdx.x, lane = tid & 31, w = tid >> 5;
    int cb = w << 3;
    int bq = lane & 3, bg = lane >> 2;

    for (int i = tid; i < 512; i += 256) {
        int r = i >> 3, c = i & 7;
        int gq = q0 + r; if (gq >= TP) gq = q0;
        cp16(dbase + AT_QU + r * 144 + c * 16, quh + ((long)z * TP + gq) * 64 + c * 8);
        cp16(dbase + AT_QV + r * 144 + c * 16, qvh + ((long)z * TP + gq) * 64 + c * 8);
        cp16(dbase + AT_B0 + r * 144 + c * 16, kkh + ((long)z * TP + r) * 64 + c * 8);
    }
    CP_COMMIT();
    CP_WAIT0();
    __syncthreads();

    uint32_t afr[4][4][4];
#pragma unroll
    for (int mi = 0; mi < 3; mi++)
#pragma unroll
        for (int k16 = 0; k16 < 4; k16++) {
            const char* pa = sm + AT_QU + (mi * 16 + bg) * 144 + k16 * 32 + bq * 4;
            afr[mi][k16][0] = *(const uint32_t*)pa;
            afr[mi][k16][1] = *(const uint32_t*)(pa + 8 * 144);
            afr[mi][k16][2] = *(const uint32_t*)(pa + 16);
            afr[mi][k16][3] = *(const uint32_t*)(pa + 8 * 144 + 16);
        }

#pragma unroll 1
    for (int ch = 0; ch < 12; ch++) {
        if (ch + 1 < 12) {
            const __half* src = (ch + 1 < 6) ? kkh : pph;
            int rows0 = ((ch + 1) % 6) * 64;
            uint32_t bb = ((ch + 1) & 1) ? AT_B1 : AT_B0;
            for (int i = tid; i < 512; i += 256) {
                int r = i >> 3, c = i & 7;
                cp16(dbase + bb + r * 144 + c * 16,
                     src + ((long)z * TP + rows0 + r) * 64 + c * 8);
            }
        }
        CP_COMMIT();
        CP_WAIT1();
        __syncthreads();
        if (ch == 6) {
#pragma unroll
            for (int mi = 0; mi < 4; mi++)
#pragma unroll
                for (int k16 = 0; k16 < 4; k16++) {
                    const char* pa = sm + AT_QV + (mi * 16 + bg) * 144 + k16 * 32 + bq * 4;
                    afr[mi][k16][0] = *(const uint32_t*)pa;
                    afr[mi][k16][1] = *(const uint32_t*)(pa + 8 * 144);
                    afr[mi][k16][2] = *(const uint32_t*)(pa + 16);
                    afr[mi][k16][3] = *(const uint32_t*)(pa + 8 * 144 + 16);
                }
        }
        uint32_t bb = (ch & 1) ? AT_B1 : AT_B0;
        int col0 = (ch % 6) * 64;
        if (ch < 6) {
            float acc[3][4];
#pragma unroll
            for (int a = 0; a < 3; a++)
#pragma unroll
                for (int e = 0; e < 4; e++) acc[a][e] = 0.0f;
#pragma unroll
            for (int k16 = 0; k16 < 4; k16++) {
                const char* pb = sm + bb + (cb + bg) * 144 + k16 * 32 + bq * 4;
                uint32_t bh[2];
                bh[0] = *(const uint32_t*)pb;
                bh[1] = *(const uint32_t*)(pb + 16);
#pragma unroll
                for (int mi = 0; mi < 3; mi++)
                    mma16816(acc[mi], afr[mi][k16], bh);
            }
#pragma unroll
            for (int mi = 0; mi < 3; mi++)
#pragma unroll
                for (int half = 0; half < 2; half++) {
                    int r = mi * 16 + bg + half * 8;
                    int col = col0 + cb + bq * 2;
                    S[r * FS_PITCH + col]     = acc[mi][half * 2 + 0];
                    S[r * FS_PITCH + col + 1] = acc[mi][half * 2 + 1];
                }
        } else {
            float acc[4][4];
#pragma unroll
            for (int a = 0; a < 4; a++)
#pragma unroll
                for (int e = 0; e < 4; e++) acc[a][e] = 0.0f;
#pragma unroll
            for (int k16 = 0; k16 < 4; k16++) {
                const char* pb = sm + bb + (cb + bg) * 144 + k16 * 32 + bq * 4;
                uint32_t bh[2];
                bh[0] = *(const uint32_t*)pb;
                bh[1] = *(const uint32_t*)(pb + 16);
#pragma unroll
                for (int mi = 0; mi < 4; mi++)
                    mma16816(acc[mi], afr[mi][k16], bh);
            }
#pragma unroll
            for (int mi = 0; mi < 4; mi++)
#pragma unroll
                for (int half = 0; half < 2; half++) {
                    int r = mi * 16 + bg + half * 8;
                    if (r > 48) continue;
                    int rp = q0 + r;
#pragma unroll
                    for (int e = 0; e < 2; e++) {
                        int jj = col0 + cb + bq * 2 + e;
                        if (jj >= TT) continue;
                        float v = acc[mi][half * 2 + e];
                        if (jj >= 350 - rp) {
                            if (r < 48) S[r * FS_PITCH + jj - 350 + rp] += v;
                        } else if (r >= 1) {
                            S[(r - 1) * FS_PITCH + jj + rp + 1] += v;
                        }
                    }
                }
        }
        __syncthreads();
    }

    // ---- softmax via ex2.approx.f16x2 -> fp16 A tile (fully convergent) ----
    if (tid < 192) {
        int r = tid >> 2, qu = tid & 3;
        const float scale = 0.044194173824159216f;        // 1/sqrt(512)
        const float a_l2 = scale * 1.4426950408889634f;   // scale*log2(e)
        float* Srow = S + r * FS_PITCH;
        char* Arow = sm + AF_A + r * AF_PITCH;
        int c0 = qu * 96;
        float mx = -1e30f;
        for (int cc = c0; cc < c0 + 96; cc++)
            if (cc < TT) mx = fmaxf(mx, Srow[cc]);
        mx = fmaxf(mx, __shfl_xor_sync(0xffffffffu, mx, 1));
        mx = fmaxf(mx, __shfl_xor_sync(0xffffffffu, mx, 2));
        float boff2 = -mx * a_l2;
        float sum = 0.0f;
        for (int cc = c0; cc < c0 + 96; cc += 2) {
            float x0 = (cc < TT)     ? Srow[cc]     * a_l2 + boff2 : -60.0f;
            float x1 = (cc + 1 < TT) ? Srow[cc + 1] * a_l2 + boff2 : -60.0f;
            __half2 hx = __floats2half2_rn(x0, x1);
            __half2 he = h2exp2(hx);
            float2 fe = __half22float2(he);
            sum += fe.x + fe.y;
            *(__half2*)(Arow + cc * 2) = he;
        }
        sum += __shfl_xor_sync(0xffffffffu, sum, 1);
        sum += __shfl_xor_sync(0xffffffffu, sum, 2);
        __half2 inv2 = __half2half2(__float2half_rn(1.0f / sum));
        for (int cc = c0; cc < c0 + 96; cc += 2) {
            __half2 v = *(__half2*)(Arow + cc * 2);
            *(__half2*)(Arow + cc * 2) = __hmul2(v, inv2);
        }
    }
    __syncthreads();

    // ---- load V tile (64 x 384 fp16, pitch 784) over dead score region ----
    for (int i = tid; i < 3072; i += 256) {
        int d = i / 48, c16 = i - d * 48;
        cp16(dbase + d * AF_PITCH + c16 * 16,
             vth + ((long)z * 64 + d) * TP + c16 * 8);
    }
    CP_COMMIT(); CP_WAIT0(); __syncthreads();

    // ---- ctx GEMM: out[48 x 64] = A[48 x 384] @ V^T, 6 warps ----
    if (w < 6) {
        int wr = w % 3, wc = w / 3;
        float acc[4][4];
#pragma unroll
        for (int a = 0; a < 4; a++)
#pragma unroll
            for (int e = 0; e < 4; e++) acc[a][e] = 0.0f;
#pragma unroll 1
        for (int k16 = 0; k16 < 24; k16++) {
            int kb = k16 * 32 + bq * 4;
            const char* pa = sm + AF_A + (wr * 16 + bg) * AF_PITCH + kb;
            uint32_t ah[4];
            ah[0] = *(const uint32_t*)pa;
            ah[1] = *(const uint32_t*)(pa + 8 * AF_PITCH);
            ah[2] = *(const uint32_t*)(pa + 16);
            ah[3] = *(const uint32_t*)(pa + 8 * AF_PITCH + 16);
#pragma unroll
            for (int ni = 0; ni < 4; ni++) {
                const char* pb = sm + (wc * 32 + ni * 8 + bg) * AF_PITCH + kb;
                uint32_t bh[2];
                bh[0] = *(const uint32_t*)pb;
                bh[1] = *(const uint32_t*)(pb + 16);
                mma16816(acc[ni], ah, bh);
            }
        }
        int b = z >> 3, h = z & 7;
#pragma unroll
        for (int half = 0; half < 2; half++) {
            int gq = q0 + wr * 16 + bg + half * 8;
            if (gq >= TT) continue;
#pragma unroll
            for (int ni = 0; ni < 4; ni++) {
                int col = wc * 32 + ni * 8 + bq * 2;
                long addr = ((long)(b * 351 + gq)) * DD + h * 64 + col;
                *(uint32_t*)(Ch + addr) = packh(acc[ni][half * 2], acc[ni][half * 2 + 1]);
            }
        }
    }
}

// ---------------- add pos-emb + LayerNorm --------------------------------------------
template<bool F16O>
__global__ void addln_kernel(const float* __restrict__ xin, float* __restrict__ xupd,
                             const float* __restrict__ pe,
                             const float* __restrict__ ga, const float* __restrict__ gb,
                             float* __restrict__ out, __half* __restrict__ ohi) {
    int row = blockIdx.x;
    int t   = row % TT;
    const float* xr = xin + (size_t)row * DD;
    int tid = threadIdx.x;
    float vals[4];
#pragma unroll
    for (int i = 0; i < 4; i++) {
        int c = tid + i * 128;
        float vv = xr[c];
        if (pe) vv += pe[(size_t)t * DD + c];
        vals[i] = vv;
    }
    if (pe) {
        float* xw = xupd + (size_t)row * DD;
#pragma unroll
        for (int i = 0; i < 4; i++) xw[tid + i * 128] = vals[i];
    }
    __shared__ float sh[4];
    float s = vals[0] + vals[1] + vals[2] + vals[3];
#pragma unroll
    for (int o = 16; o > 0; o >>= 1) s += __shfl_xor_sync(0xffffffffu, s, o);
    if ((tid & 31) == 0) sh[tid >> 5] = s;
    __syncthreads();
    float mean = (sh[0] + sh[1] + sh[2] + sh[3]) * (1.0f / DD);
    __syncthreads();
    float sq = 0.0f;
#pragma unroll
    for (int i = 0; i < 4; i++) { float d = vals[i] - mean; sq += d * d; }
#pragma unroll
    for (int o = 16; o > 0; o >>= 1) sq += __shfl_xor_sync(0xffffffffu, sq, o);
    if ((tid & 31) == 0) sh[tid >> 5] = sq;
    __syncthreads();
    float var  = sh[0] + sh[1] + sh[2] + sh[3];
    float stdv = sqrtf(var * (1.0f / (DD - 1)));
    float inv  = 1.0f / (stdv + 1e-6f);
#pragma unroll
    for (int i = 0; i < 4; i++) {
        int c = tid + i * 128;
        float v = ga[c] * (vals[i] - mean) * inv + gb[c];
        if (F16O) ohi[(size_t)row * DD + c] = __float2half_rn(v);
        else      out[(size_t)row * DD + c] = v;
    }
}

// ------------------------------------ launch -----------------------------------------
extern "C" void kernel_launch(void* const* d_in, const int* in_sizes, int n_in,
                              void* d_out, int out_size) {
    const float* X0  = (const float*)d_in[0];
    const float* MSK = (const float*)d_in[1];
    const float* PE  = (const float*)d_in[2];
    const float* Wq  = (const float*)d_in[3];
    const float* bq  = (const float*)d_in[4];
    const float* Wk  = (const float*)d_in[5];
    const float* bk  = (const float*)d_in[6];
    const float* Wv  = (const float*)d_in[7];
    const float* bv  = (const float*)d_in[8];
    const float* Wp  = (const float*)d_in[9];
    const float* Ub  = (const float*)d_in[10];
    const float* Vb  = (const float*)d_in[11];
    const float* Wo  = (const float*)d_in[12];
    const float* bo  = (const float*)d_in[13];
    const float* l1a = (const float*)d_in[14];
    const float* l1b = (const float*)d_in[15];
    const float* l2a = (const float*)d_in[16];
    const float* l2b = (const float*)d_in[17];
    const float* W1  = (const float*)d_in[18];
    const float* b1  = (const float*)d_in[19];
    const float* W2  = (const float*)d_in[20];
    const float* b2  = (const float*)d_in[21];
    const float* fna = (const float*)d_in[22];
    const float* fnb = (const float*)d_in[23];
    float* x = (float*)d_out;

    __half *quh, *qvh, *kkh, *pph, *vth;
    __half *xnh, *mkh, *cxh, *hph;
    __half *wqkv, *wph, *woh, *w1h, *w2h;
    cudaGetSymbolAddress((void**)&quh, g_quh); cudaGetSymbolAddress((void**)&qvh, g_qvh);
    cudaGetSymbolAddress((void**)&kkh, g_kkh); cudaGetSymbolAddress((void**)&pph, g_pph);
    cudaGetSymbolAddress((void**)&vth, g_vth);
    cudaGetSymbolAddress((void**)&xnh, g_xnh); cudaGetSymbolAddress((void**)&mkh, g_mkh);
    cudaGetSymbolAddress((void**)&cxh, g_cxh); cudaGetSymbolAddress((void**)&hph, g_hph);
    cudaGetSymbolAddress((void**)&wqkv, g_wqkv);
    cudaGetSymbolAddress((void**)&wph, g_wph); cudaGetSymbolAddress((void**)&woh, g_woh);
    cudaGetSymbolAddress((void**)&w1h, g_w1h); cudaGetSymbolAddress((void**)&w2h, g_w2h);

    cudaFuncSetAttribute(hmma_gemm<1, true,  false, 0>, cudaFuncAttributeMaxDynamicSharedMemorySize, SMEMSZ);
    cudaFuncSetAttribute(hmma_gemm<3, true,  false, 0>, cudaFuncAttributeMaxDynamicSharedMemorySize, SMEMSZ);
    cudaFuncSetAttribute(hmma_gemm<1, false, true,  1>, cudaFuncAttributeMaxDynamicSharedMemorySize, SMEMSZ);
    cudaFuncSetAttribute(hmma_gemm<1, false, false, 3>, cudaFuncAttributeMaxDynamicSharedMemorySize, SMEMSZ);
    cudaFuncSetAttribute(hmma_gemm<1, false, false, 5>, cudaFuncAttributeMaxDynamicSharedMemorySize, SMEMSZ);
    cudaFuncSetAttribute(attn_fused, cudaFuncAttributeMaxDynamicSharedMemorySize, FS_TOT);

    int n4per = 3 * DD * DD / 4;
    cvt_qkv<<<dim3((n4per + 255) / 256, 3), 256>>>(Wq, Wk, Wv, wqkv, n4per);
    cvt_half<<<(n4per + 255) / 256, 256>>>(Wp, wph, n4per);
    cvt_half<<<(n4per + 255) / 256, 256>>>(Wo, woh, n4per);
    int n1 = 3 * DFFX * DD / 4;
    cvt_half<<<(n1 + 255) / 256, 256>>>(W1, w1h, n1);
    int nM = BT * DD / 4;
    cvt_half<<<(nM + 255) / 256, 256>>>(MSK, mkh, nM);
    int n2 = 3 * 3 * DD * DFFX;
    cvt_w2<<<(n2 + 255) / 256, 256>>>(W2, w2h);

    dim3 gP(4, MP / 128);
    dim3 gQKV(12, MP / 128);
    dim3 gF(8, MP / 128);
    dim3 gAt(8, ZZ);

    for (int i = 0; i < 3; i++) {
        size_t oD = (size_t)i * DD, oDD = (size_t)i * DD * DD;
        addln_kernel<true><<<BT, 128>>>(i == 0 ? X0 : x, x, PE + (size_t)i * TT * DD,
                                        l1a + oD, l1b + oD, nullptr, xnh);
        hmma_gemm<1, false, false, 5><<<gQKV, 256, SMEMSZ>>>(
            xnh, wqkv + (size_t)i * 3 * DD * DD,
            bq + oD, Ub + oD, Vb + oD, bk + oD, bv + oD,
            nullptr, quh, qvh, kkh, vth, BT, 3 * DD, DD);
        hmma_gemm<1, false, false, 3><<<gP, 256, SMEMSZ>>>(
            mkh, wph + oDD, nullptr, nullptr, nullptr, nullptr, nullptr,
            nullptr, pph, nullptr, nullptr, nullptr, BT, DD, DD);
        attn_fused<<<gAt, 256, FS_TOT>>>(quh, qvh, kkh, pph, vth, cxh);
        hmma_gemm<1, true, false, 0><<<gP, 256, SMEMSZ>>>(
            cxh, woh + oDD, bo + oD, nullptr, nullptr, nullptr, nullptr,
            x, nullptr, nullptr, nullptr, nullptr, BT, DD, DD);
        addln_kernel<true><<<BT, 128>>>(x, nullptr, nullptr,
                                        l2a + oD, l2b + oD, nullptr, xnh);
        hmma_gemm<1, false, true, 1><<<gF, 256, SMEMSZ>>>(
            xnh, w1h + (size_t)i * DFFX * DD,
            b1 + (size_t)i * DFFX, nullptr, nullptr, nullptr, nullptr,
            nullptr, hph, nullptr, nullptr, nullptr, BT, DFFX, DD);
        hmma_gemm<3, true, false, 0><<<gP, 256, SMEMSZ>>>(
            hph, w2h + (size_t)i * 3 * DD * DFFX,
            b2 + oD, nullptr, nullptr, nullptr, nullptr,
            x, nullptr, nullptr, nullptr, nullptr, BT, DD, DFFX);
    }
    addln_kernel<false><<<BT, 128>>>(x, nullptr, nullptr, fna, fnb, x, nullptr);
}

// round 13
// speedup vs baseline: 6.2893x; 1.0058x over previous
#include <cuda_runtime.h>
#include <cuda_fp16.h>
#include <math.h>
#include <stdint.h>

#define BB   64
#define TT   351
#define DD   512
#define HH   8
#define DFFX 1024
#define BT   (BB*TT)       // 22464
#define MP   22528
#define HPR  22784
#define TP   384
#define ZZ   (BB*HH)       // 512
#define ZT64 ((size_t)ZZ*TP*64)
#define STAGE_BYTES 36864
#define SMEMSZ (3*STAGE_BYTES)

// fused-attention smem layout (bytes), q-block = 48 rows
#define FS_PITCH 392
#define AT_QU 75264
#define AT_QV 84480
#define AT_B0 93696
#define AT_B1 102912
#define AF_A  75264
#define AF_PITCH 784
#define FS_TOT 112896             // occ 2

// ---------------- scratch ------------------------------------------------------------
static __device__ __half g_quh[ZT64];
static __device__ __half g_qvh[ZT64];
static __device__ __half g_kkh[ZT64];
static __device__ __half g_pph[3*ZT64];            // all 3 layers, hoisted
static __device__ __half g_vth[ZT64];
static __device__ __half g_xnh[MP*(size_t)DD];
static __device__ __half g_mkh[MP*(size_t)DD];
static __device__ __half g_cxh[MP*(size_t)DD];
static __device__ __half g_hph[(size_t)HPR*DFFX];
static __device__ __half g_wqkv[3*3*DD*DD];
static __device__ __half g_wph[3*DD*DD], g_woh[3*DD*DD];
static __device__ __half g_w1h[3*DFFX*DD];
static __device__ __half g_w2h[3*3*DD*DFFX];

// ---------------- PTX helpers --------------------------------------------------------
__device__ __forceinline__ uint32_t smem_u32(const void* p) {
    uint32_t a;
    asm("{ .reg .u64 t; cvta.to.shared.u64 t, %1; cvt.u32.u64 %0, t; }" : "=r"(a) : "l"(p));
    return a;
}
__device__ __forceinline__ void cp16(uint32_t dst, const void* src) {
    asm volatile("cp.async.cg.shared.global [%0], [%1], 16;" :: "r"(dst), "l"(src) : "memory");
}
#define CP_COMMIT() asm volatile("cp.async.commit_group;" ::: "memory")
#define CP_WAIT2()  asm volatile("cp.async.wait_group 2;" ::: "memory")
#define CP_WAIT1()  asm volatile("cp.async.wait_group 1;" ::: "memory")
#define CP_WAIT0()  asm volatile("cp.async.wait_group 0;" ::: "memory")

__device__ __forceinline__ void mma16816(float* c, const uint32_t* a, const uint32_t* b) {
    asm volatile(
        "mma.sync.aligned.m16n8k16.row.col.f32.f16.f16.f32 "
        "{%0,%1,%2,%3}, {%4,%5,%6,%7}, {%8,%9}, {%0,%1,%2,%3};"
        : "+f"(c[0]), "+f"(c[1]), "+f"(c[2]), "+f"(c[3])
        : "r"(a[0]), "r"(a[1]), "r"(a[2]), "r"(a[3]), "r"(b[0]), "r"(b[1]));
}
__device__ __forceinline__ void ldsm4(uint32_t* r, uint32_t addr) {
    asm volatile("ldmatrix.sync.aligned.m8n8.x4.shared.b16 {%0,%1,%2,%3}, [%4];"
        : "=r"(r[0]), "=r"(r[1]), "=r"(r[2]), "=r"(r[3]) : "r"(addr));
}
__device__ __forceinline__ uint32_t packh(float a, float b) {
    __half2 h = __floats2half2_rn(a, b);
    return *reinterpret_cast<uint32_t*>(&h);
}

// ---------------- conversion kernels -------------------------------------------------
__global__ void cvt_qkv(const float* __restrict__ Wq, const float* __restrict__ Wk,
                        const float* __restrict__ Wv, __half* __restrict__ dst, int n4per) {
    int i = blockIdx.x * 256 + threadIdx.x;
    if (i >= n4per) return;
    int tsel = blockIdx.y;
    const float* s = (tsel == 0) ? Wq : (tsel == 1) ? Wk : Wv;
    float4 v = ((const float4*)s)[i];
    const int per_l4 = DD * DD / 4;
    int l = i / per_l4, r = i - l * per_l4;
    long di = (long)l * (3 * per_l4) + (long)tsel * per_l4 + r;
    uint2 st; st.x = packh(v.x, v.y); st.y = packh(v.z, v.w);
    ((uint2*)dst)[di] = st;
}
__global__ void cvt_half(const float* __restrict__ in, __half* __restrict__ out, int n4) {
    int i = blockIdx.x * 256 + threadIdx.x;
    if (i >= n4) return;
    float4 v = ((const float4*)in)[i];
    uint2 st; st.x = packh(v.x, v.y); st.y = packh(v.z, v.w);
    ((uint2*)out)[i] = st;
}
// W2 in: [l][n][k][s] -> out [l][s][n][k]
__global__ void cvt_w2(const float* __restrict__ in, __half* __restrict__ hi) {
    int idx = blockIdx.x * 256 + threadIdx.x;
    const int per_l = 3 * DD * DFFX;
    if (idx >= 3 * per_l) return;
    int l = idx / per_l; int r = idx - l * per_l;
    int s = r / (DD * DFFX); int r2 = r - s * (DD * DFFX);
    int n = r2 / DFFX; int k2 = r2 - n * DFFX;
    hi[idx] = __float2half_rn(in[(((size_t)l * DD + n) * DFFX + k2) * 3 + s]);
}

// ---------------- HMMA 1-term fp16 GEMM, K-chunk 64, 3-stage pipeline ----------------
// MODE 0: fp32 C (+ACC). MODE 1: fp16 padded-H remap (FF1). MODE 3: head-major
//         (supports gridDim.z layer batching via lws/los strides).
// MODE 5: merged QKV epilogue.
template<int TAPS, bool ACC, bool RELU, int MODE>
__global__ __launch_bounds__(256, 2)
void hmma_gemm(const __half* __restrict__ Ahi, const __half* __restrict__ Bhi,
               const float* __restrict__ bias, const float* __restrict__ bias2,
               const float* __restrict__ bias3, const float* __restrict__ bias4,
               const float* __restrict__ bias5,
               float* __restrict__ Cf,
               __half* __restrict__ O1h, __half* __restrict__ O2h,
               __half* __restrict__ O3h, __half* __restrict__ O4h,
               int Mstore, int N, int K, long lws, long los) {
    extern __shared__ char sm[];
    uint32_t dbase = smem_u32(sm);
    Bhi += (long)blockIdx.z * lws;
    O1h += (long)blockIdx.z * los;
    int tid = threadIdx.x, lane = tid & 31, w = tid >> 5;
    int wm = (w & 1) << 6, wn = (w >> 1) << 5;
    int bm = blockIdx.y << 7, bn = blockIdx.x << 7;

    uint32_t so[4]; long ga[4], gb[4];
#pragma unroll
    for (int j = 0; j < 4; j++) {
        int idx = tid + 256 * j; int row = idx >> 3, c16 = idx & 7;
        so[j] = row * 144 + c16 * 16;
        int grow = bm + row;
        long arow;
        if (TAPS == 3) { int b = grow / 351; int t = grow - b * 351; arow = (long)b * 353 + t; }
        else arow = grow;
        ga[j] = arow * (long)K + c16 * 8;
        gb[j] = (long)(bn + row) * K + c16 * 8;
    }
    const int kch = K >> 6;
    const int nch = TAPS * kch;

#define LOAD_CHUNK(c, stg) do { \
        int s_ = (c) / kch; int kb_ = ((c) - s_ * kch) << 6; \
        long sK_ = (TAPS == 3) ? (long)s_ * K : 0; \
        long sNK_ = (TAPS == 3) ? (long)s_ * N * K : 0; \
        uint32_t sb_ = dbase + (stg) * STAGE_BYTES; \
        _Pragma("unroll") \
        for (int j = 0; j < 4; j++) { \
            cp16(sb_ + so[j],         Ahi + sK_ + ga[j] + kb_); \
            cp16(sb_ + 18432 + so[j], Bhi + sNK_ + gb[j] + kb_); \
        } \
    } while (0)

    float acc[4][4][4];
#pragma unroll
    for (int a = 0; a < 4; a++)
#pragma unroll
        for (int b = 0; b < 4; b++)
#pragma unroll
            for (int q2 = 0; q2 < 4; q2++) acc[a][b][q2] = 0.0f;

    int bq = lane & 3, bg = lane >> 2;
    uint32_t aoff = (uint32_t)(wm + (lane & 15)) * 144 + (uint32_t)(((lane >> 4) & 1) << 4);
    uint32_t boff = 18432u + (uint32_t)(wn + ((lane >> 4) << 3) + (lane & 7)) * 144
                  + (uint32_t)(((lane >> 3) & 1) << 4);

    LOAD_CHUNK(0, 0);
    CP_COMMIT();
    LOAD_CHUNK(1, 1);
    CP_COMMIT();
#pragma unroll 1
    for (int c = 0; c < nch; c++) {
        if (c + 2 < nch) LOAD_CHUNK(c + 2, (c + 2) % 3);
        CP_COMMIT();
        CP_WAIT2();
        __syncthreads();
        uint32_t sb = dbase + (c % 3) * STAGE_BYTES;
#pragma unroll
        for (int k16 = 0; k16 < 4; k16++) {
            uint32_t kof = k16 * 32;
            uint32_t bh[4][2], t[4];
            ldsm4(t, sb + boff + kof);
            bh[0][0] = t[0]; bh[0][1] = t[1]; bh[1][0] = t[2]; bh[1][1] = t[3];
            ldsm4(t, sb + boff + 2304 + kof);
            bh[2][0] = t[0]; bh[2][1] = t[1]; bh[3][0] = t[2]; bh[3][1] = t[3];
#pragma unroll
            for (int mi = 0; mi < 4; mi++) {
                uint32_t ah[4];
                ldsm4(ah, sb + aoff + mi * 2304 + kof);
#pragma unroll
                for (int ni = 0; ni < 4; ni++)
                    mma16816(acc[mi][ni], ah, bh[ni]);
            }
        }
        __syncthreads();
    }
#undef LOAD_CHUNK

#pragma unroll
    for (int mi = 0; mi < 4; mi++) {
#pragma unroll
        for (int half = 0; half < 2; half++) {
            int m = bm + wm + mi * 16 + bg + half * 8;
            if (m >= Mstore) continue;
            int b = 0, t = 0; long crow = m;
            if (MODE == 1) { b = m / 351; t = m - b * 351; crow = (long)b * 353 + 1 + t; }
            if (MODE >= 2) { b = m / 351; t = m - b * 351; }
#pragma unroll
            for (int ni = 0; ni < 4; ni++) {
                int col = bn + wn + ni * 8 + bq * 2;
                float v0 = acc[mi][ni][half * 2 + 0];
                float v1 = acc[mi][ni][half * 2 + 1];
                if (MODE == 0 || MODE == 1 || MODE == 3) {
                    if (bias) { v0 += bias[col]; v1 += bias[col + 1]; }
                }
                if (RELU) { v0 = fmaxf(v0, 0.0f); v1 = fmaxf(v1, 0.0f); }
                if (MODE == 0) {
                    float* cp = Cf + (long)m * N + col;
                    if (ACC) { v0 += cp[0]; v1 += cp[1]; }
                    float2 st; st.x = v0; st.y = v1;
                    *(float2*)cp = st;
                } else if (MODE == 1) {
                    *(uint32_t*)(O1h + crow * (long)N + col) = packh(v0, v1);
                } else if (MODE == 3) {
                    int h = col >> 6, d = col & 63;
                    long base = ((long)(b * 8 + h) * TP + t) * 64 + d;
                    *(uint32_t*)(O1h + base) = packh(v0, v1);
                } else if (MODE == 5) {
                    int seg = col >> 9, cs = col & 511;
                    int h = cs >> 6, d = cs & 63;
                    if (seg == 0) {
                        long base = ((long)(b * 8 + h) * TP + t) * 64 + d;
                        float q0v = v0 + bias[cs], q1v = v1 + bias[cs + 1];
                        *(uint32_t*)(O1h + base) = packh(q0v + bias2[cs], q1v + bias2[cs + 1]);
                        *(uint32_t*)(O2h + base) = packh(q0v + bias3[cs], q1v + bias3[cs + 1]);
                    } else if (seg == 1) {
                        long base = ((long)(b * 8 + h) * TP + t) * 64 + d;
                        *(uint32_t*)(O3h + base) = packh(v0 + bias4[cs], v1 + bias4[cs + 1]);
                    } else {
                        float u0 = v0 + bias5[cs], u1 = v1 + bias5[cs + 1];
                        O4h[((long)(b * 8 + h) * 64 + d) * TP + t]     = __float2half_rn(u0);
                        O4h[((long)(b * 8 + h) * 64 + d + 1) * TP + t] = __float2half_rn(u1);
                    }
                }
            }
        }
    }
}

// ---------------- fully fused attention ----------------------------------------------
__global__ __launch_bounds__(256, 2)
void attn_fused(const __half* __restrict__ quh, const __half* __restrict__ qvh,
                const __half* __restrict__ kkh, const __half* __restrict__ pph,
                const __half* __restrict__ vth, __half* __restrict__ Ch) {
    extern __shared__ char sm[];
    uint32_t dbase = smem_u32(sm);
    float* S = (float*)sm;
    int z = blockIdx.y, q0 = blockIdx.x * 48;
    int tid = threadIdx.x, lane = tid & 31, w = tid >> 5;
    int cb = w << 3;
    int bq = lane & 3, bg = lane >> 2;

    for (int i = tid; i < 512; i += 256) {
        int r = i >> 3, c = i & 7;
        int gq = q0 + r; if (gq >= TP) gq = q0;
        cp16(dbase + AT_QU + r * 144 + c * 16, quh + ((long)z * TP + gq) * 64 + c * 8);
        cp16(dbase + AT_QV + r * 144 + c * 16, qvh + ((long)z * TP + gq) * 64 + c * 8);
        cp16(dbase + AT_B0 + r * 144 + c * 16, kkh + ((long)z * TP + r) * 64 + c * 8);
    }
    CP_COMMIT();
    CP_WAIT0();
    __syncthreads();

    uint32_t afr[4][4][4];
#pragma unroll
    for (int mi = 0; mi < 3; mi++)
#pragma unroll
        for (int k16 = 0; k16 < 4; k16++) {
            const char* pa = sm + AT_QU + (mi * 16 + bg) * 144 + k16 * 32 + bq * 4;
            afr[mi][k16][0] = *(const uint32_t*)pa;
            afr[mi][k16][1] = *(const uint32_t*)(pa + 8 * 144);
            afr[mi][k16][2] = *(const uint32_t*)(pa + 16);
            afr[mi][k16][3] = *(const uint32_t*)(pa + 8 * 144 + 16);
        }

#pragma unroll 1
    for (int ch = 0; ch < 12; ch++) {
        if (ch + 1 < 12) {
            const __half* src = (ch + 1 < 6) ? kkh : pph;
            int rows0 = ((ch + 1) % 6) * 64;
            uint32_t bb = ((ch + 1) & 1) ? AT_B1 : AT_B0;
            for (int i = tid; i < 512; i += 256) {
                int r = i >> 3, c = i & 7;
                cp16(dbase + bb + r * 144 + c * 16,
                     src + ((long)z * TP + rows0 + r) * 64 + c * 8);
            }
        }
        CP_COMMIT();
        CP_WAIT1();
        __syncthreads();
        if (ch == 6) {
#pragma unroll
            for (int mi = 0; mi < 4; mi++)
#pragma unroll
                for (int k16 = 0; k16 < 4; k16++) {
                    const char* pa = sm + AT_QV + (mi * 16 + bg) * 144 + k16 * 32 + bq * 4;
                    afr[mi][k16][0] = *(const uint32_t*)pa;
                    afr[mi][k16][1] = *(const uint32_t*)(pa + 8 * 144);
                    afr[mi][k16][2] = *(const uint32_t*)(pa + 16);
                    afr[mi][k16][3] = *(const uint32_t*)(pa + 8 * 144 + 16);
                }
        }
        uint32_t bb = (ch & 1) ? AT_B1 : AT_B0;
        int col0 = (ch % 6) * 64;
        if (ch < 6) {
            float acc[3][4];
#pragma unroll
            for (int a = 0; a < 3; a++)
#pragma unroll
                for (int e = 0; e < 4; e++) acc[a][e] = 0.0f;
#pragma unroll
            for (int k16 = 0; k16 < 4; k16++) {
                const char* pb = sm + bb + (cb + bg) * 144 + k16 * 32 + bq * 4;
                uint32_t bh[2];
                bh[0] = *(const uint32_t*)pb;
                bh[1] = *(const uint32_t*)(pb + 16);
#pragma unroll
                for (int mi = 0; mi < 3; mi++)
                    mma16816(acc[mi], afr[mi][k16], bh);
            }
#pragma unroll
            for (int mi = 0; mi < 3; mi++)
#pragma unroll
                for (int half = 0; half < 2; half++) {
                    int r = mi * 16 + bg + half * 8;
                    int col = col0 + cb + bq * 2;
                    S[r * FS_PITCH + col]     = acc[mi][half * 2 + 0];
                    S[r * FS_PITCH + col + 1] = acc[mi][half * 2 + 1];
                }
        } else {
            float acc[4][4];
#pragma unroll
            for (int a = 0; a < 4; a++)
#pragma unroll
                for (int e = 0; e < 4; e++) acc[a][e] = 0.0f;
#pragma unroll
            for (int k16 = 0; k16 < 4; k16++) {
                const char* pb = sm + bb + (cb + bg) * 144 + k16 * 32 + bq * 4;
                uint32_t bh[2];
                bh[0] = *(const uint32_t*)pb;
                bh[1] = *(const uint32_t*)(pb + 16);
#pragma unroll
                for (int mi = 0; mi < 4; mi++)
                    mma16816(acc[mi], afr[mi][k16], bh);
            }
#pragma unroll
            for (int mi = 0; mi < 4; mi++)
#pragma unroll
                for (int half = 0; half < 2; half++) {
                    int r = mi * 16 + bg + half * 8;
                    if (r > 48) continue;
                    int rp = q0 + r;
#pragma unroll
                    for (int e = 0; e < 2; e++) {
                        int jj = col0 + cb + bq * 2 + e;
                        if (jj >= TT) continue;
                        float v = acc[mi][half * 2 + e];
                        if (jj >= 350 - rp) {
                            if (r < 48) S[r * FS_PITCH + jj - 350 + rp] += v;
                        } else if (r >= 1) {
                            S[(r - 1) * FS_PITCH + jj + rp + 1] += v;
                        }
                    }
                }
        }
        __syncthreads();
    }

    // ---- softmax via ex2.approx.f16x2 -> fp16 A tile (fully convergent) ----
    if (tid < 192) {
        int r = tid >> 2, qu = tid & 3;
        const float scale = 0.044194173824159216f;
        const float a_l2 = scale * 1.4426950408889634f;
        float* Srow = S + r * FS_PITCH;
        char* Arow = sm + AF_A + r * AF_PITCH;
        int c0 = qu * 96;
        float mx = -1e30f;
        for (int cc = c0; cc < c0 + 96; cc++)
            if (cc < TT) mx = fmaxf(mx, Srow[cc]);
        mx = fmaxf(mx, __shfl_xor_sync(0xffffffffu, mx, 1));
        mx = fmaxf(mx, __shfl_xor_sync(0xffffffffu, mx, 2));
        float boff2 = -mx * a_l2;
        float sum = 0.0f;
        for (int cc = c0; cc < c0 + 96; cc += 2) {
            float x0 = (cc < TT)     ? Srow[cc]     * a_l2 + boff2 : -60.0f;
            float x1 = (cc + 1 < TT) ? Srow[cc + 1] * a_l2 + boff2 : -60.0f;
            __half2 hx = __floats2half2_rn(x0, x1);
            __half2 he = h2exp2(hx);
            float2 fe = __half22float2(he);
            sum += fe.x + fe.y;
            *(__half2*)(Arow + cc * 2) = he;
        }
        sum += __shfl_xor_sync(0xffffffffu, sum, 1);
        sum += __shfl_xor_sync(0xffffffffu, sum, 2);
        __half2 inv2 = __half2half2(__float2half_rn(1.0f / sum));
        for (int cc = c0; cc < c0 + 96; cc += 2) {
            __half2 v = *(__half2*)(Arow + cc * 2);
            *(__half2*)(Arow + cc * 2) = __hmul2(v, inv2);
        }
    }
    __syncthreads();

    // ---- load V tile over dead score region ----
    for (int i = tid; i < 3072; i += 256) {
        int d = i / 48, c16 = i - d * 48;
        cp16(dbase + d * AF_PITCH + c16 * 16,
             vth + ((long)z * 64 + d) * TP + c16 * 8);
    }
    CP_COMMIT(); CP_WAIT0(); __syncthreads();

    // ---- ctx GEMM: out[48 x 64] = A[48 x 384] @ V^T, 6 warps ----
    if (w < 6) {
        int wr = w % 3, wc = w / 3;
        float acc[4][4];
#pragma unroll
        for (int a = 0; a < 4; a++)
#pragma unroll
            for (int e = 0; e < 4; e++) acc[a][e] = 0.0f;
#pragma unroll 1
        for (int k16 = 0; k16 < 24; k16++) {
            int kb = k16 * 32 + bq * 4;
            const char* pa = sm + AF_A + (wr * 16 + bg) * AF_PITCH + kb;
            uint32_t ah[4];
            ah[0] = *(const uint32_t*)pa;
            ah[1] = *(const uint32_t*)(pa + 8 * AF_PITCH);
            ah[2] = *(const uint32_t*)(pa + 16);
            ah[3] = *(const uint32_t*)(pa + 8 * AF_PITCH + 16);
#pragma unroll
            for (int ni = 0; ni < 4; ni++) {
                const char* pb = sm + (wc * 32 + ni * 8 + bg) * AF_PITCH + kb;
                uint32_t bh[2];
                bh[0] = *(const uint32_t*)pb;
                bh[1] = *(const uint32_t*)(pb + 16);
                mma16816(acc[ni], ah, bh);
            }
        }
        int b = z >> 3, h = z & 7;
#pragma unroll
        for (int half = 0; half < 2; half++) {
            int gq = q0 + wr * 16 + bg + half * 8;
            if (gq >= TT) continue;
#pragma unroll
            for (int ni = 0; ni < 4; ni++) {
                int col = wc * 32 + ni * 8 + bq * 2;
                long addr = ((long)(b * 351 + gq)) * DD + h * 64 + col;
                *(uint32_t*)(Ch + addr) = packh(acc[ni][half * 2], acc[ni][half * 2 + 1]);
            }
        }
    }
}

// ---------------- add pos-emb + LayerNorm (float4-vectorized) ------------------------
template<bool F16O>
__global__ void addln_kernel(const float* __restrict__ xin, float* __restrict__ xupd,
                             const float* __restrict__ pe,
                             const float* __restrict__ ga, const float* __restrict__ gb,
                             float* __restrict__ out, __half* __restrict__ ohi) {
    int row = blockIdx.x;
    int t   = row % TT;
    int tid = threadIdx.x;          // 128; thread covers cols 4*tid..4*tid+3
    int c4 = tid << 2;
    float4 v4 = *(const float4*)(xin + (size_t)row * DD + c4);
    if (pe) {
        float4 p4 = *(const float4*)(pe + (size_t)t * DD + c4);
        v4.x += p4.x; v4.y += p4.y; v4.z += p4.z; v4.w += p4.w;
        *(float4*)(xupd + (size_t)row * DD + c4) = v4;
    }
    __shared__ float sh[4];
    float s = v4.x + v4.y + v4.z + v4.w;
#pragma unroll
    for (int o = 16; o > 0; o >>= 1) s += __shfl_xor_sync(0xffffffffu, s, o);
    if ((tid & 31) == 0) sh[tid >> 5] = s;
    __syncthreads();
    float mean = (sh[0] + sh[1] + sh[2] + sh[3]) * (1.0f / DD);
    __syncthreads();
    float d0 = v4.x - mean, d1 = v4.y - mean, d2 = v4.z - mean, d3 = v4.w - mean;
    float sq = d0 * d0 + d1 * d1 + d2 * d2 + d3 * d3;
#pragma unroll
    for (int o = 16; o > 0; o >>= 1) sq += __shfl_xor_sync(0xffffffffu, sq, o);
    if ((tid & 31) == 0) sh[tid >> 5] = sq;
    __syncthreads();
    float var  = sh[0] + sh[1] + sh[2] + sh[3];
    float stdv = sqrtf(var * (1.0f / (DD - 1)));
    float inv  = 1.0f / (stdv + 1e-6f);
    float4 a4 = *(const float4*)(ga + c4);
    float4 b4 = *(const float4*)(gb + c4);
    float o0 = a4.x * d0 * inv + b4.x;
    float o1 = a4.y * d1 * inv + b4.y;
    float o2 = a4.z * d2 * inv + b4.z;
    float o3 = a4.w * d3 * inv + b4.w;
    if (F16O) {
        uint2 st; st.x = packh(o0, o1); st.y = packh(o2, o3);
        *(uint2*)(ohi + (size_t)row * DD + c4) = st;
    } else {
        float4 st; st.x = o0; st.y = o1; st.z = o2; st.w = o3;
        *(float4*)(out + (size_t)row * DD + c4) = st;
    }
}

// ------------------------------------ launch -----------------------------------------
extern "C" void kernel_launch(void* const* d_in, const int* in_sizes, int n_in,
                              void* d_out, int out_size) {
    const float* X0  = (const float*)d_in[0];
    const float* MSK = (const float*)d_in[1];
    const float* PE  = (const float*)d_in[2];
    const float* Wq  = (const float*)d_in[3];
    const float* bq  = (const float*)d_in[4];
    const float* Wk  = (const float*)d_in[5];
    const float* bk  = (const float*)d_in[6];
    const float* Wv  = (const float*)d_in[7];
    const float* bv  = (const float*)d_in[8];
    const float* Wp  = (const float*)d_in[9];
    const float* Ub  = (const float*)d_in[10];
    const float* Vb  = (const float*)d_in[11];
    const float* Wo  = (const float*)d_in[12];
    const float* bo  = (const float*)d_in[13];
    const float* l1a = (const float*)d_in[14];
    const float* l1b = (const float*)d_in[15];
    const float* l2a = (const float*)d_in[16];
    const float* l2b = (const float*)d_in[17];
    const float* W1  = (const float*)d_in[18];
    const float* b1  = (const float*)d_in[19];
    const float* W2  = (const float*)d_in[20];
    const float* b2  = (const float*)d_in[21];
    const float* fna = (const float*)d_in[22];
    const float* fnb = (const float*)d_in[23];
    float* x = (float*)d_out;

    __half *quh, *qvh, *kkh, *pph, *vth;
    __half *xnh, *mkh, *cxh, *hph;
    __half *wqkv, *wph, *woh, *w1h, *w2h;
    cudaGetSymbolAddress((void**)&quh, g_quh); cudaGetSymbolAddress((void**)&qvh, g_qvh);
    cudaGetSymbolAddress((void**)&kkh, g_kkh); cudaGetSymbolAddress((void**)&pph, g_pph);
    cudaGetSymbolAddress((void**)&vth, g_vth);
    cudaGetSymbolAddress((void**)&xnh, g_xnh); cudaGetSymbolAddress((void**)&mkh, g_mkh);
    cudaGetSymbolAddress((void**)&cxh, g_cxh); cudaGetSymbolAddress((void**)&hph, g_hph);
    cudaGetSymbolAddress((void**)&wqkv, g_wqkv);
    cudaGetSymbolAddress((void**)&wph, g_wph); cudaGetSymbolAddress((void**)&woh, g_woh);
    cudaGetSymbolAddress((void**)&w1h, g_w1h); cudaGetSymbolAddress((void**)&w2h, g_w2h);

    cudaFuncSetAttribute(hmma_gemm<1, true,  false, 0>, cudaFuncAttributeMaxDynamicSharedMemorySize, SMEMSZ);
    cudaFuncSetAttribute(hmma_gemm<3, true,  false, 0>, cudaFuncAttributeMaxDynamicSharedMemorySize, SMEMSZ);
    cudaFuncSetAttribute(hmma_gemm<1, false, true,  1>, cudaFuncAttributeMaxDynamicSharedMemorySize, SMEMSZ);
    cudaFuncSetAttribute(hmma_gemm<1, false, false, 3>, cudaFuncAttributeMaxDynamicSharedMemorySize, SMEMSZ);
    cudaFuncSetAttribute(hmma_gemm<1, false, false, 5>, cudaFuncAttributeMaxDynamicSharedMemorySize, SMEMSZ);
    cudaFuncSetAttribute(attn_fused, cudaFuncAttributeMaxDynamicSharedMemorySize, FS_TOT);

    int n4per = 3 * DD * DD / 4;
    cvt_qkv<<<dim3((n4per + 255) / 256, 3), 256>>>(Wq, Wk, Wv, wqkv, n4per);
    cvt_half<<<(n4per + 255) / 256, 256>>>(Wp, wph, n4per);
    cvt_half<<<(n4per + 255) / 256, 256>>>(Wo, woh, n4per);
    int n1 = 3 * DFFX * DD / 4;
    cvt_half<<<(n1 + 255) / 256, 256>>>(W1, w1h, n1);
    int nM = BT * DD / 4;
    cvt_half<<<(nM + 255) / 256, 256>>>(MSK, mkh, nM);
    int n2 = 3 * 3 * DD * DFFX;
    cvt_w2<<<(n2 + 255) / 256, 256>>>(W2, w2h);

    dim3 gP(4, MP / 128);
    dim3 gP3(4, MP / 128, 3);      // 3-layer batched P projection
    dim3 gQKV(12, MP / 128);
    dim3 gF(8, MP / 128);
    dim3 gAt(8, ZZ);

    // hoisted: P = MSK @ Wp[l]^T for all 3 layers (input is layer-independent)
    hmma_gemm<1, false, false, 3><<<gP3, 256, SMEMSZ>>>(
        mkh, wph, nullptr, nullptr, nullptr, nullptr, nullptr,
        nullptr, pph, nullptr, nullptr, nullptr, BT, DD, DD,
        (long)DD * DD, (long)ZT64);

    for (int i = 0; i < 3; i++) {
        size_t oD = (size_t)i * DD;
        addln_kernel<true><<<BT, 128>>>(i == 0 ? X0 : x, x, PE + (size_t)i * TT * DD,
                                        l1a + oD, l1b + oD, nullptr, xnh);
        hmma_gemm<1, false, false, 5><<<gQKV, 256, SMEMSZ>>>(
            xnh, wqkv + (size_t)i * 3 * DD * DD,
            bq + oD, Ub + oD, Vb + oD, bk + oD, bv + oD,
            nullptr, quh, qvh, kkh, vth, BT, 3 * DD, DD, 0, 0);
        attn_fused<<<gAt, 256, FS_TOT>>>(quh, qvh, kkh, pph + (size_t)i * ZT64, vth, cxh);
        hmma_gemm<1, true, false, 0><<<gP, 256, SMEMSZ>>>(
            cxh, woh + (size_t)i * DD * DD, bo + oD, nullptr, nullptr, nullptr, nullptr,
            x, nullptr, nullptr, nullptr, nullptr, BT, DD, DD, 0, 0);
        addln_kernel<true><<<BT, 128>>>(x, nullptr, nullptr,
                                        l2a + oD, l2b + oD, nullptr, xnh);
        hmma_gemm<1, false, true, 1><<<gF, 256, SMEMSZ>>>(
            xnh, w1h + (size_t)i * DFFX * DD,
            b1 + (size_t)i * DFFX, nullptr, nullptr, nullptr, nullptr,
            nullptr, hph, nullptr, nullptr, nullptr, BT, DFFX, DD, 0, 0);
        hmma_gemm<3, true, false, 0><<<gP, 256, SMEMSZ>>>(
            hph, w2h + (size_t)i * 3 * DD * DFFX,
            b2 + oD, nullptr, nullptr, nullptr, nullptr,
            x, nullptr, nullptr, nullptr, nullptr, BT, DD, DFFX, 0, 0);
    }
    addln_kernel<false><<<BT, 128>>>(x, nullptr, nullptr, fna, fnb, x, nullptr);
}